// round 5
// baseline (speedup 1.0000x reference)
#include <cuda_runtime.h>
#include <cuda_fp16.h>
#include <cstdint>

// ---------------------------------------------------------------------------
// VSN on GB300 — Round 5: BN=256 mma.sync tiles (grid.x=1), GLU fused into
// G5 epilogue via interleaved Wv3, fp16 E buffer.
// B=8,T=2048,NV=16,D=256 -> BT=16384, DIN=4096
// ---------------------------------------------------------------------------

#define BT_TOK 16384L
#define DDIM   256
#define DIN    4096

// ---------------- scratch (bytes) ----------------
#define O_VH    0ULL            // vars fp16 [16384,4096]          128MB
#define O_H1    134217728ULL    // h1 fp16 [16384,256]
#define O_H2F   142606336ULL    // h2 fp32 [16384,256]
#define O_V1    159383552ULL    // hv1 fp16 16x[16384,256]
#define O_V2    293601280ULL    // hv2 fp16 16x[16384,256]
#define O_E     427819008ULL    // E=glu+x fp16 16x[16384,256]     128MB
#define O_SKIP  562036736ULL    // skip fp32 [16384,16]
#define O_G1    563085312ULL    // Wg1^T fp16 [256,4096]
#define O_G2    565182464ULL    // Wg2^T fp16 [256,256]
#define O_W1    565313536ULL    // Wv1^T fp16 16x[256,256]
#define O_W2    567410688ULL
#define O_W3    569507840ULL    // Wv3^T perm fp16 16x[512,256]
#define G_TOTAL 573702144ULL

__device__ __align__(1024) unsigned char g_buf[G_TOTAL];

// ---------------- helpers ----------------
__device__ __forceinline__ uint32_t smem_u32(const void* p) {
    uint32_t a;
    asm("{ .reg .u64 t; cvta.to.shared.u64 t, %1; cvt.u32.u64 %0, t; }" : "=r"(a) : "l"(p));
    return a;
}
__device__ __forceinline__ void cpasync16(uint32_t dst, const void* src) {
    asm volatile("cp.async.cg.shared.global [%0], [%1], 16;" :: "r"(dst), "l"(src));
}
#define CP_COMMIT() asm volatile("cp.async.commit_group;" ::: "memory")
#define CP_WAIT(n)  asm volatile("cp.async.wait_group %0;" :: "n"(n) : "memory")

__device__ __forceinline__ void ldsm_x4(uint32_t (&r)[4], uint32_t addr) {
    asm volatile("ldmatrix.sync.aligned.m8n8.x4.shared.b16 {%0,%1,%2,%3}, [%4];"
        : "=r"(r[0]), "=r"(r[1]), "=r"(r[2]), "=r"(r[3]) : "r"(addr));
}
__device__ __forceinline__ void mma16816(float (&c)[4], const uint32_t (&a)[4],
                                         uint32_t b0, uint32_t b1) {
    asm volatile("mma.sync.aligned.m16n8k16.row.col.f32.f16.f16.f32 "
        "{%0,%1,%2,%3}, {%4,%5,%6,%7}, {%8,%9}, {%0,%1,%2,%3};"
        : "+f"(c[0]), "+f"(c[1]), "+f"(c[2]), "+f"(c[3])
        : "r"(a[0]), "r"(a[1]), "r"(a[2]), "r"(a[3]), "r"(b0), "r"(b1));
}

// ---------------------------------------------------------------------------
// conversions
// ---------------------------------------------------------------------------
__global__ __launch_bounds__(256)
void conv_split(const float* __restrict__ x, __half* __restrict__ h)
{
    size_t base = ((size_t)blockIdx.x * 1024 + threadIdx.x * 4);
#pragma unroll
    for (int u = 0; u < 4; u++) {
        size_t i = (base + u * 1024 * 16384) ;
        float4 v = *reinterpret_cast<const float4*>(x + i);
        *reinterpret_cast<__half2*>(h + i)     = __floats2half2_rn(v.x, v.y);
        *reinterpret_cast<__half2*>(h + i + 2) = __floats2half2_rn(v.z, v.w);
    }
}

// transpose: W[K,N] -> WT[N,K] (fp16)
__global__ __launch_bounds__(256)
void conv_wT(const float* __restrict__ W, __half* __restrict__ TH, int K, int N)
{
    const size_t vb = (size_t)blockIdx.z * K * N;
    __shared__ float tile[32][33];
    const int k0 = blockIdx.y * 32, n0 = blockIdx.x * 32;
    const int tx = threadIdx.x & 31, ty = threadIdx.x >> 5;  // 32 x 8
#pragma unroll
    for (int i = 0; i < 4; i++)
        tile[ty + i * 8][tx] = W[vb + (size_t)(k0 + ty + i * 8) * N + n0 + tx];
    __syncthreads();
#pragma unroll
    for (int i = 0; i < 4; i++) {
        int n = ty + i * 8;
        TH[vb + (size_t)(n0 + n) * K + k0 + tx] = __float2half_rn(tile[tx][n]);
    }
}

// Wv3 transpose with GLU interleave: out row (2c) <- col c (a-half, c<256),
// out row (2(c-256)+1) <- col c (b-half). W[256,512] -> WT3[512,256].
__global__ __launch_bounds__(256)
void conv_wT3(const float* __restrict__ W, __half* __restrict__ TH)
{
    const size_t vbs = (size_t)blockIdx.z * 256 * 512;
    const size_t vbd = (size_t)blockIdx.z * 512 * 256;
    __shared__ float tile[32][33];
    const int k0 = blockIdx.y * 32, c0 = blockIdx.x * 32;
    const int tx = threadIdx.x & 31, ty = threadIdx.x >> 5;
#pragma unroll
    for (int i = 0; i < 4; i++)
        tile[ty + i * 8][tx] = W[vbs + (size_t)(k0 + ty + i * 8) * 512 + c0 + tx];
    __syncthreads();
#pragma unroll
    for (int i = 0; i < 4; i++) {
        int c = c0 + ty + i * 8;
        int orow = (c < 256) ? (2 * c) : (2 * (c - 256) + 1);
        TH[vbd + (size_t)orow * 256 + k0 + tx] = __float2half_rn(tile[tx][ty + i * 8]);
    }
}

// ---------------------------------------------------------------------------
// fp16 mma.sync GEMM: C[128,256] tile = A[128,K] @ B^T, B stored [N,K].
// 8 warps: 2(M) x 4(N); warp tile 64x64; BK=64; 3-stage cp.async ring.
// mode: 0=fp32 out, 1=ELU+fp16, 2=fp16, 3=GLU(interleaved)+x -> fp16 E
// ---------------------------------------------------------------------------
#define RS 72                       // smem row stride (elements), 144 bytes
#define OFF_B  18432                // 128 * 72 * 2 (A tile bytes)
#define ST_SIZE 55296               // (128 + 256) * 144
#define SMEM_TOT 165888             // 3 stages

__global__ __launch_bounds__(256, 1)
void mma_gemm(const __half* __restrict__ A, long long aV, int lda,
              const __half* __restrict__ BH, long long bV,
              const float* __restrict__ bias, int biasV,
              float* __restrict__ CF, __half* __restrict__ CH,
              const __half* __restrict__ XH,     // mode 3: vars fp16
              long long cV, int ldc, int K, int mode)
{
    extern __shared__ __align__(1024) unsigned char sm[];
    const uint32_t sb = smem_u32(sm);
    const int tid = threadIdx.x;
    const int lane = tid & 31, wid = tid >> 5;
    const int wm = wid & 1, wn = wid >> 1;
    const int v = blockIdx.z;
    const int m0 = blockIdx.y * 128;
    const int nb = blockIdx.x * 256;

    const __half* Ap  = A  + (size_t)v * aV + (size_t)m0 * lda;
    const __half* Bhp = BH + (size_t)v * bV + (size_t)nb * K;

    float acc[4][8][4];
#pragma unroll
    for (int i = 0; i < 4; i++)
#pragma unroll
        for (int j = 0; j < 8; j++)
#pragma unroll
            for (int k = 0; k < 4; k++) acc[i][j][k] = 0.f;

    const int nc = K >> 6;

    // stage loader: 384 rows x 64 halves; 12 chunks of 16B per thread
    auto load_stage = [&](int s, int k0) {
        const uint32_t base = sb + s * ST_SIZE;
#pragma unroll
        for (int t = 0; t < 12; t++) {
            const int id = tid + t * 256;
            const int row = id >> 3;
            const int cc = (id & 7) * 8;
            const uint32_t doff = (uint32_t)(row * RS + cc) * 2;
            const __half* src = (row < 128)
                ? (Ap + (size_t)row * lda + k0 + cc)
                : (Bhp + (size_t)(row - 128) * K + k0 + cc);
            cpasync16(base + doff, src);
        }
    };

    const uint32_t aoff = (uint32_t)(((wm * 64 + (lane & 15)) * RS + (lane >> 4) * 8) * 2);
    const uint32_t boff = (uint32_t)(((wn * 64 + (lane & 15)) * RS + (lane >> 4) * 8) * 2)
                          + OFF_B + (uint32_t)(128 * RS * 2) - (uint32_t)(128 * RS * 2);
    // (B rows start at smem row 128 => base offset OFF_B handled via row index)
    const uint32_t bofs = OFF_B + (uint32_t)(((wn * 64 + (lane & 15)) * RS + (lane >> 4) * 8) * 2);

    load_stage(0, 0);               CP_COMMIT();
    if (nc > 1) { load_stage(1, 64); } CP_COMMIT();

    for (int c = 0; c < nc; c++) {
        CP_WAIT(1);
        __syncthreads();
        const uint32_t base = sb + (c % 3) * ST_SIZE;
#pragma unroll
        for (int kc = 0; kc < 64; kc += 16) {
            uint32_t a[4][4], bh[4][4];
#pragma unroll
            for (int mt = 0; mt < 4; mt++)
                ldsm_x4(a[mt], base + aoff + mt * (16 * RS * 2) + kc * 2);
#pragma unroll
            for (int p = 0; p < 4; p++)
                ldsm_x4(bh[p], base + bofs + p * (16 * RS * 2) + kc * 2);
#pragma unroll
            for (int mt = 0; mt < 4; mt++)
#pragma unroll
                for (int q = 0; q < 8; q++)
                    mma16816(acc[mt][q], a[mt], bh[q >> 1][q & 1], bh[q >> 1][(q & 1) + 2]);
        }
        __syncthreads();
        if (c + 2 < nc) load_stage((c + 2) % 3, (c + 2) * 64);
        CP_COMMIT();
    }

    // ---- epilogue ----
    const int gid = lane >> 2, tig = lane & 3;
#pragma unroll
    for (int mt = 0; mt < 4; mt++) {
#pragma unroll
        for (int q = 0; q < 8; q++) {
            const int m = m0 + wm * 64 + mt * 16 + gid;
            const int n = nb + wn * 64 + q * 8 + tig * 2;
            if (mode == 3) {
                // n even: a-col (channel j=n/2), n+1: b-col
                const int j = n >> 1;
                const float* bp = bias + (size_t)v * biasV;
                const float ba = bp[j], bb = bp[j + 256];
                float a0 = acc[mt][q][0] + ba, b0 = acc[mt][q][1] + bb;
                float a1 = acc[mt][q][2] + ba, b1 = acc[mt][q][3] + bb;
                float x0 = __half2float(XH[(size_t)m * DIN + v * DDIM + j]);
                float x1 = __half2float(XH[(size_t)(m + 8) * DIN + v * DDIM + j]);
                float g0 = a0 * (1.f / (1.f + expf(-b0))) + x0;
                float g1 = a1 * (1.f / (1.f + expf(-b1))) + x1;
                __half* d = CH + (size_t)v * cV + (size_t)m * ldc + j;
                d[0] = __float2half_rn(g0);
                d[8 * ldc] = __float2half_rn(g1);
            } else {
                const float* bp = bias + (size_t)v * biasV + n;
                const float b0 = bp[0], b1 = bp[1];
                float x0 = acc[mt][q][0] + b0, x1 = acc[mt][q][1] + b1;
                float y0 = acc[mt][q][2] + b0, y1 = acc[mt][q][3] + b1;
                if (mode == 1) {
                    x0 = (x0 > 0.f) ? x0 : expm1f(x0);
                    x1 = (x1 > 0.f) ? x1 : expm1f(x1);
                    y0 = (y0 > 0.f) ? y0 : expm1f(y0);
                    y1 = (y1 > 0.f) ? y1 : expm1f(y1);
                }
                if (mode == 0) {
                    float* d0 = CF + (size_t)v * cV + (size_t)m * ldc + n;
                    float2 o0; o0.x = x0; o0.y = x1;
                    float2 o1; o1.x = y0; o1.y = y1;
                    *reinterpret_cast<float2*>(d0) = o0;
                    *reinterpret_cast<float2*>(d0 + 8 * ldc) = o1;
                } else {
                    __half* d0 = CH + (size_t)v * cV + (size_t)m * ldc + n;
                    *reinterpret_cast<__half2*>(d0) = __floats2half2_rn(x0, x1);
                    *reinterpret_cast<__half2*>(d0 + 8 * ldc) = __floats2half2_rn(y0, y1);
                }
            }
        }
    }
    (void)boff;
}

// ---------------------------------------------------------------------------
// skip = flat @ Wgs + bgs (reads fp16 VH)
// ---------------------------------------------------------------------------
__global__ __launch_bounds__(256)
void skip_kernel(const __half* __restrict__ vh, const float* __restrict__ Wgs,
                 const float* __restrict__ bgs, float* __restrict__ skipOut)
{
    __shared__ __half As[16][64];
    __shared__ float Ws[64][16];
    const int tid = threadIdx.x;
    const long t0 = (long)blockIdx.x * 16;
    const int o = tid & 15;
    const int tr = tid >> 4;
    float s = 0.f;
    for (int k0 = 0; k0 < DIN; k0 += 64) {
        *reinterpret_cast<uint2*>(&As[tid >> 4][(tid & 15) * 4]) =
            *reinterpret_cast<const uint2*>(vh + (t0 + (tid >> 4)) * DIN + k0 + (tid & 15) * 4);
        *reinterpret_cast<float4*>(&Ws[tid >> 2][(tid & 3) * 4]) =
            *reinterpret_cast<const float4*>(Wgs + (long)(k0 + (tid >> 2)) * 16 + (tid & 3) * 4);
        __syncthreads();
#pragma unroll 16
        for (int kk = 0; kk < 64; kk++) s += __half2float(As[tr][kk]) * Ws[kk][o];
        __syncthreads();
    }
    skipOut[(t0 + tr) * 16 + o] = s + bgs[o];
}

// ---------------------------------------------------------------------------
// weight logits -> softmax weights (one warp per token, Wg3 staged in smem)
// ---------------------------------------------------------------------------
__global__ __launch_bounds__(256)
void wlogits_kernel(const float* __restrict__ h2, const float* __restrict__ Wg3,
                    const float* __restrict__ bg3, const float* __restrict__ gg,
                    const float* __restrict__ bgn, const float* __restrict__ skipIn,
                    float* __restrict__ wout)
{
    __shared__ float Ws[256 * 32];
    const int tid = threadIdx.x;
    const int lane = tid & 31;
#pragma unroll
    for (int i = 0; i < 32; i++) Ws[tid + i * 256] = Wg3[tid + i * 256];
    __syncthreads();

    const long t = (long)blockIdx.x * 8 + (tid >> 5);
    const float* h2t = h2 + t * 256;
    float s = bg3[lane];
#pragma unroll 8
    for (int k = 0; k < 256; k += 4) {
        float4 h = *reinterpret_cast<const float4*>(h2t + k);
        s += h.x * Ws[(k + 0) * 32 + lane];
        s += h.y * Ws[(k + 1) * 32 + lane];
        s += h.z * Ws[(k + 2) * 32 + lane];
        s += h.w * Ws[(k + 3) * 32 + lane];
    }
    float bhalf = __shfl_down_sync(0xffffffffu, s, 16);
    float r = 0.f;
    if (lane < 16)
        r = s * (1.f / (1.f + expf(-bhalf))) + skipIn[t * 16 + lane];
    float sum = r;
    for (int m = 8; m; m >>= 1) sum += __shfl_xor_sync(0xffffffffu, sum, m, 16);
    float mean = sum * (1.f / 16.f);
    float d = r - mean;
    float vs = d * d;
    for (int m = 8; m; m >>= 1) vs += __shfl_xor_sync(0xffffffffu, vs, m, 16);
    float rstd = rsqrtf(vs * (1.f / 16.f) + 1e-6f);
    float ln = 0.f;
    if (lane < 16) ln = d * rstd * gg[lane] + bgn[lane];
    float mx = ln;
    for (int m = 8; m; m >>= 1) mx = fmaxf(mx, __shfl_xor_sync(0xffffffffu, mx, m, 16));
    float e = (lane < 16) ? expf(ln - mx) : 0.f;
    float se = e;
    for (int m = 8; m; m >>= 1) se += __shfl_xor_sync(0xffffffffu, se, m, 16);
    if (lane < 16) wout[t * 16 + lane] = e / se;
}

// ---------------------------------------------------------------------------
// out = sum_v LN(E[v]) * weight[v]    (E = glu+x fp16)
// ---------------------------------------------------------------------------
__global__ __launch_bounds__(256)
void enc_combine_kernel(const __half* __restrict__ E, const float* __restrict__ wout,
                        const float* __restrict__ gv, const float* __restrict__ bvn,
                        float* __restrict__ outp)
{
    const long t = blockIdx.x;
    const int tid = threadIdx.x;
    const int lane = tid & 31, wid = tid >> 5;
    __shared__ float sw[16];
    __shared__ float red[18];
    if (tid < 16) sw[tid] = wout[t * 16 + tid];
    __syncthreads();
    float acc = 0.f;
    for (int v = 0; v < 16; v++) {
        float e = __half2float(E[((size_t)v * BT_TOK + t) * 256 + tid]);
        float s1 = e, s2 = e * e;
        for (int m = 16; m; m >>= 1) {
            s1 += __shfl_xor_sync(0xffffffffu, s1, m);
            s2 += __shfl_xor_sync(0xffffffffu, s2, m);
        }
        if (lane == 0) { red[wid] = s1; red[8 + wid] = s2; }
        __syncthreads();
        if (wid == 0 && lane < 8) {
            float t1 = red[lane], t2 = red[8 + lane];
#pragma unroll
            for (int m = 4; m; m >>= 1) {
                t1 += __shfl_xor_sync(0x000000ffu, t1, m, 8);
                t2 += __shfl_xor_sync(0x000000ffu, t2, m, 8);
            }
            if (lane == 0) {
                float mean = t1 * (1.f / 256.f);
                float var = t2 * (1.f / 256.f) - mean * mean;
                red[16] = mean;
                red[17] = rsqrtf(var + 1e-6f);
            }
        }
        __syncthreads();
        float mean = red[16], rstd = red[17];
        float encv = (e - mean) * rstd * gv[v * DDIM + tid] + bvn[v * DDIM + tid];
        acc += encv * sw[v];
        __syncthreads();
    }
    outp[t * DDIM + tid] = acc;
}

// ---------------------------------------------------------------------------
extern "C" void kernel_launch(void* const* d_in, const int* in_sizes, int n_in,
                              void* d_out, int out_size)
{
    const float* vars = (const float*)d_in[0];
    const float* Wg1  = (const float*)d_in[1];
    const float* bg1  = (const float*)d_in[2];
    const float* Wg2  = (const float*)d_in[3];
    const float* bg2  = (const float*)d_in[4];
    const float* Wg3  = (const float*)d_in[5];
    const float* bg3  = (const float*)d_in[6];
    const float* Wgs  = (const float*)d_in[7];
    const float* bgs  = (const float*)d_in[8];
    const float* gg   = (const float*)d_in[9];
    const float* bgn  = (const float*)d_in[10];
    const float* Wv1  = (const float*)d_in[11];
    const float* bv1  = (const float*)d_in[12];
    const float* Wv2  = (const float*)d_in[13];
    const float* bv2  = (const float*)d_in[14];
    const float* Wv3  = (const float*)d_in[15];
    const float* bv3  = (const float*)d_in[16];
    const float* gv   = (const float*)d_in[17];
    const float* bvn  = (const float*)d_in[18];

    float* out  = (float*)d_out;
    float* wout = out + BT_TOK * DDIM;

    unsigned char* gb = nullptr;
    cudaGetSymbolAddress((void**)&gb, g_buf);
    __half* VH  = (__half*)(gb + O_VH);
    __half* H1  = (__half*)(gb + O_H1);
    float*  H2F = (float*)(gb + O_H2F);
    __half* V1  = (__half*)(gb + O_V1);
    __half* V2  = (__half*)(gb + O_V2);
    __half* E   = (__half*)(gb + O_E);
    float*  SKP = (float*)(gb + O_SKIP);
    __half* G1T = (__half*)(gb + O_G1);
    __half* G2T = (__half*)(gb + O_G2);
    __half* W1T = (__half*)(gb + O_W1);
    __half* W2T = (__half*)(gb + O_W2);
    __half* W3T = (__half*)(gb + O_W3);

    cudaFuncSetAttribute(mma_gemm, cudaFuncAttributeMaxDynamicSharedMemorySize, SMEM_TOT);

    // conversions
    conv_split<<<16384, 256>>>(vars, VH);
    conv_wT<<<dim3(8, 128, 1), 256>>>(Wg1, G1T, 4096, 256);
    conv_wT<<<dim3(8, 8, 1),   256>>>(Wg2, G2T, 256, 256);
    conv_wT<<<dim3(8, 8, 16),  256>>>(Wv1, W1T, 256, 256);
    conv_wT<<<dim3(8, 8, 16),  256>>>(Wv2, W2T, 256, 256);
    conv_wT3<<<dim3(16, 8, 16), 256>>>(Wv3, W3T);

    // skip path
    skip_kernel<<<1024, 256>>>(VH, Wgs, bgs, SKP);

    const long long S1 = BT_TOK * 256;

    // G1: h1 = elu(flat @ Wg1 + bg1)
    mma_gemm<<<dim3(1, 128, 1), 256, SMEM_TOT>>>(
        VH, 0, DIN, G1T, 0, bg1, 0, nullptr, H1, nullptr, 0, 256, 4096, 1);
    // G2: h2 = h1 @ Wg2 + bg2 (fp32 out)
    mma_gemm<<<dim3(1, 128, 1), 256, SMEM_TOT>>>(
        H1, 0, 256, G2T, 0, bg2, 0, H2F, nullptr, nullptr, 0, 256, 256, 0);
    wlogits_kernel<<<2048, 256>>>(H2F, Wg3, bg3, gg, bgn, SKP, wout);
    // G3: hv1 = elu(x_v @ Wv1[v] + bv1[v])
    mma_gemm<<<dim3(1, 128, 16), 256, SMEM_TOT>>>(
        VH, 256, DIN, W1T, 65536, bv1, 256, nullptr, V1, nullptr, S1, 256, 256, 1);
    // G4: hv2 = hv1 @ Wv2[v] + bv2[v]
    mma_gemm<<<dim3(1, 128, 16), 256, SMEM_TOT>>>(
        V1, S1, 256, W2T, 65536, bv2, 256, nullptr, V2, nullptr, S1, 256, 256, 2);
    // G5: E = glu(hv2 @ Wv3perm[v] + bv3) + x   (N=512 interleaved -> 256 ch)
    mma_gemm<<<dim3(2, 128, 16), 256, SMEM_TOT>>>(
        V2, S1, 256, W3T, (long long)512 * 256, bv3, 512,
        nullptr, E, VH, S1, 256, 256, 3);
    // final combine
    enc_combine_kernel<<<16384, 256>>>(E, wout, gv, bvn, out);
}

// round 6
// speedup vs baseline: 1.4855x; 1.4855x over previous
#include <cuda_runtime.h>
#include <cuda_fp16.h>
#include <cstdint>

// ---------------------------------------------------------------------------
// VSN on GB300 — Round 6: R4 GEMM core (BN=128, 4-stage) + GLU-fused G5
// epilogue (fp16 E buffer) + barrier-free enc_combine + wide-chunk skip.
// B=8,T=2048,NV=16,D=256 -> BT=16384, DIN=4096
// ---------------------------------------------------------------------------

#define BT_TOK 16384L
#define DDIM   256
#define DIN    4096

// ---------------- scratch (bytes) ----------------
#define O_VH    0ULL            // vars fp16 [16384,4096]          128MB
#define O_H1    134217728ULL    // h1 fp16 [16384,256]
#define O_H2F   142606336ULL    // h2 fp32 [16384,256]
#define O_V1    159383552ULL    // hv1 fp16 16x[16384,256]
#define O_V2    293601280ULL    // hv2 fp16 16x[16384,256]
#define O_E     427819008ULL    // E=glu+x fp16 16x[16384,256]     128MB
#define O_SKIP  562036736ULL    // skip fp32 [16384,16]
#define O_G1    563085312ULL    // Wg1^T fp16 [256,4096]
#define O_G2    565182464ULL    // Wg2^T fp16 [256,256]
#define O_W1    565313536ULL    // Wv1^T fp16 16x[256,256]
#define O_W2    567410688ULL
#define O_W3    569507840ULL    // Wv3^T perm fp16 16x[512,256]
#define G_TOTAL 573702144ULL

__device__ __align__(1024) unsigned char g_buf[G_TOTAL];

// ---------------- helpers ----------------
__device__ __forceinline__ uint32_t smem_u32(const void* p) {
    uint32_t a;
    asm("{ .reg .u64 t; cvta.to.shared.u64 t, %1; cvt.u32.u64 %0, t; }" : "=r"(a) : "l"(p));
    return a;
}
__device__ __forceinline__ void cpasync16(uint32_t dst, const void* src) {
    asm volatile("cp.async.cg.shared.global [%0], [%1], 16;" :: "r"(dst), "l"(src));
}
#define CP_COMMIT() asm volatile("cp.async.commit_group;" ::: "memory")
#define CP_WAIT(n)  asm volatile("cp.async.wait_group %0;" :: "n"(n) : "memory")

__device__ __forceinline__ void ldsm_x4(uint32_t (&r)[4], uint32_t addr) {
    asm volatile("ldmatrix.sync.aligned.m8n8.x4.shared.b16 {%0,%1,%2,%3}, [%4];"
        : "=r"(r[0]), "=r"(r[1]), "=r"(r[2]), "=r"(r[3]) : "r"(addr));
}
__device__ __forceinline__ void mma16816(float (&c)[4], const uint32_t (&a)[4],
                                         uint32_t b0, uint32_t b1) {
    asm volatile("mma.sync.aligned.m16n8k16.row.col.f32.f16.f16.f32 "
        "{%0,%1,%2,%3}, {%4,%5,%6,%7}, {%8,%9}, {%0,%1,%2,%3};"
        : "+f"(c[0]), "+f"(c[1]), "+f"(c[2]), "+f"(c[3])
        : "r"(a[0]), "r"(a[1]), "r"(a[2]), "r"(a[3]), "r"(b0), "r"(b1));
}

// ---------------------------------------------------------------------------
// conversions
// ---------------------------------------------------------------------------
__global__ __launch_bounds__(256)
void conv_split(const float* __restrict__ x, __half* __restrict__ h)
{
    size_t i = ((size_t)blockIdx.x * 256 + threadIdx.x) * 4;
    float4 v = *reinterpret_cast<const float4*>(x + i);
    *reinterpret_cast<__half2*>(h + i)     = __floats2half2_rn(v.x, v.y);
    *reinterpret_cast<__half2*>(h + i + 2) = __floats2half2_rn(v.z, v.w);
}

// transpose: W[K,N] -> WT[N,K] (fp16)
__global__ __launch_bounds__(256)
void conv_wT(const float* __restrict__ W, __half* __restrict__ TH, int K, int N)
{
    const size_t vb = (size_t)blockIdx.z * K * N;
    __shared__ float tile[32][33];
    const int k0 = blockIdx.y * 32, n0 = blockIdx.x * 32;
    const int tx = threadIdx.x & 31, ty = threadIdx.x >> 5;  // 32 x 8
#pragma unroll
    for (int i = 0; i < 4; i++)
        tile[ty + i * 8][tx] = W[vb + (size_t)(k0 + ty + i * 8) * N + n0 + tx];
    __syncthreads();
#pragma unroll
    for (int i = 0; i < 4; i++) {
        int n = ty + i * 8;
        TH[vb + (size_t)(n0 + n) * K + k0 + tx] = __float2half_rn(tile[tx][n]);
    }
}

// Wv3 transpose with GLU interleave: col c<256 (a_c) -> out row 2c;
// col c>=256 (b_{c-256}) -> out row 2(c-256)+1. W[256,512] -> WT3[512,256].
__global__ __launch_bounds__(256)
void conv_wT3(const float* __restrict__ W, __half* __restrict__ TH)
{
    const size_t vbs = (size_t)blockIdx.z * 256 * 512;
    const size_t vbd = (size_t)blockIdx.z * 512 * 256;
    __shared__ float tile[32][33];
    const int k0 = blockIdx.y * 32, c0 = blockIdx.x * 32;
    const int tx = threadIdx.x & 31, ty = threadIdx.x >> 5;
#pragma unroll
    for (int i = 0; i < 4; i++)
        tile[ty + i * 8][tx] = W[vbs + (size_t)(k0 + ty + i * 8) * 512 + c0 + tx];
    __syncthreads();
#pragma unroll
    for (int i = 0; i < 4; i++) {
        int c = c0 + ty + i * 8;
        int orow = (c < 256) ? (2 * c) : (2 * (c - 256) + 1);
        TH[vbd + (size_t)orow * 256 + k0 + tx] = __float2half_rn(tile[tx][ty + i * 8]);
    }
}

// ---------------------------------------------------------------------------
// fp16 mma.sync GEMM: C[128,128] tile = A[128,K] @ B^T, B stored [N,K].
// 8 warps: 2(M) x 4(N); warp tile 64x32; BK=64; 4-stage cp.async ring.
// mode: 0=fp32 out, 1=ELU+fp16, 2=fp16, 3=GLU(interleaved)+x -> fp16 E
// ---------------------------------------------------------------------------
#define RS 72                       // smem row stride (elements), 144 bytes
#define OFF_B  18432                // 128 * 72 * 2
#define ST_SIZE 36864
#define SMEM_TOT 147456             // 4 stages

__global__ __launch_bounds__(256, 1)
void mma_gemm(const __half* __restrict__ A, long long aV, int lda,
              const __half* __restrict__ BH, long long bV,
              const float* __restrict__ bias, int biasV,
              float* __restrict__ CF, __half* __restrict__ CH,
              const __half* __restrict__ XH,
              long long cV, int ldc, int K, int mode)
{
    extern __shared__ __align__(1024) unsigned char sm[];
    const uint32_t sb = smem_u32(sm);
    const int tid = threadIdx.x;
    const int lane = tid & 31, wid = tid >> 5;
    const int wm = wid & 1, wn = wid >> 1;
    const int v = blockIdx.z;
    const int m0 = blockIdx.y * 128;
    const int nb = blockIdx.x * 128;

    const __half* Ap  = A  + (size_t)v * aV + (size_t)m0 * lda;
    const __half* Bhp = BH + (size_t)v * bV + (size_t)nb * K;

    const int lr = tid >> 3;            // 0..31 (+ t*32)
    const int lc = (tid & 7) * 8;

    float acc[4][4][4];
#pragma unroll
    for (int i = 0; i < 4; i++)
#pragma unroll
        for (int j = 0; j < 4; j++)
#pragma unroll
            for (int k = 0; k < 4; k++) acc[i][j][k] = 0.f;

    const int nc = K >> 6;

    auto load_stage = [&](int s, int k0) {
        const uint32_t base = sb + s * ST_SIZE;
#pragma unroll
        for (int t = 0; t < 4; t++) {
            const int row = lr + t * 32;
            const uint32_t doff = (uint32_t)(row * RS + lc) * 2;
            cpasync16(base + doff,         Ap  + (size_t)row * lda + k0 + lc);
            cpasync16(base + OFF_B + doff, Bhp + (size_t)row * K   + k0 + lc);
        }
    };

    const uint32_t aoff = (uint32_t)(((wm * 64 + (lane & 15)) * RS + (lane >> 4) * 8) * 2);
    const uint32_t boff = (uint32_t)(((wn * 32 + (lane & 15)) * RS + (lane >> 4) * 8) * 2);

    load_stage(0, 0);          CP_COMMIT();
    if (nc > 1) load_stage(1, 64);  CP_COMMIT();
    if (nc > 2) load_stage(2, 128); CP_COMMIT();

    for (int c = 0; c < nc; c++) {
        CP_WAIT(2);
        __syncthreads();
        const uint32_t base = sb + (c & 3) * ST_SIZE;
#pragma unroll
        for (int kc = 0; kc < 64; kc += 16) {
            uint32_t a[4][4], bh[2][4];
#pragma unroll
            for (int mt = 0; mt < 4; mt++)
                ldsm_x4(a[mt], base + aoff + mt * (16 * RS * 2) + kc * 2);
#pragma unroll
            for (int p = 0; p < 2; p++)
                ldsm_x4(bh[p], base + OFF_B + boff + p * (16 * RS * 2) + kc * 2);
#pragma unroll
            for (int mt = 0; mt < 4; mt++)
#pragma unroll
                for (int q = 0; q < 4; q++)
                    mma16816(acc[mt][q], a[mt], bh[q >> 1][q & 1], bh[q >> 1][(q & 1) + 2]);
        }
        __syncthreads();
        if (c + 3 < nc) load_stage((c + 3) & 3, (c + 3) * 64);
        CP_COMMIT();
    }

    // ---- epilogue ----
    const int gid = lane >> 2, tig = lane & 3;
#pragma unroll
    for (int mt = 0; mt < 4; mt++) {
#pragma unroll
        for (int q = 0; q < 4; q++) {
            const int m = m0 + wm * 64 + mt * 16 + gid;
            const int n = nb + wn * 32 + q * 8 + tig * 2;
            if (mode == 3) {
                // interleaved: n even -> a of channel j=n/2, n+1 -> b
                const int j = n >> 1;
                const float* bp = bias + (size_t)v * biasV;
                const float ba = bp[j], bb = bp[j + 256];
                float a0 = acc[mt][q][0] + ba, b0 = acc[mt][q][1] + bb;
                float a1 = acc[mt][q][2] + ba, b1 = acc[mt][q][3] + bb;
                float x0 = __half2float(XH[(size_t)m * DIN + v * DDIM + j]);
                float x1 = __half2float(XH[(size_t)(m + 8) * DIN + v * DDIM + j]);
                float g0 = a0 * (1.f / (1.f + expf(-b0))) + x0;
                float g1 = a1 * (1.f / (1.f + expf(-b1))) + x1;
                __half* d = CH + (size_t)v * cV + (size_t)m * ldc + j;
                d[0] = __float2half_rn(g0);
                d[8 * ldc] = __float2half_rn(g1);
            } else {
                const float* bp = bias + (size_t)v * biasV + n;
                const float b0 = bp[0], b1 = bp[1];
                float x0 = acc[mt][q][0] + b0, x1 = acc[mt][q][1] + b1;
                float y0 = acc[mt][q][2] + b0, y1 = acc[mt][q][3] + b1;
                if (mode == 1) {
                    x0 = (x0 > 0.f) ? x0 : expm1f(x0);
                    x1 = (x1 > 0.f) ? x1 : expm1f(x1);
                    y0 = (y0 > 0.f) ? y0 : expm1f(y0);
                    y1 = (y1 > 0.f) ? y1 : expm1f(y1);
                }
                if (mode == 0) {
                    float* d0 = CF + (size_t)v * cV + (size_t)m * ldc + n;
                    float2 o0; o0.x = x0; o0.y = x1;
                    float2 o1; o1.x = y0; o1.y = y1;
                    *reinterpret_cast<float2*>(d0) = o0;
                    *reinterpret_cast<float2*>(d0 + 8 * ldc) = o1;
                } else {
                    __half* d0 = CH + (size_t)v * cV + (size_t)m * ldc + n;
                    *reinterpret_cast<__half2*>(d0) = __floats2half2_rn(x0, x1);
                    *reinterpret_cast<__half2*>(d0 + 8 * ldc) = __floats2half2_rn(y0, y1);
                }
            }
        }
    }
}

// ---------------------------------------------------------------------------
// skip = flat @ Wgs + bgs (fp16 VH), K-chunk 256
// ---------------------------------------------------------------------------
__global__ __launch_bounds__(256)
void skip_kernel(const __half* __restrict__ vh, const float* __restrict__ Wgs,
                 const float* __restrict__ bgs, float* __restrict__ skipOut)
{
    __shared__ __half As[16][256];
    __shared__ float Ws[256][16];
    const int tid = threadIdx.x;
    const long t0 = (long)blockIdx.x * 16;
    const int o = tid & 15;
    const int tr = tid >> 4;
    float s = 0.f;
    for (int k0 = 0; k0 < DIN; k0 += 256) {
        // As: 16 rows x 256 halves; each thread 16 halves (2 x 16B)
        {
            const int r = tid >> 4;            // 0..15
            const int cc = (tid & 15) * 16;    // 0..240
            *reinterpret_cast<uint4*>(&As[r][cc]) =
                *reinterpret_cast<const uint4*>(vh + (t0 + r) * DIN + k0 + cc);
            *reinterpret_cast<uint4*>(&As[r][cc + 8]) =
                *reinterpret_cast<const uint4*>(vh + (t0 + r) * DIN + k0 + cc + 8);
        }
        // Ws: 256 rows x 16 floats; each thread 16 floats (4 x float4)
        {
            const int r = (tid >> 0) ;          // each thread handles 1 k-row? 256 rows/256 thr
            *reinterpret_cast<float4*>(&Ws[r][0])  = *reinterpret_cast<const float4*>(Wgs + (long)(k0 + r) * 16 + 0);
            *reinterpret_cast<float4*>(&Ws[r][4])  = *reinterpret_cast<const float4*>(Wgs + (long)(k0 + r) * 16 + 4);
            *reinterpret_cast<float4*>(&Ws[r][8])  = *reinterpret_cast<const float4*>(Wgs + (long)(k0 + r) * 16 + 8);
            *reinterpret_cast<float4*>(&Ws[r][12]) = *reinterpret_cast<const float4*>(Wgs + (long)(k0 + r) * 16 + 12);
        }
        __syncthreads();
#pragma unroll 16
        for (int kk = 0; kk < 256; kk++) s += __half2float(As[tr][kk]) * Ws[kk][o];
        __syncthreads();
    }
    skipOut[(t0 + tr) * 16 + o] = s + bgs[o];
}

// ---------------------------------------------------------------------------
// weight logits -> softmax weights (one warp per token, Wg3 staged in smem)
// ---------------------------------------------------------------------------
__global__ __launch_bounds__(256)
void wlogits_kernel(const float* __restrict__ h2, const float* __restrict__ Wg3,
                    const float* __restrict__ bg3, const float* __restrict__ gg,
                    const float* __restrict__ bgn, const float* __restrict__ skipIn,
                    float* __restrict__ wout)
{
    __shared__ float Ws[256 * 32];
    const int tid = threadIdx.x;
    const int lane = tid & 31;
#pragma unroll
    for (int i = 0; i < 32; i++) Ws[tid + i * 256] = Wg3[tid + i * 256];
    __syncthreads();

    const long t = (long)blockIdx.x * 8 + (tid >> 5);
    const float* h2t = h2 + t * 256;
    float s = bg3[lane];
#pragma unroll 8
    for (int k = 0; k < 256; k += 4) {
        float4 h = *reinterpret_cast<const float4*>(h2t + k);
        s += h.x * Ws[(k + 0) * 32 + lane];
        s += h.y * Ws[(k + 1) * 32 + lane];
        s += h.z * Ws[(k + 2) * 32 + lane];
        s += h.w * Ws[(k + 3) * 32 + lane];
    }
    float bhalf = __shfl_down_sync(0xffffffffu, s, 16);
    float r = 0.f;
    if (lane < 16)
        r = s * (1.f / (1.f + expf(-bhalf))) + skipIn[t * 16 + lane];
    float sum = r;
    for (int m = 8; m; m >>= 1) sum += __shfl_xor_sync(0xffffffffu, sum, m, 16);
    float mean = sum * (1.f / 16.f);
    float d = r - mean;
    float vs = d * d;
    for (int m = 8; m; m >>= 1) vs += __shfl_xor_sync(0xffffffffu, vs, m, 16);
    float rstd = rsqrtf(vs * (1.f / 16.f) + 1e-6f);
    float ln = 0.f;
    if (lane < 16) ln = d * rstd * gg[lane] + bgn[lane];
    float mx = ln;
    for (int m = 8; m; m >>= 1) mx = fmaxf(mx, __shfl_xor_sync(0xffffffffu, mx, m, 16));
    float e = (lane < 16) ? expf(ln - mx) : 0.f;
    float se = e;
    for (int m = 8; m; m >>= 1) se += __shfl_xor_sync(0xffffffffu, se, m, 16);
    if (lane < 16) wout[t * 16 + lane] = e / se;
}

// ---------------------------------------------------------------------------
// out = sum_v LN(E[v]) * weight[v]
// Block = 1 token; 8 warps; warp w handles v = 2w, 2w+1. Per-var LN is fully
// in-warp (8 channels/lane), zero barriers in the v loop.
// ---------------------------------------------------------------------------
__global__ __launch_bounds__(256)
void enc_combine_kernel(const __half* __restrict__ E, const float* __restrict__ wout,
                        const float* __restrict__ gv, const float* __restrict__ bvn,
                        float* __restrict__ outp)
{
    const long t = blockIdx.x;
    const int tid = threadIdx.x;
    const int lane = tid & 31, wid = tid >> 5;
    __shared__ float sw[16];
    __shared__ float part[8][256];
    if (tid < 16) sw[tid] = wout[t * 16 + tid];
    __syncthreads();

    const int c0 = lane * 8;
    float acc[8];
#pragma unroll
    for (int i = 0; i < 8; i++) acc[i] = 0.f;

#pragma unroll
    for (int vi = 0; vi < 2; vi++) {
        const int v = wid * 2 + vi;
        const __half* ep = E + ((size_t)v * BT_TOK + t) * 256 + c0;
        uint4 raw = *reinterpret_cast<const uint4*>(ep);
        __half2 h01 = *reinterpret_cast<__half2*>(&raw.x);
        __half2 h23 = *reinterpret_cast<__half2*>(&raw.y);
        __half2 h45 = *reinterpret_cast<__half2*>(&raw.z);
        __half2 h67 = *reinterpret_cast<__half2*>(&raw.w);
        float e[8];
        e[0] = __half2float(h01.x); e[1] = __half2float(h01.y);
        e[2] = __half2float(h23.x); e[3] = __half2float(h23.y);
        e[4] = __half2float(h45.x); e[5] = __half2float(h45.y);
        e[6] = __half2float(h67.x); e[7] = __half2float(h67.y);
        float s1 = 0.f, s2 = 0.f;
#pragma unroll
        for (int i = 0; i < 8; i++) { s1 += e[i]; s2 += e[i] * e[i]; }
#pragma unroll
        for (int m = 16; m; m >>= 1) {
            s1 += __shfl_xor_sync(0xffffffffu, s1, m);
            s2 += __shfl_xor_sync(0xffffffffu, s2, m);
        }
        const float mean = s1 * (1.f / 256.f);
        const float var = s2 * (1.f / 256.f) - mean * mean;
        const float rstd = rsqrtf(var + 1e-6f);
        const float w = sw[v];
        const float4 g0 = *reinterpret_cast<const float4*>(gv + v * DDIM + c0);
        const float4 g1 = *reinterpret_cast<const float4*>(gv + v * DDIM + c0 + 4);
        const float4 b0 = *reinterpret_cast<const float4*>(bvn + v * DDIM + c0);
        const float4 b1 = *reinterpret_cast<const float4*>(bvn + v * DDIM + c0 + 4);
        const float gva[8] = {g0.x, g0.y, g0.z, g0.w, g1.x, g1.y, g1.z, g1.w};
        const float bva[8] = {b0.x, b0.y, b0.z, b0.w, b1.x, b1.y, b1.z, b1.w};
#pragma unroll
        for (int i = 0; i < 8; i++)
            acc[i] += ((e[i] - mean) * rstd * gva[i] + bva[i]) * w;
    }
#pragma unroll
    for (int i = 0; i < 8; i++) part[wid][c0 + i] = acc[i];
    __syncthreads();
    // 256 threads: thread c sums part[0..7][c]
    float s = 0.f;
#pragma unroll
    for (int wwi = 0; wwi < 8; wwi++) s += part[wwi][tid];
    outp[t * DDIM + tid] = s;
}

// ---------------------------------------------------------------------------
extern "C" void kernel_launch(void* const* d_in, const int* in_sizes, int n_in,
                              void* d_out, int out_size)
{
    const float* vars = (const float*)d_in[0];
    const float* Wg1  = (const float*)d_in[1];
    const float* bg1  = (const float*)d_in[2];
    const float* Wg2  = (const float*)d_in[3];
    const float* bg2  = (const float*)d_in[4];
    const float* Wg3  = (const float*)d_in[5];
    const float* bg3  = (const float*)d_in[6];
    const float* Wgs  = (const float*)d_in[7];
    const float* bgs  = (const float*)d_in[8];
    const float* gg   = (const float*)d_in[9];
    const float* bgn  = (const float*)d_in[10];
    const float* Wv1  = (const float*)d_in[11];
    const float* bv1  = (const float*)d_in[12];
    const float* Wv2  = (const float*)d_in[13];
    const float* bv2  = (const float*)d_in[14];
    const float* Wv3  = (const float*)d_in[15];
    const float* bv3  = (const float*)d_in[16];
    const float* gv   = (const float*)d_in[17];
    const float* bvn  = (const float*)d_in[18];

    float* out  = (float*)d_out;
    float* wout = out + BT_TOK * DDIM;

    unsigned char* gb = nullptr;
    cudaGetSymbolAddress((void**)&gb, g_buf);
    __half* VH  = (__half*)(gb + O_VH);
    __half* H1  = (__half*)(gb + O_H1);
    float*  H2F = (float*)(gb + O_H2F);
    __half* V1  = (__half*)(gb + O_V1);
    __half* V2  = (__half*)(gb + O_V2);
    __half* E   = (__half*)(gb + O_E);
    float*  SKP = (float*)(gb + O_SKIP);
    __half* G1T = (__half*)(gb + O_G1);
    __half* G2T = (__half*)(gb + O_G2);
    __half* W1T = (__half*)(gb + O_W1);
    __half* W2T = (__half*)(gb + O_W2);
    __half* W3T = (__half*)(gb + O_W3);

    cudaFuncSetAttribute(mma_gemm, cudaFuncAttributeMaxDynamicSharedMemorySize, SMEM_TOT);

    // conversions
    conv_split<<<65536, 256>>>(vars, VH);
    conv_wT<<<dim3(8, 128, 1), 256>>>(Wg1, G1T, 4096, 256);
    conv_wT<<<dim3(8, 8, 1),   256>>>(Wg2, G2T, 256, 256);
    conv_wT<<<dim3(8, 8, 16),  256>>>(Wv1, W1T, 256, 256);
    conv_wT<<<dim3(8, 8, 16),  256>>>(Wv2, W2T, 256, 256);
    conv_wT3<<<dim3(16, 8, 16), 256>>>(Wv3, W3T);

    // skip path
    skip_kernel<<<1024, 256>>>(VH, Wgs, bgs, SKP);

    const long long S1 = BT_TOK * 256;

    // G1: h1 = elu(flat @ Wg1 + bg1)
    mma_gemm<<<dim3(2, 128, 1), 256, SMEM_TOT>>>(
        VH, 0, DIN, G1T, 0, bg1, 0, nullptr, H1, nullptr, 0, 256, 4096, 1);
    // G2: h2 = h1 @ Wg2 + bg2 (fp32 out)
    mma_gemm<<<dim3(2, 128, 1), 256, SMEM_TOT>>>(
        H1, 0, 256, G2T, 0, bg2, 0, H2F, nullptr, nullptr, 0, 256, 256, 0);
    wlogits_kernel<<<2048, 256>>>(H2F, Wg3, bg3, gg, bgn, SKP, wout);
    // G3: hv1 = elu(x_v @ Wv1[v] + bv1[v])
    mma_gemm<<<dim3(2, 128, 16), 256, SMEM_TOT>>>(
        VH, 256, DIN, W1T, 65536, bv1, 256, nullptr, V1, nullptr, S1, 256, 256, 1);
    // G4: hv2 = hv1 @ Wv2[v] + bv2[v]
    mma_gemm<<<dim3(2, 128, 16), 256, SMEM_TOT>>>(
        V1, S1, 256, W2T, 65536, bv2, 256, nullptr, V2, nullptr, S1, 256, 256, 2);
    // G5: E = glu(hv2 @ Wv3perm[v] + bv3) + x   (N=512 interleaved -> 256 ch)
    mma_gemm<<<dim3(4, 128, 16), 256, SMEM_TOT>>>(
        V2, S1, 256, W3T, (long long)512 * 256, bv3, 512,
        nullptr, E, VH, S1, 256, 256, 3);
    // final combine
    enc_combine_kernel<<<16384, 256>>>(E, wout, gv, bvn, out);
}

// round 7
// speedup vs baseline: 1.6032x; 1.0792x over previous
#include <cuda_runtime.h>
#include <cuda_fp16.h>
#include <cstdint>

// ---------------------------------------------------------------------------
// VSN on GB300 — Round 7: R4 GEMM core + GLU-fused G5 with smem-staged
// vectorized E stores; x-add moved to enc_combine (coalesced).
// B=8,T=2048,NV=16,D=256 -> BT=16384, DIN=4096
// ---------------------------------------------------------------------------

#define BT_TOK 16384L
#define DDIM   256
#define DIN    4096

// ---------------- scratch (bytes) ----------------
#define O_VH    0ULL            // vars fp16 [16384,4096]          128MB
#define O_H1    134217728ULL    // h1 fp16 [16384,256]
#define O_H2F   142606336ULL    // h2 fp32 [16384,256]
#define O_V1    159383552ULL    // hv1 fp16 16x[16384,256]
#define O_V2    293601280ULL    // hv2 fp16 16x[16384,256]
#define O_E     427819008ULL    // E=glu fp16 16x[16384,256]       128MB
#define O_SKIP  562036736ULL    // skip fp32 [16384,16]
#define O_G1    563085312ULL    // Wg1^T fp16 [256,4096]
#define O_G2    565182464ULL    // Wg2^T fp16 [256,256]
#define O_W1    565313536ULL    // Wv1^T fp16 16x[256,256]
#define O_W2    567410688ULL
#define O_W3    569507840ULL    // Wv3^T perm fp16 16x[512,256]
#define G_TOTAL 573702144ULL

__device__ __align__(1024) unsigned char g_buf[G_TOTAL];

// ---------------- helpers ----------------
__device__ __forceinline__ uint32_t smem_u32(const void* p) {
    uint32_t a;
    asm("{ .reg .u64 t; cvta.to.shared.u64 t, %1; cvt.u32.u64 %0, t; }" : "=r"(a) : "l"(p));
    return a;
}
__device__ __forceinline__ void cpasync16(uint32_t dst, const void* src) {
    asm volatile("cp.async.cg.shared.global [%0], [%1], 16;" :: "r"(dst), "l"(src));
}
#define CP_COMMIT() asm volatile("cp.async.commit_group;" ::: "memory")
#define CP_WAIT(n)  asm volatile("cp.async.wait_group %0;" :: "n"(n) : "memory")

__device__ __forceinline__ void ldsm_x4(uint32_t (&r)[4], uint32_t addr) {
    asm volatile("ldmatrix.sync.aligned.m8n8.x4.shared.b16 {%0,%1,%2,%3}, [%4];"
        : "=r"(r[0]), "=r"(r[1]), "=r"(r[2]), "=r"(r[3]) : "r"(addr));
}
__device__ __forceinline__ void mma16816(float (&c)[4], const uint32_t (&a)[4],
                                         uint32_t b0, uint32_t b1) {
    asm volatile("mma.sync.aligned.m16n8k16.row.col.f32.f16.f16.f32 "
        "{%0,%1,%2,%3}, {%4,%5,%6,%7}, {%8,%9}, {%0,%1,%2,%3};"
        : "+f"(c[0]), "+f"(c[1]), "+f"(c[2]), "+f"(c[3])
        : "r"(a[0]), "r"(a[1]), "r"(a[2]), "r"(a[3]), "r"(b0), "r"(b1));
}

// ---------------------------------------------------------------------------
// conversions
// ---------------------------------------------------------------------------
__global__ __launch_bounds__(256)
void conv_split(const float* __restrict__ x, __half* __restrict__ h)
{
    size_t i = ((size_t)blockIdx.x * 256 + threadIdx.x) * 4;
    float4 v = *reinterpret_cast<const float4*>(x + i);
    *reinterpret_cast<__half2*>(h + i)     = __floats2half2_rn(v.x, v.y);
    *reinterpret_cast<__half2*>(h + i + 2) = __floats2half2_rn(v.z, v.w);
}

// transpose: W[K,N] -> WT[N,K] (fp16)
__global__ __launch_bounds__(256)
void conv_wT(const float* __restrict__ W, __half* __restrict__ TH, int K, int N)
{
    const size_t vb = (size_t)blockIdx.z * K * N;
    __shared__ float tile[32][33];
    const int k0 = blockIdx.y * 32, n0 = blockIdx.x * 32;
    const int tx = threadIdx.x & 31, ty = threadIdx.x >> 5;  // 32 x 8
#pragma unroll
    for (int i = 0; i < 4; i++)
        tile[ty + i * 8][tx] = W[vb + (size_t)(k0 + ty + i * 8) * N + n0 + tx];
    __syncthreads();
#pragma unroll
    for (int i = 0; i < 4; i++) {
        int n = ty + i * 8;
        TH[vb + (size_t)(n0 + n) * K + k0 + tx] = __float2half_rn(tile[tx][n]);
    }
}

// Wv3 transpose with GLU interleave: col c<256 (a_c) -> out row 2c;
// col c>=256 (b_{c-256}) -> out row 2(c-256)+1. W[256,512] -> WT3[512,256].
__global__ __launch_bounds__(256)
void conv_wT3(const float* __restrict__ W, __half* __restrict__ TH)
{
    const size_t vbs = (size_t)blockIdx.z * 256 * 512;
    const size_t vbd = (size_t)blockIdx.z * 512 * 256;
    __shared__ float tile[32][33];
    const int k0 = blockIdx.y * 32, c0 = blockIdx.x * 32;
    const int tx = threadIdx.x & 31, ty = threadIdx.x >> 5;
#pragma unroll
    for (int i = 0; i < 4; i++)
        tile[ty + i * 8][tx] = W[vbs + (size_t)(k0 + ty + i * 8) * 512 + c0 + tx];
    __syncthreads();
#pragma unroll
    for (int i = 0; i < 4; i++) {
        int c = c0 + ty + i * 8;
        int orow = (c < 256) ? (2 * c) : (2 * (c - 256) + 1);
        TH[vbd + (size_t)orow * 256 + k0 + tx] = __float2half_rn(tile[tx][ty + i * 8]);
    }
}

// ---------------------------------------------------------------------------
// fp16 mma.sync GEMM: C[128,128] tile = A[128,K] @ B^T, B stored [N,K].
// 8 warps: 2(M) x 4(N); warp tile 64x32; BK=64; 4-stage cp.async ring.
// mode: 0=fp32 out, 1=ELU+fp16, 2=fp16, 3=GLU(interleaved)->smem->fp16 E
// ---------------------------------------------------------------------------
#define RS 72                       // smem row stride (elements), 144 bytes
#define OFF_B  18432                // 128 * 72 * 2
#define ST_SIZE 36864
#define SMEM_TOT 147456             // 4 stages

__global__ __launch_bounds__(256, 1)
void mma_gemm(const __half* __restrict__ A, long long aV, int lda,
              const __half* __restrict__ BH, long long bV,
              const float* __restrict__ bias, int biasV,
              float* __restrict__ CF, __half* __restrict__ CH,
              long long cV, int ldc, int K, int mode)
{
    extern __shared__ __align__(1024) unsigned char sm[];
    const uint32_t sb = smem_u32(sm);
    const int tid = threadIdx.x;
    const int lane = tid & 31, wid = tid >> 5;
    const int wm = wid & 1, wn = wid >> 1;
    const int v = blockIdx.z;
    const int m0 = blockIdx.y * 128;
    const int nb = blockIdx.x * 128;

    const __half* Ap  = A  + (size_t)v * aV + (size_t)m0 * lda;
    const __half* Bhp = BH + (size_t)v * bV + (size_t)nb * K;

    const int lr = tid >> 3;            // 0..31 (+ t*32)
    const int lc = (tid & 7) * 8;

    float acc[4][4][4];
#pragma unroll
    for (int i = 0; i < 4; i++)
#pragma unroll
        for (int j = 0; j < 4; j++)
#pragma unroll
            for (int k = 0; k < 4; k++) acc[i][j][k] = 0.f;

    const int nc = K >> 6;

    auto load_stage = [&](int s, int k0) {
        const uint32_t base = sb + s * ST_SIZE;
#pragma unroll
        for (int t = 0; t < 4; t++) {
            const int row = lr + t * 32;
            const uint32_t doff = (uint32_t)(row * RS + lc) * 2;
            cpasync16(base + doff,         Ap  + (size_t)row * lda + k0 + lc);
            cpasync16(base + OFF_B + doff, Bhp + (size_t)row * K   + k0 + lc);
        }
    };

    const uint32_t aoff = (uint32_t)(((wm * 64 + (lane & 15)) * RS + (lane >> 4) * 8) * 2);
    const uint32_t boff = (uint32_t)(((wn * 32 + (lane & 15)) * RS + (lane >> 4) * 8) * 2);

    load_stage(0, 0);          CP_COMMIT();
    if (nc > 1) load_stage(1, 64);  CP_COMMIT();
    if (nc > 2) load_stage(2, 128); CP_COMMIT();

    for (int c = 0; c < nc; c++) {
        CP_WAIT(2);
        __syncthreads();
        const uint32_t base = sb + (c & 3) * ST_SIZE;
#pragma unroll
        for (int kc = 0; kc < 64; kc += 16) {
            uint32_t a[4][4], bh[2][4];
#pragma unroll
            for (int mt = 0; mt < 4; mt++)
                ldsm_x4(a[mt], base + aoff + mt * (16 * RS * 2) + kc * 2);
#pragma unroll
            for (int p = 0; p < 2; p++)
                ldsm_x4(bh[p], base + OFF_B + boff + p * (16 * RS * 2) + kc * 2);
#pragma unroll
            for (int mt = 0; mt < 4; mt++)
#pragma unroll
                for (int q = 0; q < 4; q++)
                    mma16816(acc[mt][q], a[mt], bh[q >> 1][q & 1], bh[q >> 1][(q & 1) + 2]);
        }
        __syncthreads();
        if (c + 3 < nc) load_stage((c + 3) & 3, (c + 3) * 64);
        CP_COMMIT();
    }

    // ---- epilogue ----
    const int gid = lane >> 2, tig = lane & 3;
    if (mode == 3) {
        // stage a*sigmoid(b) in smem [128 rows][64 channels], then coalesced out
        __half* Eg = reinterpret_cast<__half*>(sm);
        const int jbase = nb >> 1;   // global channel base for this n-tile
#pragma unroll
        for (int mt = 0; mt < 4; mt++) {
#pragma unroll
            for (int q = 0; q < 4; q++) {
                const int nl = wn * 32 + q * 8 + tig * 2;   // local n (even)
                const int jl = nl >> 1;                     // local channel 0..63
                const int jg = jbase + jl;
                const float* bp = bias + (size_t)v * biasV;
                const float ba = bp[jg], bb = bp[jg + 256];
                const int r0 = wm * 64 + mt * 16 + gid;
                float a0 = acc[mt][q][0] + ba, b0 = acc[mt][q][1] + bb;
                float a1 = acc[mt][q][2] + ba, b1 = acc[mt][q][3] + bb;
                Eg[r0 * 64 + jl]       = __float2half_rn(a0 * (1.f / (1.f + expf(-b0))));
                Eg[(r0 + 8) * 64 + jl] = __float2half_rn(a1 * (1.f / (1.f + expf(-b1))));
            }
        }
        __syncthreads();
        // copy out: 128 rows x 64 halves; thread -> (row = tid>>1, 32-half chunk)
        const int row = tid >> 1;
        const int ch = (tid & 1) * 32;
        const __half* src = Eg + row * 64 + ch;
        __half* dst = CH + (size_t)v * cV + (size_t)(m0 + row) * ldc + jbase + ch;
#pragma unroll
        for (int u = 0; u < 4; u++)
            *reinterpret_cast<uint4*>(dst + u * 8) =
                *reinterpret_cast<const uint4*>(src + u * 8);
        return;
    }
#pragma unroll
    for (int mt = 0; mt < 4; mt++) {
#pragma unroll
        for (int q = 0; q < 4; q++) {
            const int m = m0 + wm * 64 + mt * 16 + gid;
            const int n = nb + wn * 32 + q * 8 + tig * 2;
            const float* bp = bias + (size_t)v * biasV + n;
            const float b0 = bp[0], b1 = bp[1];
            float x0 = acc[mt][q][0] + b0, x1 = acc[mt][q][1] + b1;
            float y0 = acc[mt][q][2] + b0, y1 = acc[mt][q][3] + b1;
            if (mode == 1) {
                x0 = (x0 > 0.f) ? x0 : expm1f(x0);
                x1 = (x1 > 0.f) ? x1 : expm1f(x1);
                y0 = (y0 > 0.f) ? y0 : expm1f(y0);
                y1 = (y1 > 0.f) ? y1 : expm1f(y1);
            }
            if (mode == 0) {
                float* d0 = CF + (size_t)v * cV + (size_t)m * ldc + n;
                float2 o0; o0.x = x0; o0.y = x1;
                float2 o1; o1.x = y0; o1.y = y1;
                *reinterpret_cast<float2*>(d0) = o0;
                *reinterpret_cast<float2*>(d0 + 8 * ldc) = o1;
            } else {
                __half* d0 = CH + (size_t)v * cV + (size_t)m * ldc + n;
                *reinterpret_cast<__half2*>(d0) = __floats2half2_rn(x0, x1);
                *reinterpret_cast<__half2*>(d0 + 8 * ldc) = __floats2half2_rn(y0, y1);
            }
        }
    }
}

// ---------------------------------------------------------------------------
// skip = flat @ Wgs + bgs (fp16 VH), K-chunk 256
// ---------------------------------------------------------------------------
__global__ __launch_bounds__(256)
void skip_kernel(const __half* __restrict__ vh, const float* __restrict__ Wgs,
                 const float* __restrict__ bgs, float* __restrict__ skipOut)
{
    __shared__ __half As[16][256];
    __shared__ float Ws[256][16];
    const int tid = threadIdx.x;
    const long t0 = (long)blockIdx.x * 16;
    const int o = tid & 15;
    const int tr = tid >> 4;
    float s = 0.f;
    for (int k0 = 0; k0 < DIN; k0 += 256) {
        {
            const int r = tid >> 4;
            const int cc = (tid & 15) * 16;
            *reinterpret_cast<uint4*>(&As[r][cc]) =
                *reinterpret_cast<const uint4*>(vh + (t0 + r) * DIN + k0 + cc);
            *reinterpret_cast<uint4*>(&As[r][cc + 8]) =
                *reinterpret_cast<const uint4*>(vh + (t0 + r) * DIN + k0 + cc + 8);
        }
        {
            const int r = tid;
            *reinterpret_cast<float4*>(&Ws[r][0])  = *reinterpret_cast<const float4*>(Wgs + (long)(k0 + r) * 16 + 0);
            *reinterpret_cast<float4*>(&Ws[r][4])  = *reinterpret_cast<const float4*>(Wgs + (long)(k0 + r) * 16 + 4);
            *reinterpret_cast<float4*>(&Ws[r][8])  = *reinterpret_cast<const float4*>(Wgs + (long)(k0 + r) * 16 + 8);
            *reinterpret_cast<float4*>(&Ws[r][12]) = *reinterpret_cast<const float4*>(Wgs + (long)(k0 + r) * 16 + 12);
        }
        __syncthreads();
#pragma unroll 16
        for (int kk = 0; kk < 256; kk++) s += __half2float(As[tr][kk]) * Ws[kk][o];
        __syncthreads();
    }
    skipOut[(t0 + tr) * 16 + o] = s + bgs[o];
}

// ---------------------------------------------------------------------------
// weight logits -> softmax weights (one warp per token, Wg3 staged in smem)
// ---------------------------------------------------------------------------
__global__ __launch_bounds__(256)
void wlogits_kernel(const float* __restrict__ h2, const float* __restrict__ Wg3,
                    const float* __restrict__ bg3, const float* __restrict__ gg,
                    const float* __restrict__ bgn, const float* __restrict__ skipIn,
                    float* __restrict__ wout)
{
    __shared__ float Ws[256 * 32];
    const int tid = threadIdx.x;
    const int lane = tid & 31;
#pragma unroll
    for (int i = 0; i < 32; i++) Ws[tid + i * 256] = Wg3[tid + i * 256];
    __syncthreads();

    const long t = (long)blockIdx.x * 8 + (tid >> 5);
    const float* h2t = h2 + t * 256;
    float s = bg3[lane];
#pragma unroll 8
    for (int k = 0; k < 256; k += 4) {
        float4 h = *reinterpret_cast<const float4*>(h2t + k);
        s += h.x * Ws[(k + 0) * 32 + lane];
        s += h.y * Ws[(k + 1) * 32 + lane];
        s += h.z * Ws[(k + 2) * 32 + lane];
        s += h.w * Ws[(k + 3) * 32 + lane];
    }
    float bhalf = __shfl_down_sync(0xffffffffu, s, 16);
    float r = 0.f;
    if (lane < 16)
        r = s * (1.f / (1.f + expf(-bhalf))) + skipIn[t * 16 + lane];
    float sum = r;
    for (int m = 8; m; m >>= 1) sum += __shfl_xor_sync(0xffffffffu, sum, m, 16);
    float mean = sum * (1.f / 16.f);
    float d = r - mean;
    float vs = d * d;
    for (int m = 8; m; m >>= 1) vs += __shfl_xor_sync(0xffffffffu, vs, m, 16);
    float rstd = rsqrtf(vs * (1.f / 16.f) + 1e-6f);
    float ln = 0.f;
    if (lane < 16) ln = d * rstd * gg[lane] + bgn[lane];
    float mx = ln;
    for (int m = 8; m; m >>= 1) mx = fmaxf(mx, __shfl_xor_sync(0xffffffffu, mx, m, 16));
    float e = (lane < 16) ? expf(ln - mx) : 0.f;
    float se = e;
    for (int m = 8; m; m >>= 1) se += __shfl_xor_sync(0xffffffffu, se, m, 16);
    if (lane < 16) wout[t * 16 + lane] = e / se;
}

// ---------------------------------------------------------------------------
// out = sum_v LN(E[v] + x[v]) * weight[v]
// Block = 1 token; warp w handles v = 2w, 2w+1; in-warp LN (8 ch/lane).
// ---------------------------------------------------------------------------
__global__ __launch_bounds__(256)
void enc_combine_kernel(const __half* __restrict__ E, const __half* __restrict__ vh,
                        const float* __restrict__ wout, const float* __restrict__ gv,
                        const float* __restrict__ bvn, float* __restrict__ outp)
{
    const long t = blockIdx.x;
    const int tid = threadIdx.x;
    const int lane = tid & 31, wid = tid >> 5;
    __shared__ float sw[16];
    __shared__ float part[8][256];
    if (tid < 16) sw[tid] = wout[t * 16 + tid];
    __syncthreads();

    const int c0 = lane * 8;
    float acc[8];
#pragma unroll
    for (int i = 0; i < 8; i++) acc[i] = 0.f;

#pragma unroll
    for (int vi = 0; vi < 2; vi++) {
        const int v = wid * 2 + vi;
        uint4 rawE = *reinterpret_cast<const uint4*>(
            E + ((size_t)v * BT_TOK + t) * 256 + c0);
        uint4 rawX = *reinterpret_cast<const uint4*>(
            vh + (size_t)t * DIN + v * DDIM + c0);
        const __half2* he = reinterpret_cast<const __half2*>(&rawE);
        const __half2* hx = reinterpret_cast<const __half2*>(&rawX);
        float e[8];
#pragma unroll
        for (int i = 0; i < 4; i++) {
            float2 fe = __half22float2(he[i]);
            float2 fx = __half22float2(hx[i]);
            e[2 * i]     = fe.x + fx.x;
            e[2 * i + 1] = fe.y + fx.y;
        }
        float s1 = 0.f, s2 = 0.f;
#pragma unroll
        for (int i = 0; i < 8; i++) { s1 += e[i]; s2 += e[i] * e[i]; }
#pragma unroll
        for (int m = 16; m; m >>= 1) {
            s1 += __shfl_xor_sync(0xffffffffu, s1, m);
            s2 += __shfl_xor_sync(0xffffffffu, s2, m);
        }
        const float mean = s1 * (1.f / 256.f);
        const float var = s2 * (1.f / 256.f) - mean * mean;
        const float rstd = rsqrtf(var + 1e-6f);
        const float w = sw[v];
        const float4 g0 = *reinterpret_cast<const float4*>(gv + v * DDIM + c0);
        const float4 g1 = *reinterpret_cast<const float4*>(gv + v * DDIM + c0 + 4);
        const float4 b0 = *reinterpret_cast<const float4*>(bvn + v * DDIM + c0);
        const float4 b1 = *reinterpret_cast<const float4*>(bvn + v * DDIM + c0 + 4);
        const float gva[8] = {g0.x, g0.y, g0.z, g0.w, g1.x, g1.y, g1.z, g1.w};
        const float bva[8] = {b0.x, b0.y, b0.z, b0.w, b1.x, b1.y, b1.z, b1.w};
#pragma unroll
        for (int i = 0; i < 8; i++)
            acc[i] += ((e[i] - mean) * rstd * gva[i] + bva[i]) * w;
    }
#pragma unroll
    for (int i = 0; i < 8; i++) part[wid][c0 + i] = acc[i];
    __syncthreads();
    float s = 0.f;
#pragma unroll
    for (int wwi = 0; wwi < 8; wwi++) s += part[wwi][tid];
    outp[t * DDIM + tid] = s;
}

// ---------------------------------------------------------------------------
extern "C" void kernel_launch(void* const* d_in, const int* in_sizes, int n_in,
                              void* d_out, int out_size)
{
    const float* vars = (const float*)d_in[0];
    const float* Wg1  = (const float*)d_in[1];
    const float* bg1  = (const float*)d_in[2];
    const float* Wg2  = (const float*)d_in[3];
    const float* bg2  = (const float*)d_in[4];
    const float* Wg3  = (const float*)d_in[5];
    const float* bg3  = (const float*)d_in[6];
    const float* Wgs  = (const float*)d_in[7];
    const float* bgs  = (const float*)d_in[8];
    const float* gg   = (const float*)d_in[9];
    const float* bgn  = (const float*)d_in[10];
    const float* Wv1  = (const float*)d_in[11];
    const float* bv1  = (const float*)d_in[12];
    const float* Wv2  = (const float*)d_in[13];
    const float* bv2  = (const float*)d_in[14];
    const float* Wv3  = (const float*)d_in[15];
    const float* bv3  = (const float*)d_in[16];
    const float* gv   = (const float*)d_in[17];
    const float* bvn  = (const float*)d_in[18];

    float* out  = (float*)d_out;
    float* wout = out + BT_TOK * DDIM;

    unsigned char* gb = nullptr;
    cudaGetSymbolAddress((void**)&gb, g_buf);
    __half* VH  = (__half*)(gb + O_VH);
    __half* H1  = (__half*)(gb + O_H1);
    float*  H2F = (float*)(gb + O_H2F);
    __half* V1  = (__half*)(gb + O_V1);
    __half* V2  = (__half*)(gb + O_V2);
    __half* E   = (__half*)(gb + O_E);
    float*  SKP = (float*)(gb + O_SKIP);
    __half* G1T = (__half*)(gb + O_G1);
    __half* G2T = (__half*)(gb + O_G2);
    __half* W1T = (__half*)(gb + O_W1);
    __half* W2T = (__half*)(gb + O_W2);
    __half* W3T = (__half*)(gb + O_W3);

    cudaFuncSetAttribute(mma_gemm, cudaFuncAttributeMaxDynamicSharedMemorySize, SMEM_TOT);

    // conversions
    conv_split<<<65536, 256>>>(vars, VH);
    conv_wT<<<dim3(8, 128, 1), 256>>>(Wg1, G1T, 4096, 256);
    conv_wT<<<dim3(8, 8, 1),   256>>>(Wg2, G2T, 256, 256);
    conv_wT<<<dim3(8, 8, 16),  256>>>(Wv1, W1T, 256, 256);
    conv_wT<<<dim3(8, 8, 16),  256>>>(Wv2, W2T, 256, 256);
    conv_wT3<<<dim3(16, 8, 16), 256>>>(Wv3, W3T);

    // skip path
    skip_kernel<<<1024, 256>>>(VH, Wgs, bgs, SKP);

    const long long S1 = BT_TOK * 256;

    // G1: h1 = elu(flat @ Wg1 + bg1)
    mma_gemm<<<dim3(2, 128, 1), 256, SMEM_TOT>>>(
        VH, 0, DIN, G1T, 0, bg1, 0, nullptr, H1, 0, 256, 4096, 1);
    // G2: h2 = h1 @ Wg2 + bg2 (fp32 out)
    mma_gemm<<<dim3(2, 128, 1), 256, SMEM_TOT>>>(
        H1, 0, 256, G2T, 0, bg2, 0, H2F, nullptr, 0, 256, 256, 0);
    wlogits_kernel<<<2048, 256>>>(H2F, Wg3, bg3, gg, bgn, SKP, wout);
    // G3: hv1 = elu(x_v @ Wv1[v] + bv1[v])
    mma_gemm<<<dim3(2, 128, 16), 256, SMEM_TOT>>>(
        VH, 256, DIN, W1T, 65536, bv1, 256, nullptr, V1, S1, 256, 256, 1);
    // G4: hv2 = hv1 @ Wv2[v] + bv2[v]
    mma_gemm<<<dim3(2, 128, 16), 256, SMEM_TOT>>>(
        V1, S1, 256, W2T, 65536, bv2, 256, nullptr, V2, S1, 256, 256, 2);
    // G5: E = glu(hv2 @ Wv3perm[v] + bv3)   (N=512 interleaved -> 256 ch)
    mma_gemm<<<dim3(4, 128, 16), 256, SMEM_TOT>>>(
        V2, S1, 256, W3T, (long long)512 * 256, bv3, 512,
        nullptr, E, S1, 256, 256, 3);
    // final combine (adds x, LN, weighted sum)
    enc_combine_kernel<<<16384, 256>>>(E, VH, wout, gv, bvn, out);
}

// round 8
// speedup vs baseline: 1.7283x; 1.0780x over previous
#include <cuda_runtime.h>
#include <cuda_fp16.h>
#include <cstdint>

// ---------------------------------------------------------------------------
// VSN on GB300 — Round 8: fully-fused per-variable chain (G3+G4+G5+GLU) in one
// kernel with smem-resident activations; R7 core for G1/G2; fp16 E buffer.
// B=8,T=2048,NV=16,D=256 -> BT=16384, DIN=4096
// ---------------------------------------------------------------------------

#define BT_TOK 16384L
#define DDIM   256
#define DIN    4096

// ---------------- scratch (bytes) ----------------
#define O_VH    0ULL            // vars fp16 [16384,4096]          128MB
#define O_H1    134217728ULL    // h1 fp16 [16384,256]
#define O_H2F   142606336ULL    // h2 fp32 [16384,256]
#define O_E     159383552ULL    // E=glu fp16 16x[16384,256]       128MB
#define O_SKIP  293601280ULL    // skip fp32 [16384,16]
#define O_G1    294649856ULL    // Wg1^T fp16 [256,4096]
#define O_G2    296747008ULL    // Wg2^T fp16 [256,256]
#define O_W1    296878080ULL    // Wv1^T fp16 16x[256,256]
#define O_W2    298975232ULL
#define O_W3    301072384ULL    // Wv3^T perm fp16 16x[512,256]
#define G_TOTAL 305266688ULL

__device__ __align__(1024) unsigned char g_buf[G_TOTAL];

// ---------------- helpers ----------------
__device__ __forceinline__ uint32_t smem_u32(const void* p) {
    uint32_t a;
    asm("{ .reg .u64 t; cvta.to.shared.u64 t, %1; cvt.u32.u64 %0, t; }" : "=r"(a) : "l"(p));
    return a;
}
__device__ __forceinline__ void cpasync16(uint32_t dst, const void* src) {
    asm volatile("cp.async.cg.shared.global [%0], [%1], 16;" :: "r"(dst), "l"(src));
}
#define CP_COMMIT() asm volatile("cp.async.commit_group;" ::: "memory")
#define CP_WAIT(n)  asm volatile("cp.async.wait_group %0;" :: "n"(n) : "memory")

__device__ __forceinline__ void ldsm_x4(uint32_t (&r)[4], uint32_t addr) {
    asm volatile("ldmatrix.sync.aligned.m8n8.x4.shared.b16 {%0,%1,%2,%3}, [%4];"
        : "=r"(r[0]), "=r"(r[1]), "=r"(r[2]), "=r"(r[3]) : "r"(addr));
}
__device__ __forceinline__ void mma16816(float (&c)[4], const uint32_t (&a)[4],
                                         uint32_t b0, uint32_t b1) {
    asm volatile("mma.sync.aligned.m16n8k16.row.col.f32.f16.f16.f32 "
        "{%0,%1,%2,%3}, {%4,%5,%6,%7}, {%8,%9}, {%0,%1,%2,%3};"
        : "+f"(c[0]), "+f"(c[1]), "+f"(c[2]), "+f"(c[3])
        : "r"(a[0]), "r"(a[1]), "r"(a[2]), "r"(a[3]), "r"(b0), "r"(b1));
}

// ---------------------------------------------------------------------------
// conversions
// ---------------------------------------------------------------------------
__global__ __launch_bounds__(256)
void conv_split(const float* __restrict__ x, __half* __restrict__ h)
{
    size_t i = ((size_t)blockIdx.x * 256 + threadIdx.x) * 4;
    float4 v = *reinterpret_cast<const float4*>(x + i);
    *reinterpret_cast<__half2*>(h + i)     = __floats2half2_rn(v.x, v.y);
    *reinterpret_cast<__half2*>(h + i + 2) = __floats2half2_rn(v.z, v.w);
}

__global__ __launch_bounds__(256)
void conv_wT(const float* __restrict__ W, __half* __restrict__ TH, int K, int N)
{
    const size_t vb = (size_t)blockIdx.z * K * N;
    __shared__ float tile[32][33];
    const int k0 = blockIdx.y * 32, n0 = blockIdx.x * 32;
    const int tx = threadIdx.x & 31, ty = threadIdx.x >> 5;
#pragma unroll
    for (int i = 0; i < 4; i++)
        tile[ty + i * 8][tx] = W[vb + (size_t)(k0 + ty + i * 8) * N + n0 + tx];
    __syncthreads();
#pragma unroll
    for (int i = 0; i < 4; i++) {
        int n = ty + i * 8;
        TH[vb + (size_t)(n0 + n) * K + k0 + tx] = __float2half_rn(tile[tx][n]);
    }
}

// Wv3 transpose with GLU interleave: col c<256 -> row 2c; col c>=256 -> row 2(c-256)+1
__global__ __launch_bounds__(256)
void conv_wT3(const float* __restrict__ W, __half* __restrict__ TH)
{
    const size_t vbs = (size_t)blockIdx.z * 256 * 512;
    const size_t vbd = (size_t)blockIdx.z * 512 * 256;
    __shared__ float tile[32][33];
    const int k0 = blockIdx.y * 32, c0 = blockIdx.x * 32;
    const int tx = threadIdx.x & 31, ty = threadIdx.x >> 5;
#pragma unroll
    for (int i = 0; i < 4; i++)
        tile[ty + i * 8][tx] = W[vbs + (size_t)(k0 + ty + i * 8) * 512 + c0 + tx];
    __syncthreads();
#pragma unroll
    for (int i = 0; i < 4; i++) {
        int c = c0 + ty + i * 8;
        int orow = (c < 256) ? (2 * c) : (2 * (c - 256) + 1);
        TH[vbd + (size_t)orow * 256 + k0 + tx] = __float2half_rn(tile[tx][ty + i * 8]);
    }
}

// ---------------------------------------------------------------------------
// mma_gemm (R7): for G1 (mode1) and G2 (mode0). BK=64, 4-stage cp.async.
// ---------------------------------------------------------------------------
#define RS 72
#define OFF_B  18432
#define ST_SIZE 36864
#define SMEM_TOT 147456

__global__ __launch_bounds__(256, 1)
void mma_gemm(const __half* __restrict__ A, long long aV, int lda,
              const __half* __restrict__ BH, long long bV,
              const float* __restrict__ bias, int biasV,
              float* __restrict__ CF, __half* __restrict__ CH,
              long long cV, int ldc, int K, int mode)
{
    extern __shared__ __align__(1024) unsigned char sm[];
    const uint32_t sb = smem_u32(sm);
    const int tid = threadIdx.x;
    const int lane = tid & 31, wid = tid >> 5;
    const int wm = wid & 1, wn = wid >> 1;
    const int v = blockIdx.z;
    const int m0 = blockIdx.y * 128;
    const int nb = blockIdx.x * 128;

    const __half* Ap  = A  + (size_t)v * aV + (size_t)m0 * lda;
    const __half* Bhp = BH + (size_t)v * bV + (size_t)nb * K;

    const int lr = tid >> 3;
    const int lc = (tid & 7) * 8;

    float acc[4][4][4];
#pragma unroll
    for (int i = 0; i < 4; i++)
#pragma unroll
        for (int j = 0; j < 4; j++)
#pragma unroll
            for (int k = 0; k < 4; k++) acc[i][j][k] = 0.f;

    const int nc = K >> 6;

    auto load_stage = [&](int s, int k0) {
        const uint32_t base = sb + s * ST_SIZE;
#pragma unroll
        for (int t = 0; t < 4; t++) {
            const int row = lr + t * 32;
            const uint32_t doff = (uint32_t)(row * RS + lc) * 2;
            cpasync16(base + doff,         Ap  + (size_t)row * lda + k0 + lc);
            cpasync16(base + OFF_B + doff, Bhp + (size_t)row * K   + k0 + lc);
        }
    };

    const uint32_t aoff = (uint32_t)(((wm * 64 + (lane & 15)) * RS + (lane >> 4) * 8) * 2);
    const uint32_t boff = (uint32_t)(((wn * 32 + (lane & 15)) * RS + (lane >> 4) * 8) * 2);

    load_stage(0, 0);          CP_COMMIT();
    if (nc > 1) load_stage(1, 64);  CP_COMMIT();
    if (nc > 2) load_stage(2, 128); CP_COMMIT();

    for (int c = 0; c < nc; c++) {
        CP_WAIT(2);
        __syncthreads();
        const uint32_t base = sb + (c & 3) * ST_SIZE;
#pragma unroll
        for (int kc = 0; kc < 64; kc += 16) {
            uint32_t a[4][4], bh[2][4];
#pragma unroll
            for (int mt = 0; mt < 4; mt++)
                ldsm_x4(a[mt], base + aoff + mt * (16 * RS * 2) + kc * 2);
#pragma unroll
            for (int p = 0; p < 2; p++)
                ldsm_x4(bh[p], base + OFF_B + boff + p * (16 * RS * 2) + kc * 2);
#pragma unroll
            for (int mt = 0; mt < 4; mt++)
#pragma unroll
                for (int q = 0; q < 4; q++)
                    mma16816(acc[mt][q], a[mt], bh[q >> 1][q & 1], bh[q >> 1][(q & 1) + 2]);
        }
        __syncthreads();
        if (c + 3 < nc) load_stage((c + 3) & 3, (c + 3) * 64);
        CP_COMMIT();
    }

    const int gid = lane >> 2, tig = lane & 3;
#pragma unroll
    for (int mt = 0; mt < 4; mt++) {
#pragma unroll
        for (int q = 0; q < 4; q++) {
            const int m = m0 + wm * 64 + mt * 16 + gid;
            const int n = nb + wn * 32 + q * 8 + tig * 2;
            const float* bp = bias + (size_t)v * biasV + n;
            const float b0 = bp[0], b1 = bp[1];
            float x0 = acc[mt][q][0] + b0, x1 = acc[mt][q][1] + b1;
            float y0 = acc[mt][q][2] + b0, y1 = acc[mt][q][3] + b1;
            if (mode == 1) {
                x0 = (x0 > 0.f) ? x0 : expm1f(x0);
                x1 = (x1 > 0.f) ? x1 : expm1f(x1);
                y0 = (y0 > 0.f) ? y0 : expm1f(y0);
                y1 = (y1 > 0.f) ? y1 : expm1f(y1);
            }
            if (mode == 0) {
                float* d0 = CF + (size_t)v * cV + (size_t)m * ldc + n;
                float2 o0; o0.x = x0; o0.y = x1;
                float2 o1; o1.x = y0; o1.y = y1;
                *reinterpret_cast<float2*>(d0) = o0;
                *reinterpret_cast<float2*>(d0 + 8 * ldc) = o1;
            } else {
                __half* d0 = CH + (size_t)v * cV + (size_t)m * ldc + n;
                *reinterpret_cast<__half2*>(d0) = __floats2half2_rn(x0, x1);
                *reinterpret_cast<__half2*>(d0 + 8 * ldc) = __floats2half2_rn(y0, y1);
            }
        }
    }
}

// ---------------------------------------------------------------------------
// fused per-variable chain: E = glu(elu(x@W1+b1)@W2+b2 @ W3perm + b3)
// grid (128 m-tiles, 16 vars), 256 threads, 1 CTA/SM.
// smem: A0 (4 chunks x 18432), A1 (same), WB (2 x 18432) = 184320 B.
// Activation buffers use the chunk layout: chunk c holds k in [64c,64c+64),
// addr = buf + c*18432 + row*144 + (k%64)*2  (RS=72 halves).
// ---------------------------------------------------------------------------
#define FA0 0u
#define FA1 73728u
#define FWB 147456u
#define FSMEM 184320

__global__ __launch_bounds__(256, 1)
void fused_var(const __half* __restrict__ VH,
               const __half* __restrict__ W1T, const __half* __restrict__ W2T,
               const __half* __restrict__ W3T,
               const float* __restrict__ bv1, const float* __restrict__ bv2,
               const float* __restrict__ bv3,
               __half* __restrict__ E)
{
    extern __shared__ __align__(1024) unsigned char sm[];
    const uint32_t sb = smem_u32(sm);
    const int tid = threadIdx.x;
    const int lane = tid & 31, wid = tid >> 5;
    const int wm = wid & 1, wn = wid >> 1;
    const int gid = lane >> 2, tig = lane & 3;
    const int v = blockIdx.y;
    const int m0 = blockIdx.x * 128;

    // ---- load x_v tile [128,256] into A0 (4 chunks) ----
    {
        const __half* xp = VH + (size_t)m0 * DIN + v * 256;
#pragma unroll
        for (int t = 0; t < 16; t++) {
            const int id = tid + t * 256;
            const int ch = id >> 10;          // chunk 0..3
            const int rem = id & 1023;
            const int row = rem >> 3;
            const int lc8 = (rem & 7) * 8;
            cpasync16(sb + FA0 + ch * 18432 + (uint32_t)(row * RS + lc8) * 2,
                      xp + (size_t)row * DIN + ch * 64 + lc8);
        }
        CP_COMMIT();
    }

    const uint32_t aoff = (uint32_t)(((wm * 64 + (lane & 15)) * RS + (lane >> 4) * 8) * 2);
    const uint32_t boff = (uint32_t)(((wn * 32 + (lane & 15)) * RS + (lane >> 4) * 8) * 2);
    const int lr = tid >> 3;
    const int lc = (tid & 7) * 8;

    for (int stage = 0; stage < 3; stage++) {
        const __half* W = (stage == 0) ? (W1T + (size_t)v * 65536)
                        : (stage == 1) ? (W2T + (size_t)v * 65536)
                                       : (W3T + (size_t)v * 131072);
        const int nPass = (stage == 2) ? 4 : 2;
        const uint32_t aBuf = (stage == 1) ? FA1 : FA0;
        const uint32_t oBuf = (stage == 0) ? FA1 : FA0;

        for (int np = 0; np < nPass; np++) {
            float acc[4][4][4];
#pragma unroll
            for (int i = 0; i < 4; i++)
#pragma unroll
                for (int j = 0; j < 4; j++)
#pragma unroll
                    for (int k = 0; k < 4; k++) acc[i][j][k] = 0.f;

            const __half* Wp = W + (size_t)(np * 128) * 256;
            // prologue: chunks 0,1 into slots 0,1
#pragma unroll
            for (int pc = 0; pc < 2; pc++) {
#pragma unroll
                for (int t = 0; t < 4; t++) {
                    const int row = lr + t * 32;
                    cpasync16(sb + FWB + pc * 18432 + (uint32_t)(row * RS + lc) * 2,
                              Wp + (size_t)row * 256 + pc * 64 + lc);
                }
                CP_COMMIT();
            }

            for (int c = 0; c < 4; c++) {
                if (c < 3) { CP_WAIT(1); } else { CP_WAIT(0); }
                __syncthreads();
                const uint32_t abase = sb + aBuf + c * 18432;
                const uint32_t bbase = sb + FWB + (c & 1) * 18432;
#pragma unroll
                for (int kc = 0; kc < 64; kc += 16) {
                    uint32_t a[4][4], bh[2][4];
#pragma unroll
                    for (int mt = 0; mt < 4; mt++)
                        ldsm_x4(a[mt], abase + aoff + mt * (16 * RS * 2) + kc * 2);
#pragma unroll
                    for (int p = 0; p < 2; p++)
                        ldsm_x4(bh[p], bbase + boff + p * (16 * RS * 2) + kc * 2);
#pragma unroll
                    for (int mt = 0; mt < 4; mt++)
#pragma unroll
                        for (int q = 0; q < 4; q++)
                            mma16816(acc[mt][q], a[mt], bh[q >> 1][q & 1], bh[q >> 1][(q & 1) + 2]);
                }
                __syncthreads();
                if (c + 2 < 4) {
#pragma unroll
                    for (int t = 0; t < 4; t++) {
                        const int row = lr + t * 32;
                        cpasync16(sb + FWB + (c & 1) * 18432 + (uint32_t)(row * RS + lc) * 2,
                                  Wp + (size_t)row * 256 + (c + 2) * 64 + lc);
                    }
                    CP_COMMIT();
                }
            }

            // ---- epilogue ----
            if (stage < 2) {
                // write act(acc+bias) into oBuf chunk layout at global n = np*128+local
                const float* bp = ((stage == 0) ? bv1 : bv2) + (size_t)v * 256;
                __half* ob = reinterpret_cast<__half*>(sm) + (oBuf >> 1);
#pragma unroll
                for (int mt = 0; mt < 4; mt++) {
#pragma unroll
                    for (int q = 0; q < 4; q++) {
                        const int m = wm * 64 + mt * 16 + gid;
                        const int gn = np * 128 + wn * 32 + q * 8 + tig * 2;
                        const float b0 = bp[gn], b1 = bp[gn + 1];
                        float x0 = acc[mt][q][0] + b0, x1 = acc[mt][q][1] + b1;
                        float y0 = acc[mt][q][2] + b0, y1 = acc[mt][q][3] + b1;
                        if (stage == 0) {
                            x0 = (x0 > 0.f) ? x0 : expm1f(x0);
                            x1 = (x1 > 0.f) ? x1 : expm1f(x1);
                            y0 = (y0 > 0.f) ? y0 : expm1f(y0);
                            y1 = (y1 > 0.f) ? y1 : expm1f(y1);
                        }
                        const int ch = gn >> 6;
                        const int ko = gn & 63;
                        __half* d0 = ob + ch * 9216 + m * RS + ko;
                        *reinterpret_cast<__half2*>(d0) = __floats2half2_rn(x0, x1);
                        *reinterpret_cast<__half2*>(d0 + 8 * RS) = __floats2half2_rn(y0, y1);
                    }
                }
                __syncthreads();   // outputs visible before next pass/stage reads
            } else {
                // GLU epilogue -> stage in A1 [128][64] -> coalesced E store
                const float* bp = bv3 + (size_t)v * 512;
                const int jbase = np * 64;
                __half* Eg = reinterpret_cast<__half*>(sm) + (FA1 >> 1);
#pragma unroll
                for (int mt = 0; mt < 4; mt++) {
#pragma unroll
                    for (int q = 0; q < 4; q++) {
                        const int nl = wn * 32 + q * 8 + tig * 2;
                        const int jl = nl >> 1;
                        const int jg = jbase + jl;
                        const float ba = bp[jg], bb = bp[jg + 256];
                        const int r0 = wm * 64 + mt * 16 + gid;
                        float a0 = acc[mt][q][0] + ba, b0 = acc[mt][q][1] + bb;
                        float a1 = acc[mt][q][2] + ba, b1 = acc[mt][q][3] + bb;
                        Eg[r0 * 64 + jl]       = __float2half_rn(a0 * (1.f / (1.f + expf(-b0))));
                        Eg[(r0 + 8) * 64 + jl] = __float2half_rn(a1 * (1.f / (1.f + expf(-b1))));
                    }
                }
                __syncthreads();
                const int row = tid >> 1;
                const int chh = (tid & 1) * 32;
                const __half* src = Eg + row * 64 + chh;
                __half* dst = E + ((size_t)v * BT_TOK + m0 + row) * 256 + jbase + chh;
#pragma unroll
                for (int u = 0; u < 4; u++)
                    *reinterpret_cast<uint4*>(dst + u * 8) =
                        *reinterpret_cast<const uint4*>(src + u * 8);
                __syncthreads();   // before reusing Eg staging next pass
            }
        }
    }
}

// ---------------------------------------------------------------------------
// skip = flat @ Wgs + bgs (fp16 VH), K-chunk 256
// ---------------------------------------------------------------------------
__global__ __launch_bounds__(256)
void skip_kernel(const __half* __restrict__ vh, const float* __restrict__ Wgs,
                 const float* __restrict__ bgs, float* __restrict__ skipOut)
{
    __shared__ __half As[16][256];
    __shared__ float Ws[256][16];
    const int tid = threadIdx.x;
    const long t0 = (long)blockIdx.x * 16;
    const int o = tid & 15;
    const int tr = tid >> 4;
    float s = 0.f;
    for (int k0 = 0; k0 < DIN; k0 += 256) {
        {
            const int r = tid >> 4;
            const int cc = (tid & 15) * 16;
            *reinterpret_cast<uint4*>(&As[r][cc]) =
                *reinterpret_cast<const uint4*>(vh + (t0 + r) * DIN + k0 + cc);
            *reinterpret_cast<uint4*>(&As[r][cc + 8]) =
                *reinterpret_cast<const uint4*>(vh + (t0 + r) * DIN + k0 + cc + 8);
        }
        {
            const int r = tid;
            *reinterpret_cast<float4*>(&Ws[r][0])  = *reinterpret_cast<const float4*>(Wgs + (long)(k0 + r) * 16 + 0);
            *reinterpret_cast<float4*>(&Ws[r][4])  = *reinterpret_cast<const float4*>(Wgs + (long)(k0 + r) * 16 + 4);
            *reinterpret_cast<float4*>(&Ws[r][8])  = *reinterpret_cast<const float4*>(Wgs + (long)(k0 + r) * 16 + 8);
            *reinterpret_cast<float4*>(&Ws[r][12]) = *reinterpret_cast<const float4*>(Wgs + (long)(k0 + r) * 16 + 12);
        }
        __syncthreads();
#pragma unroll 16
        for (int kk = 0; kk < 256; kk++) s += __half2float(As[tr][kk]) * Ws[kk][o];
        __syncthreads();
    }
    skipOut[(t0 + tr) * 16 + o] = s + bgs[o];
}

// ---------------------------------------------------------------------------
// weight logits -> softmax weights
// ---------------------------------------------------------------------------
__global__ __launch_bounds__(256)
void wlogits_kernel(const float* __restrict__ h2, const float* __restrict__ Wg3,
                    const float* __restrict__ bg3, const float* __restrict__ gg,
                    const float* __restrict__ bgn, const float* __restrict__ skipIn,
                    float* __restrict__ wout)
{
    __shared__ float Ws[256 * 32];
    const int tid = threadIdx.x;
    const int lane = tid & 31;
#pragma unroll
    for (int i = 0; i < 32; i++) Ws[tid + i * 256] = Wg3[tid + i * 256];
    __syncthreads();

    const long t = (long)blockIdx.x * 8 + (tid >> 5);
    const float* h2t = h2 + t * 256;
    float s = bg3[lane];
#pragma unroll 8
    for (int k = 0; k < 256; k += 4) {
        float4 h = *reinterpret_cast<const float4*>(h2t + k);
        s += h.x * Ws[(k + 0) * 32 + lane];
        s += h.y * Ws[(k + 1) * 32 + lane];
        s += h.z * Ws[(k + 2) * 32 + lane];
        s += h.w * Ws[(k + 3) * 32 + lane];
    }
    float bhalf = __shfl_down_sync(0xffffffffu, s, 16);
    float r = 0.f;
    if (lane < 16)
        r = s * (1.f / (1.f + expf(-bhalf))) + skipIn[t * 16 + lane];
    float sum = r;
    for (int m = 8; m; m >>= 1) sum += __shfl_xor_sync(0xffffffffu, sum, m, 16);
    float mean = sum * (1.f / 16.f);
    float d = r - mean;
    float vs = d * d;
    for (int m = 8; m; m >>= 1) vs += __shfl_xor_sync(0xffffffffu, vs, m, 16);
    float rstd = rsqrtf(vs * (1.f / 16.f) + 1e-6f);
    float ln = 0.f;
    if (lane < 16) ln = d * rstd * gg[lane] + bgn[lane];
    float mx = ln;
    for (int m = 8; m; m >>= 1) mx = fmaxf(mx, __shfl_xor_sync(0xffffffffu, mx, m, 16));
    float e = (lane < 16) ? expf(ln - mx) : 0.f;
    float se = e;
    for (int m = 8; m; m >>= 1) se += __shfl_xor_sync(0xffffffffu, se, m, 16);
    if (lane < 16) wout[t * 16 + lane] = e / se;
}

// ---------------------------------------------------------------------------
// out = sum_v LN(E[v] + x[v]) * weight[v]
// ---------------------------------------------------------------------------
__global__ __launch_bounds__(256)
void enc_combine_kernel(const __half* __restrict__ E, const __half* __restrict__ vh,
                        const float* __restrict__ wout, const float* __restrict__ gv,
                        const float* __restrict__ bvn, float* __restrict__ outp)
{
    const long t = blockIdx.x;
    const int tid = threadIdx.x;
    const int lane = tid & 31, wid = tid >> 5;
    __shared__ float sw[16];
    __shared__ float part[8][256];
    if (tid < 16) sw[tid] = wout[t * 16 + tid];
    __syncthreads();

    const int c0 = lane * 8;
    float acc[8];
#pragma unroll
    for (int i = 0; i < 8; i++) acc[i] = 0.f;

#pragma unroll
    for (int vi = 0; vi < 2; vi++) {
        const int v = wid * 2 + vi;
        uint4 rawE = *reinterpret_cast<const uint4*>(
            E + ((size_t)v * BT_TOK + t) * 256 + c0);
        uint4 rawX = *reinterpret_cast<const uint4*>(
            vh + (size_t)t * DIN + v * DDIM + c0);
        const __half2* he = reinterpret_cast<const __half2*>(&rawE);
        const __half2* hx = reinterpret_cast<const __half2*>(&rawX);
        float e[8];
#pragma unroll
        for (int i = 0; i < 4; i++) {
            float2 fe = __half22float2(he[i]);
            float2 fx = __half22float2(hx[i]);
            e[2 * i]     = fe.x + fx.x;
            e[2 * i + 1] = fe.y + fx.y;
        }
        float s1 = 0.f, s2 = 0.f;
#pragma unroll
        for (int i = 0; i < 8; i++) { s1 += e[i]; s2 += e[i] * e[i]; }
#pragma unroll
        for (int m = 16; m; m >>= 1) {
            s1 += __shfl_xor_sync(0xffffffffu, s1, m);
            s2 += __shfl_xor_sync(0xffffffffu, s2, m);
        }
        const float mean = s1 * (1.f / 256.f);
        const float var = s2 * (1.f / 256.f) - mean * mean;
        const float rstd = rsqrtf(var + 1e-6f);
        const float w = sw[v];
        const float4 g0 = *reinterpret_cast<const float4*>(gv + v * DDIM + c0);
        const float4 g1 = *reinterpret_cast<const float4*>(gv + v * DDIM + c0 + 4);
        const float4 b0 = *reinterpret_cast<const float4*>(bvn + v * DDIM + c0);
        const float4 b1 = *reinterpret_cast<const float4*>(bvn + v * DDIM + c0 + 4);
        const float gva[8] = {g0.x, g0.y, g0.z, g0.w, g1.x, g1.y, g1.z, g1.w};
        const float bva[8] = {b0.x, b0.y, b0.z, b0.w, b1.x, b1.y, b1.z, b1.w};
#pragma unroll
        for (int i = 0; i < 8; i++)
            acc[i] += ((e[i] - mean) * rstd * gva[i] + bva[i]) * w;
    }
#pragma unroll
    for (int i = 0; i < 8; i++) part[wid][c0 + i] = acc[i];
    __syncthreads();
    float s = 0.f;
#pragma unroll
    for (int wwi = 0; wwi < 8; wwi++) s += part[wwi][tid];
    outp[t * DDIM + tid] = s;
}

// ---------------------------------------------------------------------------
extern "C" void kernel_launch(void* const* d_in, const int* in_sizes, int n_in,
                              void* d_out, int out_size)
{
    const float* vars = (const float*)d_in[0];
    const float* Wg1  = (const float*)d_in[1];
    const float* bg1  = (const float*)d_in[2];
    const float* Wg2  = (const float*)d_in[3];
    const float* bg2  = (const float*)d_in[4];
    const float* Wg3  = (const float*)d_in[5];
    const float* bg3  = (const float*)d_in[6];
    const float* Wgs  = (const float*)d_in[7];
    const float* bgs  = (const float*)d_in[8];
    const float* gg   = (const float*)d_in[9];
    const float* bgn  = (const float*)d_in[10];
    const float* Wv1  = (const float*)d_in[11];
    const float* bv1  = (const float*)d_in[12];
    const float* Wv2  = (const float*)d_in[13];
    const float* bv2  = (const float*)d_in[14];
    const float* Wv3  = (const float*)d_in[15];
    const float* bv3  = (const float*)d_in[16];
    const float* gv   = (const float*)d_in[17];
    const float* bvn  = (const float*)d_in[18];

    float* out  = (float*)d_out;
    float* wout = out + BT_TOK * DDIM;

    unsigned char* gb = nullptr;
    cudaGetSymbolAddress((void**)&gb, g_buf);
    __half* VH  = (__half*)(gb + O_VH);
    __half* H1  = (__half*)(gb + O_H1);
    float*  H2F = (float*)(gb + O_H2F);
    __half* E   = (__half*)(gb + O_E);
    float*  SKP = (float*)(gb + O_SKIP);
    __half* G1T = (__half*)(gb + O_G1);
    __half* G2T = (__half*)(gb + O_G2);
    __half* W1T = (__half*)(gb + O_W1);
    __half* W2T = (__half*)(gb + O_W2);
    __half* W3T = (__half*)(gb + O_W3);

    cudaFuncSetAttribute(mma_gemm, cudaFuncAttributeMaxDynamicSharedMemorySize, SMEM_TOT);
    cudaFuncSetAttribute(fused_var, cudaFuncAttributeMaxDynamicSharedMemorySize, FSMEM);

    // conversions
    conv_split<<<65536, 256>>>(vars, VH);
    conv_wT<<<dim3(8, 128, 1), 256>>>(Wg1, G1T, 4096, 256);
    conv_wT<<<dim3(8, 8, 1),   256>>>(Wg2, G2T, 256, 256);
    conv_wT<<<dim3(8, 8, 16),  256>>>(Wv1, W1T, 256, 256);
    conv_wT<<<dim3(8, 8, 16),  256>>>(Wv2, W2T, 256, 256);
    conv_wT3<<<dim3(16, 8, 16), 256>>>(Wv3, W3T);

    // fused per-variable chain (independent of weight-GRN path)
    fused_var<<<dim3(128, 16), 256, FSMEM>>>(VH, W1T, W2T, W3T, bv1, bv2, bv3, E);

    // weight-GRN path
    skip_kernel<<<1024, 256>>>(VH, Wgs, bgs, SKP);
    mma_gemm<<<dim3(2, 128, 1), 256, SMEM_TOT>>>(
        VH, 0, DIN, G1T, 0, bg1, 0, nullptr, H1, 0, 256, 4096, 1);
    mma_gemm<<<dim3(2, 128, 1), 256, SMEM_TOT>>>(
        H1, 0, 256, G2T, 0, bg2, 0, H2F, nullptr, 0, 256, 256, 0);
    wlogits_kernel<<<2048, 256>>>(H2F, Wg3, bg3, gg, bgn, SKP, wout);

    // final combine
    enc_combine_kernel<<<16384, 256>>>(E, VH, wout, gv, bvn, out);
}

// round 9
// speedup vs baseline: 1.9947x; 1.1541x over previous
#include <cuda_runtime.h>
#include <cuda_fp16.h>
#include <cstdint>

// ---------------------------------------------------------------------------
// VSN on GB300 — Round 9: fused per-variable chain with M=64 tiles
// (110.6 KB smem -> 2 CTAs/SM for barrier/epilogue overlap).
// B=8,T=2048,NV=16,D=256 -> BT=16384, DIN=4096
// ---------------------------------------------------------------------------

#define BT_TOK 16384L
#define DDIM   256
#define DIN    4096

// ---------------- scratch (bytes) ----------------
#define O_VH    0ULL            // vars fp16 [16384,4096]          128MB
#define O_H1    134217728ULL    // h1 fp16 [16384,256]
#define O_H2F   142606336ULL    // h2 fp32 [16384,256]
#define O_E     159383552ULL    // E=glu fp16 16x[16384,256]       128MB
#define O_SKIP  293601280ULL    // skip fp32 [16384,16]
#define O_G1    294649856ULL    // Wg1^T fp16 [256,4096]
#define O_G2    296747008ULL    // Wg2^T fp16 [256,256]
#define O_W1    296878080ULL    // Wv1^T fp16 16x[256,256]
#define O_W2    298975232ULL
#define O_W3    301072384ULL    // Wv3^T perm fp16 16x[512,256]
#define G_TOTAL 305266688ULL

__device__ __align__(1024) unsigned char g_buf[G_TOTAL];

// ---------------- helpers ----------------
__device__ __forceinline__ uint32_t smem_u32(const void* p) {
    uint32_t a;
    asm("{ .reg .u64 t; cvta.to.shared.u64 t, %1; cvt.u32.u64 %0, t; }" : "=r"(a) : "l"(p));
    return a;
}
__device__ __forceinline__ void cpasync16(uint32_t dst, const void* src) {
    asm volatile("cp.async.cg.shared.global [%0], [%1], 16;" :: "r"(dst), "l"(src));
}
#define CP_COMMIT() asm volatile("cp.async.commit_group;" ::: "memory")
#define CP_WAIT(n)  asm volatile("cp.async.wait_group %0;" :: "n"(n) : "memory")

__device__ __forceinline__ void ldsm_x4(uint32_t (&r)[4], uint32_t addr) {
    asm volatile("ldmatrix.sync.aligned.m8n8.x4.shared.b16 {%0,%1,%2,%3}, [%4];"
        : "=r"(r[0]), "=r"(r[1]), "=r"(r[2]), "=r"(r[3]) : "r"(addr));
}
__device__ __forceinline__ void mma16816(float (&c)[4], const uint32_t (&a)[4],
                                         uint32_t b0, uint32_t b1) {
    asm volatile("mma.sync.aligned.m16n8k16.row.col.f32.f16.f16.f32 "
        "{%0,%1,%2,%3}, {%4,%5,%6,%7}, {%8,%9}, {%0,%1,%2,%3};"
        : "+f"(c[0]), "+f"(c[1]), "+f"(c[2]), "+f"(c[3])
        : "r"(a[0]), "r"(a[1]), "r"(a[2]), "r"(a[3]), "r"(b0), "r"(b1));
}

// ---------------------------------------------------------------------------
// conversions
// ---------------------------------------------------------------------------
__global__ __launch_bounds__(256)
void conv_split(const float* __restrict__ x, __half* __restrict__ h)
{
    size_t i = ((size_t)blockIdx.x * 256 + threadIdx.x) * 4;
    float4 v = *reinterpret_cast<const float4*>(x + i);
    *reinterpret_cast<__half2*>(h + i)     = __floats2half2_rn(v.x, v.y);
    *reinterpret_cast<__half2*>(h + i + 2) = __floats2half2_rn(v.z, v.w);
}

__global__ __launch_bounds__(256)
void conv_wT(const float* __restrict__ W, __half* __restrict__ TH, int K, int N)
{
    const size_t vb = (size_t)blockIdx.z * K * N;
    __shared__ float tile[32][33];
    const int k0 = blockIdx.y * 32, n0 = blockIdx.x * 32;
    const int tx = threadIdx.x & 31, ty = threadIdx.x >> 5;
#pragma unroll
    for (int i = 0; i < 4; i++)
        tile[ty + i * 8][tx] = W[vb + (size_t)(k0 + ty + i * 8) * N + n0 + tx];
    __syncthreads();
#pragma unroll
    for (int i = 0; i < 4; i++) {
        int n = ty + i * 8;
        TH[vb + (size_t)(n0 + n) * K + k0 + tx] = __float2half_rn(tile[tx][n]);
    }
}

// Wv3 transpose with GLU interleave
__global__ __launch_bounds__(256)
void conv_wT3(const float* __restrict__ W, __half* __restrict__ TH)
{
    const size_t vbs = (size_t)blockIdx.z * 256 * 512;
    const size_t vbd = (size_t)blockIdx.z * 512 * 256;
    __shared__ float tile[32][33];
    const int k0 = blockIdx.y * 32, c0 = blockIdx.x * 32;
    const int tx = threadIdx.x & 31, ty = threadIdx.x >> 5;
#pragma unroll
    for (int i = 0; i < 4; i++)
        tile[ty + i * 8][tx] = W[vbs + (size_t)(k0 + ty + i * 8) * 512 + c0 + tx];
    __syncthreads();
#pragma unroll
    for (int i = 0; i < 4; i++) {
        int c = c0 + ty + i * 8;
        int orow = (c < 256) ? (2 * c) : (2 * (c - 256) + 1);
        TH[vbd + (size_t)orow * 256 + k0 + tx] = __float2half_rn(tile[tx][ty + i * 8]);
    }
}

// ---------------------------------------------------------------------------
// mma_gemm (R7 core): G1 (mode1) and G2 (mode0).
// ---------------------------------------------------------------------------
#define RS 72
#define OFF_B  18432
#define ST_SIZE 36864
#define SMEM_TOT 147456

__global__ __launch_bounds__(256, 1)
void mma_gemm(const __half* __restrict__ A, long long aV, int lda,
              const __half* __restrict__ BH, long long bV,
              const float* __restrict__ bias, int biasV,
              float* __restrict__ CF, __half* __restrict__ CH,
              long long cV, int ldc, int K, int mode)
{
    extern __shared__ __align__(1024) unsigned char sm[];
    const uint32_t sb = smem_u32(sm);
    const int tid = threadIdx.x;
    const int lane = tid & 31, wid = tid >> 5;
    const int wm = wid & 1, wn = wid >> 1;
    const int v = blockIdx.z;
    const int m0 = blockIdx.y * 128;
    const int nb = blockIdx.x * 128;

    const __half* Ap  = A  + (size_t)v * aV + (size_t)m0 * lda;
    const __half* Bhp = BH + (size_t)v * bV + (size_t)nb * K;

    const int lr = tid >> 3;
    const int lc = (tid & 7) * 8;

    float acc[4][4][4];
#pragma unroll
    for (int i = 0; i < 4; i++)
#pragma unroll
        for (int j = 0; j < 4; j++)
#pragma unroll
            for (int k = 0; k < 4; k++) acc[i][j][k] = 0.f;

    const int nc = K >> 6;

    auto load_stage = [&](int s, int k0) {
        const uint32_t base = sb + s * ST_SIZE;
#pragma unroll
        for (int t = 0; t < 4; t++) {
            const int row = lr + t * 32;
            const uint32_t doff = (uint32_t)(row * RS + lc) * 2;
            cpasync16(base + doff,         Ap  + (size_t)row * lda + k0 + lc);
            cpasync16(base + OFF_B + doff, Bhp + (size_t)row * K   + k0 + lc);
        }
    };

    const uint32_t aoff = (uint32_t)(((wm * 64 + (lane & 15)) * RS + (lane >> 4) * 8) * 2);
    const uint32_t boff = (uint32_t)(((wn * 32 + (lane & 15)) * RS + (lane >> 4) * 8) * 2);

    load_stage(0, 0);          CP_COMMIT();
    if (nc > 1) load_stage(1, 64);  CP_COMMIT();
    if (nc > 2) load_stage(2, 128); CP_COMMIT();

    for (int c = 0; c < nc; c++) {
        CP_WAIT(2);
        __syncthreads();
        const uint32_t base = sb + (c & 3) * ST_SIZE;
#pragma unroll
        for (int kc = 0; kc < 64; kc += 16) {
            uint32_t a[4][4], bh[2][4];
#pragma unroll
            for (int mt = 0; mt < 4; mt++)
                ldsm_x4(a[mt], base + aoff + mt * (16 * RS * 2) + kc * 2);
#pragma unroll
            for (int p = 0; p < 2; p++)
                ldsm_x4(bh[p], base + OFF_B + boff + p * (16 * RS * 2) + kc * 2);
#pragma unroll
            for (int mt = 0; mt < 4; mt++)
#pragma unroll
                for (int q = 0; q < 4; q++)
                    mma16816(acc[mt][q], a[mt], bh[q >> 1][q & 1], bh[q >> 1][(q & 1) + 2]);
        }
        __syncthreads();
        if (c + 3 < nc) load_stage((c + 3) & 3, (c + 3) * 64);
        CP_COMMIT();
    }

    const int gid = lane >> 2, tig = lane & 3;
#pragma unroll
    for (int mt = 0; mt < 4; mt++) {
#pragma unroll
        for (int q = 0; q < 4; q++) {
            const int m = m0 + wm * 64 + mt * 16 + gid;
            const int n = nb + wn * 32 + q * 8 + tig * 2;
            const float* bp = bias + (size_t)v * biasV + n;
            const float b0 = bp[0], b1 = bp[1];
            float x0 = acc[mt][q][0] + b0, x1 = acc[mt][q][1] + b1;
            float y0 = acc[mt][q][2] + b0, y1 = acc[mt][q][3] + b1;
            if (mode == 1) {
                x0 = (x0 > 0.f) ? x0 : expm1f(x0);
                x1 = (x1 > 0.f) ? x1 : expm1f(x1);
                y0 = (y0 > 0.f) ? y0 : expm1f(y0);
                y1 = (y1 > 0.f) ? y1 : expm1f(y1);
            }
            if (mode == 0) {
                float* d0 = CF + (size_t)v * cV + (size_t)m * ldc + n;
                float2 o0; o0.x = x0; o0.y = x1;
                float2 o1; o1.x = y0; o1.y = y1;
                *reinterpret_cast<float2*>(d0) = o0;
                *reinterpret_cast<float2*>(d0 + 8 * ldc) = o1;
            } else {
                __half* d0 = CH + (size_t)v * cV + (size_t)m * ldc + n;
                *reinterpret_cast<__half2*>(d0) = __floats2half2_rn(x0, x1);
                *reinterpret_cast<__half2*>(d0 + 8 * ldc) = __floats2half2_rn(y0, y1);
            }
        }
    }
}

// ---------------------------------------------------------------------------
// fused per-variable chain, M=64 tiles (2 CTAs/SM):
//   E = glu(elu(x@W1+b1)@W2+b2 @ W3perm + b3)
// smem: A0 4x9216, A1 4x9216, WB 2x18432 = 110592 B.
// Warp tile 32x32: wm=wid&1 (2 M-groups of 32), wn=wid>>1 (4 N-groups of 32).
// ---------------------------------------------------------------------------
#define ACH 9216u                   // 64 * 72 * 2
#define FA0 0u
#define FA1 36864u
#define FWB 73728u
#define FSMEM 110592

__global__ __launch_bounds__(256, 2)
void fused_var(const __half* __restrict__ VH,
               const __half* __restrict__ W1T, const __half* __restrict__ W2T,
               const __half* __restrict__ W3T,
               const float* __restrict__ bv1, const float* __restrict__ bv2,
               const float* __restrict__ bv3,
               __half* __restrict__ E)
{
    extern __shared__ __align__(1024) unsigned char sm[];
    const uint32_t sb = smem_u32(sm);
    const int tid = threadIdx.x;
    const int lane = tid & 31, wid = tid >> 5;
    const int wm = wid & 1, wn = wid >> 1;
    const int gid = lane >> 2, tig = lane & 3;
    const int v = blockIdx.y;
    const int m0 = blockIdx.x * 64;

    // ---- load x_v tile [64,256] into A0 (4 chunks) ----
    {
        const __half* xp = VH + (size_t)m0 * DIN + v * 256;
#pragma unroll
        for (int t = 0; t < 8; t++) {
            const int id = tid + t * 256;
            const int ch = id >> 9;           // 512 sub-loads per chunk
            const int rem = id & 511;
            const int row = rem >> 3;
            const int lc8 = (rem & 7) * 8;
            cpasync16(sb + FA0 + ch * ACH + (uint32_t)(row * RS + lc8) * 2,
                      xp + (size_t)row * DIN + ch * 64 + lc8);
        }
        CP_COMMIT();
    }

    const uint32_t aoff = (uint32_t)(((wm * 32 + (lane & 15)) * RS + (lane >> 4) * 8) * 2);
    const uint32_t boff = (uint32_t)(((wn * 32 + (lane & 15)) * RS + (lane >> 4) * 8) * 2);
    const int lr = tid >> 3;
    const int lc = (tid & 7) * 8;

    for (int stage = 0; stage < 3; stage++) {
        const __half* W = (stage == 0) ? (W1T + (size_t)v * 65536)
                        : (stage == 1) ? (W2T + (size_t)v * 65536)
                                       : (W3T + (size_t)v * 131072);
        const int nPass = (stage == 2) ? 4 : 2;
        const uint32_t aBuf = (stage == 1) ? FA1 : FA0;
        const uint32_t oBuf = (stage == 0) ? FA1 : FA0;

        for (int np = 0; np < nPass; np++) {
            float acc[2][4][4];
#pragma unroll
            for (int i = 0; i < 2; i++)
#pragma unroll
                for (int j = 0; j < 4; j++)
#pragma unroll
                    for (int k = 0; k < 4; k++) acc[i][j][k] = 0.f;

            const __half* Wp = W + (size_t)(np * 128) * 256;
#pragma unroll
            for (int pc = 0; pc < 2; pc++) {
#pragma unroll
                for (int t = 0; t < 4; t++) {
                    const int row = lr + t * 32;
                    cpasync16(sb + FWB + pc * 18432 + (uint32_t)(row * RS + lc) * 2,
                              Wp + (size_t)row * 256 + pc * 64 + lc);
                }
                CP_COMMIT();
            }

            for (int c = 0; c < 4; c++) {
                if (c < 3) { CP_WAIT(1); } else { CP_WAIT(0); }
                __syncthreads();
                const uint32_t abase = sb + aBuf + c * ACH;
                const uint32_t bbase = sb + FWB + (c & 1) * 18432;
#pragma unroll
                for (int kc = 0; kc < 64; kc += 16) {
                    uint32_t a[2][4], bh[2][4];
#pragma unroll
                    for (int mt = 0; mt < 2; mt++)
                        ldsm_x4(a[mt], abase + aoff + mt * (16 * RS * 2) + kc * 2);
#pragma unroll
                    for (int p = 0; p < 2; p++)
                        ldsm_x4(bh[p], bbase + boff + p * (16 * RS * 2) + kc * 2);
#pragma unroll
                    for (int mt = 0; mt < 2; mt++)
#pragma unroll
                        for (int q = 0; q < 4; q++)
                            mma16816(acc[mt][q], a[mt], bh[q >> 1][q & 1], bh[q >> 1][(q & 1) + 2]);
                }
                __syncthreads();
                if (c + 2 < 4) {
#pragma unroll
                    for (int t = 0; t < 4; t++) {
                        const int row = lr + t * 32;
                        cpasync16(sb + FWB + (c & 1) * 18432 + (uint32_t)(row * RS + lc) * 2,
                                  Wp + (size_t)row * 256 + (c + 2) * 64 + lc);
                    }
                    CP_COMMIT();
                }
            }

            // ---- epilogue ----
            if (stage < 2) {
                const float* bp = ((stage == 0) ? bv1 : bv2) + (size_t)v * 256;
                __half* ob = reinterpret_cast<__half*>(sm) + (oBuf >> 1);
#pragma unroll
                for (int mt = 0; mt < 2; mt++) {
#pragma unroll
                    for (int q = 0; q < 4; q++) {
                        const int m = wm * 32 + mt * 16 + gid;
                        const int gn = np * 128 + wn * 32 + q * 8 + tig * 2;
                        const float b0 = bp[gn], b1 = bp[gn + 1];
                        float x0 = acc[mt][q][0] + b0, x1 = acc[mt][q][1] + b1;
                        float y0 = acc[mt][q][2] + b0, y1 = acc[mt][q][3] + b1;
                        if (stage == 0) {
                            x0 = (x0 > 0.f) ? x0 : expm1f(x0);
                            x1 = (x1 > 0.f) ? x1 : expm1f(x1);
                            y0 = (y0 > 0.f) ? y0 : expm1f(y0);
                            y1 = (y1 > 0.f) ? y1 : expm1f(y1);
                        }
                        const int ch = gn >> 6;
                        const int ko = gn & 63;
                        __half* d0 = ob + ch * (ACH / 2) + m * RS + ko;
                        *reinterpret_cast<__half2*>(d0) = __floats2half2_rn(x0, x1);
                        *reinterpret_cast<__half2*>(d0 + 8 * RS) = __floats2half2_rn(y0, y1);
                    }
                }
                __syncthreads();
            } else {
                // GLU -> stage in A1 [64][64] -> coalesced E store
                const float* bp = bv3 + (size_t)v * 512;
                const int jbase = np * 64;
                __half* Eg = reinterpret_cast<__half*>(sm) + (FA1 >> 1);
#pragma unroll
                for (int mt = 0; mt < 2; mt++) {
#pragma unroll
                    for (int q = 0; q < 4; q++) {
                        const int nl = wn * 32 + q * 8 + tig * 2;
                        const int jl = nl >> 1;
                        const int jg = jbase + jl;
                        const float ba = bp[jg], bb = bp[jg + 256];
                        const int r0 = wm * 32 + mt * 16 + gid;
                        float a0 = acc[mt][q][0] + ba, b0 = acc[mt][q][1] + bb;
                        float a1 = acc[mt][q][2] + ba, b1 = acc[mt][q][3] + bb;
                        Eg[r0 * 64 + jl]       = __float2half_rn(a0 * (1.f / (1.f + expf(-b0))));
                        Eg[(r0 + 8) * 64 + jl] = __float2half_rn(a1 * (1.f / (1.f + expf(-b1))));
                    }
                }
                __syncthreads();
                const int row = tid >> 2;          // 0..63
                const int chh = (tid & 3) * 16;    // 0,16,32,48
                const __half* src = Eg + row * 64 + chh;
                __half* dst = E + ((size_t)v * BT_TOK + m0 + row) * 256 + jbase + chh;
                *reinterpret_cast<uint4*>(dst)     = *reinterpret_cast<const uint4*>(src);
                *reinterpret_cast<uint4*>(dst + 8) = *reinterpret_cast<const uint4*>(src + 8);
                __syncthreads();
            }
        }
    }
}

// ---------------------------------------------------------------------------
// skip = flat @ Wgs + bgs (fp16 VH), K-chunk 256
// ---------------------------------------------------------------------------
__global__ __launch_bounds__(256)
void skip_kernel(const __half* __restrict__ vh, const float* __restrict__ Wgs,
                 const float* __restrict__ bgs, float* __restrict__ skipOut)
{
    __shared__ __half As[16][256];
    __shared__ float Ws[256][16];
    const int tid = threadIdx.x;
    const long t0 = (long)blockIdx.x * 16;
    const int o = tid & 15;
    const int tr = tid >> 4;
    float s = 0.f;
    for (int k0 = 0; k0 < DIN; k0 += 256) {
        {
            const int r = tid >> 4;
            const int cc = (tid & 15) * 16;
            *reinterpret_cast<uint4*>(&As[r][cc]) =
                *reinterpret_cast<const uint4*>(vh + (t0 + r) * DIN + k0 + cc);
            *reinterpret_cast<uint4*>(&As[r][cc + 8]) =
                *reinterpret_cast<const uint4*>(vh + (t0 + r) * DIN + k0 + cc + 8);
        }
        {
            const int r = tid;
            *reinterpret_cast<float4*>(&Ws[r][0])  = *reinterpret_cast<const float4*>(Wgs + (long)(k0 + r) * 16 + 0);
            *reinterpret_cast<float4*>(&Ws[r][4])  = *reinterpret_cast<const float4*>(Wgs + (long)(k0 + r) * 16 + 4);
            *reinterpret_cast<float4*>(&Ws[r][8])  = *reinterpret_cast<const float4*>(Wgs + (long)(k0 + r) * 16 + 8);
            *reinterpret_cast<float4*>(&Ws[r][12]) = *reinterpret_cast<const float4*>(Wgs + (long)(k0 + r) * 16 + 12);
        }
        __syncthreads();
#pragma unroll 16
        for (int kk = 0; kk < 256; kk++) s += __half2float(As[tr][kk]) * Ws[kk][o];
        __syncthreads();
    }
    skipOut[(t0 + tr) * 16 + o] = s + bgs[o];
}

// ---------------------------------------------------------------------------
// weight logits -> softmax weights
// ---------------------------------------------------------------------------
__global__ __launch_bounds__(256)
void wlogits_kernel(const float* __restrict__ h2, const float* __restrict__ Wg3,
                    const float* __restrict__ bg3, const float* __restrict__ gg,
                    const float* __restrict__ bgn, const float* __restrict__ skipIn,
                    float* __restrict__ wout)
{
    __shared__ float Ws[256 * 32];
    const int tid = threadIdx.x;
    const int lane = tid & 31;
#pragma unroll
    for (int i = 0; i < 32; i++) Ws[tid + i * 256] = Wg3[tid + i * 256];
    __syncthreads();

    const long t = (long)blockIdx.x * 8 + (tid >> 5);
    const float* h2t = h2 + t * 256;
    float s = bg3[lane];
#pragma unroll 8
    for (int k = 0; k < 256; k += 4) {
        float4 h = *reinterpret_cast<const float4*>(h2t + k);
        s += h.x * Ws[(k + 0) * 32 + lane];
        s += h.y * Ws[(k + 1) * 32 + lane];
        s += h.z * Ws[(k + 2) * 32 + lane];
        s += h.w * Ws[(k + 3) * 32 + lane];
    }
    float bhalf = __shfl_down_sync(0xffffffffu, s, 16);
    float r = 0.f;
    if (lane < 16)
        r = s * (1.f / (1.f + expf(-bhalf))) + skipIn[t * 16 + lane];
    float sum = r;
    for (int m = 8; m; m >>= 1) sum += __shfl_xor_sync(0xffffffffu, sum, m, 16);
    float mean = sum * (1.f / 16.f);
    float d = r - mean;
    float vs = d * d;
    for (int m = 8; m; m >>= 1) vs += __shfl_xor_sync(0xffffffffu, vs, m, 16);
    float rstd = rsqrtf(vs * (1.f / 16.f) + 1e-6f);
    float ln = 0.f;
    if (lane < 16) ln = d * rstd * gg[lane] + bgn[lane];
    float mx = ln;
    for (int m = 8; m; m >>= 1) mx = fmaxf(mx, __shfl_xor_sync(0xffffffffu, mx, m, 16));
    float e = (lane < 16) ? expf(ln - mx) : 0.f;
    float se = e;
    for (int m = 8; m; m >>= 1) se += __shfl_xor_sync(0xffffffffu, se, m, 16);
    if (lane < 16) wout[t * 16 + lane] = e / se;
}

// ---------------------------------------------------------------------------
// out = sum_v LN(E[v] + x[v]) * weight[v]
// ---------------------------------------------------------------------------
__global__ __launch_bounds__(256)
void enc_combine_kernel(const __half* __restrict__ E, const __half* __restrict__ vh,
                        const float* __restrict__ wout, const float* __restrict__ gv,
                        const float* __restrict__ bvn, float* __restrict__ outp)
{
    const long t = blockIdx.x;
    const int tid = threadIdx.x;
    const int lane = tid & 31, wid = tid >> 5;
    __shared__ float sw[16];
    __shared__ float part[8][256];
    if (tid < 16) sw[tid] = wout[t * 16 + tid];
    __syncthreads();

    const int c0 = lane * 8;
    float acc[8];
#pragma unroll
    for (int i = 0; i < 8; i++) acc[i] = 0.f;

#pragma unroll
    for (int vi = 0; vi < 2; vi++) {
        const int v = wid * 2 + vi;
        uint4 rawE = *reinterpret_cast<const uint4*>(
            E + ((size_t)v * BT_TOK + t) * 256 + c0);
        uint4 rawX = *reinterpret_cast<const uint4*>(
            vh + (size_t)t * DIN + v * DDIM + c0);
        const __half2* he = reinterpret_cast<const __half2*>(&rawE);
        const __half2* hx = reinterpret_cast<const __half2*>(&rawX);
        float e[8];
#pragma unroll
        for (int i = 0; i < 4; i++) {
            float2 fe = __half22float2(he[i]);
            float2 fx = __half22float2(hx[i]);
            e[2 * i]     = fe.x + fx.x;
            e[2 * i + 1] = fe.y + fx.y;
        }
        float s1 = 0.f, s2 = 0.f;
#pragma unroll
        for (int i = 0; i < 8; i++) { s1 += e[i]; s2 += e[i] * e[i]; }
#pragma unroll
        for (int m = 16; m; m >>= 1) {
            s1 += __shfl_xor_sync(0xffffffffu, s1, m);
            s2 += __shfl_xor_sync(0xffffffffu, s2, m);
        }
        const float mean = s1 * (1.f / 256.f);
        const float var = s2 * (1.f / 256.f) - mean * mean;
        const float rstd = rsqrtf(var + 1e-6f);
        const float w = sw[v];
        const float4 g0 = *reinterpret_cast<const float4*>(gv + v * DDIM + c0);
        const float4 g1 = *reinterpret_cast<const float4*>(gv + v * DDIM + c0 + 4);
        const float4 b0 = *reinterpret_cast<const float4*>(bvn + v * DDIM + c0);
        const float4 b1 = *reinterpret_cast<const float4*>(bvn + v * DDIM + c0 + 4);
        const float gva[8] = {g0.x, g0.y, g0.z, g0.w, g1.x, g1.y, g1.z, g1.w};
        const float bva[8] = {b0.x, b0.y, b0.z, b0.w, b1.x, b1.y, b1.z, b1.w};
#pragma unroll
        for (int i = 0; i < 8; i++)
            acc[i] += ((e[i] - mean) * rstd * gva[i] + bva[i]) * w;
    }
#pragma unroll
    for (int i = 0; i < 8; i++) part[wid][c0 + i] = acc[i];
    __syncthreads();
    float s = 0.f;
#pragma unroll
    for (int wwi = 0; wwi < 8; wwi++) s += part[wwi][tid];
    outp[t * DDIM + tid] = s;
}

// ---------------------------------------------------------------------------
extern "C" void kernel_launch(void* const* d_in, const int* in_sizes, int n_in,
                              void* d_out, int out_size)
{
    const float* vars = (const float*)d_in[0];
    const float* Wg1  = (const float*)d_in[1];
    const float* bg1  = (const float*)d_in[2];
    const float* Wg2  = (const float*)d_in[3];
    const float* bg2  = (const float*)d_in[4];
    const float* Wg3  = (const float*)d_in[5];
    const float* bg3  = (const float*)d_in[6];
    const float* Wgs  = (const float*)d_in[7];
    const float* bgs  = (const float*)d_in[8];
    const float* gg   = (const float*)d_in[9];
    const float* bgn  = (const float*)d_in[10];
    const float* Wv1  = (const float*)d_in[11];
    const float* bv1  = (const float*)d_in[12];
    const float* Wv2  = (const float*)d_in[13];
    const float* bv2  = (const float*)d_in[14];
    const float* Wv3  = (const float*)d_in[15];
    const float* bv3  = (const float*)d_in[16];
    const float* gv   = (const float*)d_in[17];
    const float* bvn  = (const float*)d_in[18];

    float* out  = (float*)d_out;
    float* wout = out + BT_TOK * DDIM;

    unsigned char* gb = nullptr;
    cudaGetSymbolAddress((void**)&gb, g_buf);
    __half* VH  = (__half*)(gb + O_VH);
    __half* H1  = (__half*)(gb + O_H1);
    float*  H2F = (float*)(gb + O_H2F);
    __half* E   = (__half*)(gb + O_E);
    float*  SKP = (float*)(gb + O_SKIP);
    __half* G1T = (__half*)(gb + O_G1);
    __half* G2T = (__half*)(gb + O_G2);
    __half* W1T = (__half*)(gb + O_W1);
    __half* W2T = (__half*)(gb + O_W2);
    __half* W3T = (__half*)(gb + O_W3);

    cudaFuncSetAttribute(mma_gemm, cudaFuncAttributeMaxDynamicSharedMemorySize, SMEM_TOT);
    cudaFuncSetAttribute(fused_var, cudaFuncAttributeMaxDynamicSharedMemorySize, FSMEM);

    // conversions
    conv_split<<<65536, 256>>>(vars, VH);
    conv_wT<<<dim3(8, 128, 1), 256>>>(Wg1, G1T, 4096, 256);
    conv_wT<<<dim3(8, 8, 1),   256>>>(Wg2, G2T, 256, 256);
    conv_wT<<<dim3(8, 8, 16),  256>>>(Wv1, W1T, 256, 256);
    conv_wT<<<dim3(8, 8, 16),  256>>>(Wv2, W2T, 256, 256);
    conv_wT3<<<dim3(16, 8, 16), 256>>>(Wv3, W3T);

    // fused per-variable chain (M=64 tiles, 2 CTAs/SM)
    fused_var<<<dim3(256, 16), 256, FSMEM>>>(VH, W1T, W2T, W3T, bv1, bv2, bv3, E);

    // weight-GRN path
    skip_kernel<<<1024, 256>>>(VH, Wgs, bgs, SKP);
    mma_gemm<<<dim3(2, 128, 1), 256, SMEM_TOT>>>(
        VH, 0, DIN, G1T, 0, bg1, 0, nullptr, H1, 0, 256, 4096, 1);
    mma_gemm<<<dim3(2, 128, 1), 256, SMEM_TOT>>>(
        H1, 0, 256, G2T, 0, bg2, 0, H2F, nullptr, 0, 256, 256, 0);
    wlogits_kernel<<<2048, 256>>>(H2F, Wg3, bg3, gg, bgn, SKP, wout);

    // final combine
    enc_combine_kernel<<<16384, 256>>>(E, VH, wout, gv, bvn, out);
}

// round 10
// speedup vs baseline: 2.0325x; 1.0190x over previous
#include <cuda_runtime.h>
#include <cuda_fp16.h>
#include <cstdint>

// ---------------------------------------------------------------------------
// VSN on GB300 — Round 10: mma_gemm -> 3-stage ring + 2 CTAs/SM (G1 wave fix);
// fused per-variable chain (M=64, 2 CTAs/SM) as in R9.
// B=8,T=2048,NV=16,D=256 -> BT=16384, DIN=4096
// ---------------------------------------------------------------------------

#define BT_TOK 16384L
#define DDIM   256
#define DIN    4096

// ---------------- scratch (bytes) ----------------
#define O_VH    0ULL            // vars fp16 [16384,4096]          128MB
#define O_H1    134217728ULL    // h1 fp16 [16384,256]
#define O_H2F   142606336ULL    // h2 fp32 [16384,256]
#define O_E     159383552ULL    // E=glu fp16 16x[16384,256]       128MB
#define O_SKIP  293601280ULL    // skip fp32 [16384,16]
#define O_G1    294649856ULL    // Wg1^T fp16 [256,4096]
#define O_G2    296747008ULL    // Wg2^T fp16 [256,256]
#define O_W1    296878080ULL    // Wv1^T fp16 16x[256,256]
#define O_W2    298975232ULL
#define O_W3    301072384ULL    // Wv3^T perm fp16 16x[512,256]
#define G_TOTAL 305266688ULL

__device__ __align__(1024) unsigned char g_buf[G_TOTAL];

// ---------------- helpers ----------------
__device__ __forceinline__ uint32_t smem_u32(const void* p) {
    uint32_t a;
    asm("{ .reg .u64 t; cvta.to.shared.u64 t, %1; cvt.u32.u64 %0, t; }" : "=r"(a) : "l"(p));
    return a;
}
__device__ __forceinline__ void cpasync16(uint32_t dst, const void* src) {
    asm volatile("cp.async.cg.shared.global [%0], [%1], 16;" :: "r"(dst), "l"(src));
}
#define CP_COMMIT() asm volatile("cp.async.commit_group;" ::: "memory")
#define CP_WAIT(n)  asm volatile("cp.async.wait_group %0;" :: "n"(n) : "memory")

__device__ __forceinline__ void ldsm_x4(uint32_t (&r)[4], uint32_t addr) {
    asm volatile("ldmatrix.sync.aligned.m8n8.x4.shared.b16 {%0,%1,%2,%3}, [%4];"
        : "=r"(r[0]), "=r"(r[1]), "=r"(r[2]), "=r"(r[3]) : "r"(addr));
}
__device__ __forceinline__ void mma16816(float (&c)[4], const uint32_t (&a)[4],
                                         uint32_t b0, uint32_t b1) {
    asm volatile("mma.sync.aligned.m16n8k16.row.col.f32.f16.f16.f32 "
        "{%0,%1,%2,%3}, {%4,%5,%6,%7}, {%8,%9}, {%0,%1,%2,%3};"
        : "+f"(c[0]), "+f"(c[1]), "+f"(c[2]), "+f"(c[3])
        : "r"(a[0]), "r"(a[1]), "r"(a[2]), "r"(a[3]), "r"(b0), "r"(b1));
}

// ---------------------------------------------------------------------------
// conversions
// ---------------------------------------------------------------------------
__global__ __launch_bounds__(256)
void conv_split(const float* __restrict__ x, __half* __restrict__ h)
{
    size_t i = ((size_t)blockIdx.x * 512 + threadIdx.x * 2) * 4;
#pragma unroll
    for (int u = 0; u < 2; u++) {
        float4 v = *reinterpret_cast<const float4*>(x + i + u * 4);
        *reinterpret_cast<__half2*>(h + i + u * 4)     = __floats2half2_rn(v.x, v.y);
        *reinterpret_cast<__half2*>(h + i + u * 4 + 2) = __floats2half2_rn(v.z, v.w);
    }
}

__global__ __launch_bounds__(256)
void conv_wT(const float* __restrict__ W, __half* __restrict__ TH, int K, int N)
{
    const size_t vb = (size_t)blockIdx.z * K * N;
    __shared__ float tile[32][33];
    const int k0 = blockIdx.y * 32, n0 = blockIdx.x * 32;
    const int tx = threadIdx.x & 31, ty = threadIdx.x >> 5;
#pragma unroll
    for (int i = 0; i < 4; i++)
        tile[ty + i * 8][tx] = W[vb + (size_t)(k0 + ty + i * 8) * N + n0 + tx];
    __syncthreads();
#pragma unroll
    for (int i = 0; i < 4; i++) {
        int n = ty + i * 8;
        TH[vb + (size_t)(n0 + n) * K + k0 + tx] = __float2half_rn(tile[tx][n]);
    }
}

// Wv3 transpose with GLU interleave
__global__ __launch_bounds__(256)
void conv_wT3(const float* __restrict__ W, __half* __restrict__ TH)
{
    const size_t vbs = (size_t)blockIdx.z * 256 * 512;
    const size_t vbd = (size_t)blockIdx.z * 512 * 256;
    __shared__ float tile[32][33];
    const int k0 = blockIdx.y * 32, c0 = blockIdx.x * 32;
    const int tx = threadIdx.x & 31, ty = threadIdx.x >> 5;
#pragma unroll
    for (int i = 0; i < 4; i++)
        tile[ty + i * 8][tx] = W[vbs + (size_t)(k0 + ty + i * 8) * 512 + c0 + tx];
    __syncthreads();
#pragma unroll
    for (int i = 0; i < 4; i++) {
        int c = c0 + ty + i * 8;
        int orow = (c < 256) ? (2 * c) : (2 * (c - 256) + 1);
        TH[vbd + (size_t)orow * 256 + k0 + tx] = __float2half_rn(tile[tx][ty + i * 8]);
    }
}

// ---------------------------------------------------------------------------
// mma_gemm: 3-stage cp.async ring, 2 CTAs/SM. G1 (mode1), G2 (mode0).
// ---------------------------------------------------------------------------
#define RS 72
#define OFF_B  18432
#define ST_SIZE 36864
#define SMEM_TOT 110592             // 3 stages

__global__ __launch_bounds__(256, 2)
void mma_gemm(const __half* __restrict__ A, long long aV, int lda,
              const __half* __restrict__ BH, long long bV,
              const float* __restrict__ bias, int biasV,
              float* __restrict__ CF, __half* __restrict__ CH,
              long long cV, int ldc, int K, int mode)
{
    extern __shared__ __align__(1024) unsigned char sm[];
    const uint32_t sb = smem_u32(sm);
    const int tid = threadIdx.x;
    const int lane = tid & 31, wid = tid >> 5;
    const int wm = wid & 1, wn = wid >> 1;
    const int v = blockIdx.z;
    const int m0 = blockIdx.y * 128;
    const int nb = blockIdx.x * 128;

    const __half* Ap  = A  + (size_t)v * aV + (size_t)m0 * lda;
    const __half* Bhp = BH + (size_t)v * bV + (size_t)nb * K;

    const int lr = tid >> 3;
    const int lc = (tid & 7) * 8;

    float acc[4][4][4];
#pragma unroll
    for (int i = 0; i < 4; i++)
#pragma unroll
        for (int j = 0; j < 4; j++)
#pragma unroll
            for (int k = 0; k < 4; k++) acc[i][j][k] = 0.f;

    const int nc = K >> 6;

    auto load_stage = [&](int s, int k0) {
        const uint32_t base = sb + s * ST_SIZE;
#pragma unroll
        for (int t = 0; t < 4; t++) {
            const int row = lr + t * 32;
            const uint32_t doff = (uint32_t)(row * RS + lc) * 2;
            cpasync16(base + doff,         Ap  + (size_t)row * lda + k0 + lc);
            cpasync16(base + OFF_B + doff, Bhp + (size_t)row * K   + k0 + lc);
        }
    };

    const uint32_t aoff = (uint32_t)(((wm * 64 + (lane & 15)) * RS + (lane >> 4) * 8) * 2);
    const uint32_t boff = (uint32_t)(((wn * 32 + (lane & 15)) * RS + (lane >> 4) * 8) * 2);

    load_stage(0, 0);              CP_COMMIT();
    if (nc > 1) { load_stage(1, 64); } CP_COMMIT();

    int sidx = 0;          // stage of chunk c
    for (int c = 0; c < nc; c++) {
        CP_WAIT(1);
        __syncthreads();
        const uint32_t base = sb + sidx * ST_SIZE;
#pragma unroll
        for (int kc = 0; kc < 64; kc += 16) {
            uint32_t a[4][4], bh[2][4];
#pragma unroll
            for (int mt = 0; mt < 4; mt++)
                ldsm_x4(a[mt], base + aoff + mt * (16 * RS * 2) + kc * 2);
#pragma unroll
            for (int p = 0; p < 2; p++)
                ldsm_x4(bh[p], base + OFF_B + boff + p * (16 * RS * 2) + kc * 2);
#pragma unroll
            for (int mt = 0; mt < 4; mt++)
#pragma unroll
                for (int q = 0; q < 4; q++)
                    mma16816(acc[mt][q], a[mt], bh[q >> 1][q & 1], bh[q >> 1][(q & 1) + 2]);
        }
        __syncthreads();
        if (c + 2 < nc) {
            int ns = sidx + 2; if (ns >= 3) ns -= 3;
            load_stage(ns, (c + 2) * 64);
        }
        CP_COMMIT();
        if (++sidx == 3) sidx = 0;
    }

    const int gid = lane >> 2, tig = lane & 3;
#pragma unroll
    for (int mt = 0; mt < 4; mt++) {
#pragma unroll
        for (int q = 0; q < 4; q++) {
            const int m = m0 + wm * 64 + mt * 16 + gid;
            const int n = nb + wn * 32 + q * 8 + tig * 2;
            const float* bp = bias + (size_t)v * biasV + n;
            const float b0 = bp[0], b1 = bp[1];
            float x0 = acc[mt][q][0] + b0, x1 = acc[mt][q][1] + b1;
            float y0 = acc[mt][q][2] + b0, y1 = acc[mt][q][3] + b1;
            if (mode == 1) {
                x0 = (x0 > 0.f) ? x0 : expm1f(x0);
                x1 = (x1 > 0.f) ? x1 : expm1f(x1);
                y0 = (y0 > 0.f) ? y0 : expm1f(y0);
                y1 = (y1 > 0.f) ? y1 : expm1f(y1);
            }
            if (mode == 0) {
                float* d0 = CF + (size_t)v * cV + (size_t)m * ldc + n;
                float2 o0; o0.x = x0; o0.y = x1;
                float2 o1; o1.x = y0; o1.y = y1;
                *reinterpret_cast<float2*>(d0) = o0;
                *reinterpret_cast<float2*>(d0 + 8 * ldc) = o1;
            } else {
                __half* d0 = CH + (size_t)v * cV + (size_t)m * ldc + n;
                *reinterpret_cast<__half2*>(d0) = __floats2half2_rn(x0, x1);
                *reinterpret_cast<__half2*>(d0 + 8 * ldc) = __floats2half2_rn(y0, y1);
            }
        }
    }
}

// ---------------------------------------------------------------------------
// fused per-variable chain, M=64 tiles (2 CTAs/SM):
//   E = glu(elu(x@W1+b1)@W2+b2 @ W3perm + b3)
// ---------------------------------------------------------------------------
#define ACH 9216u                   // 64 * 72 * 2
#define FA0 0u
#define FA1 36864u
#define FWB 73728u
#define FSMEM 110592

__global__ __launch_bounds__(256, 2)
void fused_var(const __half* __restrict__ VH,
               const __half* __restrict__ W1T, const __half* __restrict__ W2T,
               const __half* __restrict__ W3T,
               const float* __restrict__ bv1, const float* __restrict__ bv2,
               const float* __restrict__ bv3,
               __half* __restrict__ E)
{
    extern __shared__ __align__(1024) unsigned char sm[];
    const uint32_t sb = smem_u32(sm);
    const int tid = threadIdx.x;
    const int lane = tid & 31, wid = tid >> 5;
    const int wm = wid & 1, wn = wid >> 1;
    const int gid = lane >> 2, tig = lane & 3;
    const int v = blockIdx.y;
    const int m0 = blockIdx.x * 64;

    // ---- load x_v tile [64,256] into A0 (4 chunks) ----
    {
        const __half* xp = VH + (size_t)m0 * DIN + v * 256;
#pragma unroll
        for (int t = 0; t < 8; t++) {
            const int id = tid + t * 256;
            const int ch = id >> 9;
            const int rem = id & 511;
            const int row = rem >> 3;
            const int lc8 = (rem & 7) * 8;
            cpasync16(sb + FA0 + ch * ACH + (uint32_t)(row * RS + lc8) * 2,
                      xp + (size_t)row * DIN + ch * 64 + lc8);
        }
        CP_COMMIT();
    }

    const uint32_t aoff = (uint32_t)(((wm * 32 + (lane & 15)) * RS + (lane >> 4) * 8) * 2);
    const uint32_t boff = (uint32_t)(((wn * 32 + (lane & 15)) * RS + (lane >> 4) * 8) * 2);
    const int lr = tid >> 3;
    const int lc = (tid & 7) * 8;

    for (int stage = 0; stage < 3; stage++) {
        const __half* W = (stage == 0) ? (W1T + (size_t)v * 65536)
                        : (stage == 1) ? (W2T + (size_t)v * 65536)
                                       : (W3T + (size_t)v * 131072);
        const int nPass = (stage == 2) ? 4 : 2;
        const uint32_t aBuf = (stage == 1) ? FA1 : FA0;
        const uint32_t oBuf = (stage == 0) ? FA1 : FA0;

        for (int np = 0; np < nPass; np++) {
            float acc[2][4][4];
#pragma unroll
            for (int i = 0; i < 2; i++)
#pragma unroll
                for (int j = 0; j < 4; j++)
#pragma unroll
                    for (int k = 0; k < 4; k++) acc[i][j][k] = 0.f;

            const __half* Wp = W + (size_t)(np * 128) * 256;
#pragma unroll
            for (int pc = 0; pc < 2; pc++) {
#pragma unroll
                for (int t = 0; t < 4; t++) {
                    const int row = lr + t * 32;
                    cpasync16(sb + FWB + pc * 18432 + (uint32_t)(row * RS + lc) * 2,
                              Wp + (size_t)row * 256 + pc * 64 + lc);
                }
                CP_COMMIT();
            }

            for (int c = 0; c < 4; c++) {
                if (c < 3) { CP_WAIT(1); } else { CP_WAIT(0); }
                __syncthreads();
                const uint32_t abase = sb + aBuf + c * ACH;
                const uint32_t bbase = sb + FWB + (c & 1) * 18432;
#pragma unroll
                for (int kc = 0; kc < 64; kc += 16) {
                    uint32_t a[2][4], bh[2][4];
#pragma unroll
                    for (int mt = 0; mt < 2; mt++)
                        ldsm_x4(a[mt], abase + aoff + mt * (16 * RS * 2) + kc * 2);
#pragma unroll
                    for (int p = 0; p < 2; p++)
                        ldsm_x4(bh[p], bbase + boff + p * (16 * RS * 2) + kc * 2);
#pragma unroll
                    for (int mt = 0; mt < 2; mt++)
#pragma unroll
                        for (int q = 0; q < 4; q++)
                            mma16816(acc[mt][q], a[mt], bh[q >> 1][q & 1], bh[q >> 1][(q & 1) + 2]);
                }
                __syncthreads();
                if (c + 2 < 4) {
#pragma unroll
                    for (int t = 0; t < 4; t++) {
                        const int row = lr + t * 32;
                        cpasync16(sb + FWB + (c & 1) * 18432 + (uint32_t)(row * RS + lc) * 2,
                                  Wp + (size_t)row * 256 + (c + 2) * 64 + lc);
                    }
                    CP_COMMIT();
                }
            }

            // ---- epilogue ----
            if (stage < 2) {
                const float* bp = ((stage == 0) ? bv1 : bv2) + (size_t)v * 256;
                __half* ob = reinterpret_cast<__half*>(sm) + (oBuf >> 1);
#pragma unroll
                for (int mt = 0; mt < 2; mt++) {
#pragma unroll
                    for (int q = 0; q < 4; q++) {
                        const int m = wm * 32 + mt * 16 + gid;
                        const int gn = np * 128 + wn * 32 + q * 8 + tig * 2;
                        const float b0 = bp[gn], b1 = bp[gn + 1];
                        float x0 = acc[mt][q][0] + b0, x1 = acc[mt][q][1] + b1;
                        float y0 = acc[mt][q][2] + b0, y1 = acc[mt][q][3] + b1;
                        if (stage == 0) {
                            x0 = (x0 > 0.f) ? x0 : expm1f(x0);
                            x1 = (x1 > 0.f) ? x1 : expm1f(x1);
                            y0 = (y0 > 0.f) ? y0 : expm1f(y0);
                            y1 = (y1 > 0.f) ? y1 : expm1f(y1);
                        }
                        const int ch = gn >> 6;
                        const int ko = gn & 63;
                        __half* d0 = ob + ch * (ACH / 2) + m * RS + ko;
                        *reinterpret_cast<__half2*>(d0) = __floats2half2_rn(x0, x1);
                        *reinterpret_cast<__half2*>(d0 + 8 * RS) = __floats2half2_rn(y0, y1);
                    }
                }
                __syncthreads();
            } else {
                // GLU -> stage in A1 [64][64] -> coalesced E store
                const float* bp = bv3 + (size_t)v * 512;
                const int jbase = np * 64;
                __half* Eg = reinterpret_cast<__half*>(sm) + (FA1 >> 1);
#pragma unroll
                for (int mt = 0; mt < 2; mt++) {
#pragma unroll
                    for (int q = 0; q < 4; q++) {
                        const int nl = wn * 32 + q * 8 + tig * 2;
                        const int jl = nl >> 1;
                        const int jg = jbase + jl;
                        const float ba = bp[jg], bb = bp[jg + 256];
                        const int r0 = wm * 32 + mt * 16 + gid;
                        float a0 = acc[mt][q][0] + ba, b0 = acc[mt][q][1] + bb;
                        float a1 = acc[mt][q][2] + ba, b1 = acc[mt][q][3] + bb;
                        Eg[r0 * 64 + jl]       = __float2half_rn(a0 * (1.f / (1.f + expf(-b0))));
                        Eg[(r0 + 8) * 64 + jl] = __float2half_rn(a1 * (1.f / (1.f + expf(-b1))));
                    }
                }
                __syncthreads();
                const int row = tid >> 2;
                const int chh = (tid & 3) * 16;
                const __half* src = Eg + row * 64 + chh;
                __half* dst = E + ((size_t)v * BT_TOK + m0 + row) * 256 + jbase + chh;
                *reinterpret_cast<uint4*>(dst)     = *reinterpret_cast<const uint4*>(src);
                *reinterpret_cast<uint4*>(dst + 8) = *reinterpret_cast<const uint4*>(src + 8);
                __syncthreads();
            }
        }
    }
}

// ---------------------------------------------------------------------------
// skip = flat @ Wgs + bgs (fp16 VH), K-chunk 256
// ---------------------------------------------------------------------------
__global__ __launch_bounds__(256)
void skip_kernel(const __half* __restrict__ vh, const float* __restrict__ Wgs,
                 const float* __restrict__ bgs, float* __restrict__ skipOut)
{
    __shared__ __half As[16][256];
    __shared__ float Ws[256][16];
    const int tid = threadIdx.x;
    const long t0 = (long)blockIdx.x * 16;
    const int o = tid & 15;
    const int tr = tid >> 4;
    float s = 0.f;
    for (int k0 = 0; k0 < DIN; k0 += 256) {
        {
            const int r = tid >> 4;
            const int cc = (tid & 15) * 16;
            *reinterpret_cast<uint4*>(&As[r][cc]) =
                *reinterpret_cast<const uint4*>(vh + (t0 + r) * DIN + k0 + cc);
            *reinterpret_cast<uint4*>(&As[r][cc + 8]) =
                *reinterpret_cast<const uint4*>(vh + (t0 + r) * DIN + k0 + cc + 8);
        }
        {
            const int r = tid;
            *reinterpret_cast<float4*>(&Ws[r][0])  = *reinterpret_cast<const float4*>(Wgs + (long)(k0 + r) * 16 + 0);
            *reinterpret_cast<float4*>(&Ws[r][4])  = *reinterpret_cast<const float4*>(Wgs + (long)(k0 + r) * 16 + 4);
            *reinterpret_cast<float4*>(&Ws[r][8])  = *reinterpret_cast<const float4*>(Wgs + (long)(k0 + r) * 16 + 8);
            *reinterpret_cast<float4*>(&Ws[r][12]) = *reinterpret_cast<const float4*>(Wgs + (long)(k0 + r) * 16 + 12);
        }
        __syncthreads();
#pragma unroll 16
        for (int kk = 0; kk < 256; kk++) s += __half2float(As[tr][kk]) * Ws[kk][o];
        __syncthreads();
    }
    skipOut[(t0 + tr) * 16 + o] = s + bgs[o];
}

// ---------------------------------------------------------------------------
// weight logits -> softmax weights
// ---------------------------------------------------------------------------
__global__ __launch_bounds__(256)
void wlogits_kernel(const float* __restrict__ h2, const float* __restrict__ Wg3,
                    const float* __restrict__ bg3, const float* __restrict__ gg,
                    const float* __restrict__ bgn, const float* __restrict__ skipIn,
                    float* __restrict__ wout)
{
    __shared__ float Ws[256 * 32];
    const int tid = threadIdx.x;
    const int lane = tid & 31;
#pragma unroll
    for (int i = 0; i < 32; i++) Ws[tid + i * 256] = Wg3[tid + i * 256];
    __syncthreads();

    const long t = (long)blockIdx.x * 8 + (tid >> 5);
    const float* h2t = h2 + t * 256;
    float s = bg3[lane];
#pragma unroll 8
    for (int k = 0; k < 256; k += 4) {
        float4 h = *reinterpret_cast<const float4*>(h2t + k);
        s += h.x * Ws[(k + 0) * 32 + lane];
        s += h.y * Ws[(k + 1) * 32 + lane];
        s += h.z * Ws[(k + 2) * 32 + lane];
        s += h.w * Ws[(k + 3) * 32 + lane];
    }
    float bhalf = __shfl_down_sync(0xffffffffu, s, 16);
    float r = 0.f;
    if (lane < 16)
        r = s * (1.f / (1.f + expf(-bhalf))) + skipIn[t * 16 + lane];
    float sum = r;
    for (int m = 8; m; m >>= 1) sum += __shfl_xor_sync(0xffffffffu, sum, m, 16);
    float mean = sum * (1.f / 16.f);
    float d = r - mean;
    float vs = d * d;
    for (int m = 8; m; m >>= 1) vs += __shfl_xor_sync(0xffffffffu, vs, m, 16);
    float rstd = rsqrtf(vs * (1.f / 16.f) + 1e-6f);
    float ln = 0.f;
    if (lane < 16) ln = d * rstd * gg[lane] + bgn[lane];
    float mx = ln;
    for (int m = 8; m; m >>= 1) mx = fmaxf(mx, __shfl_xor_sync(0xffffffffu, mx, m, 16));
    float e = (lane < 16) ? expf(ln - mx) : 0.f;
    float se = e;
    for (int m = 8; m; m >>= 1) se += __shfl_xor_sync(0xffffffffu, se, m, 16);
    if (lane < 16) wout[t * 16 + lane] = e / se;
}

// ---------------------------------------------------------------------------
// out = sum_v LN(E[v] + x[v]) * weight[v]
// ---------------------------------------------------------------------------
__global__ __launch_bounds__(256)
void enc_combine_kernel(const __half* __restrict__ E, const __half* __restrict__ vh,
                        const float* __restrict__ wout, const float* __restrict__ gv,
                        const float* __restrict__ bvn, float* __restrict__ outp)
{
    const long t = blockIdx.x;
    const int tid = threadIdx.x;
    const int lane = tid & 31, wid = tid >> 5;
    __shared__ float sw[16];
    __shared__ float part[8][256];
    if (tid < 16) sw[tid] = wout[t * 16 + tid];
    __syncthreads();

    const int c0 = lane * 8;
    float acc[8];
#pragma unroll
    for (int i = 0; i < 8; i++) acc[i] = 0.f;

#pragma unroll
    for (int vi = 0; vi < 2; vi++) {
        const int v = wid * 2 + vi;
        uint4 rawE = *reinterpret_cast<const uint4*>(
            E + ((size_t)v * BT_TOK + t) * 256 + c0);
        uint4 rawX = *reinterpret_cast<const uint4*>(
            vh + (size_t)t * DIN + v * DDIM + c0);
        const __half2* he = reinterpret_cast<const __half2*>(&rawE);
        const __half2* hx = reinterpret_cast<const __half2*>(&rawX);
        float e[8];
#pragma unroll
        for (int i = 0; i < 4; i++) {
            float2 fe = __half22float2(he[i]);
            float2 fx = __half22float2(hx[i]);
            e[2 * i]     = fe.x + fx.x;
            e[2 * i + 1] = fe.y + fx.y;
        }
        float s1 = 0.f, s2 = 0.f;
#pragma unroll
        for (int i = 0; i < 8; i++) { s1 += e[i]; s2 += e[i] * e[i]; }
#pragma unroll
        for (int m = 16; m; m >>= 1) {
            s1 += __shfl_xor_sync(0xffffffffu, s1, m);
            s2 += __shfl_xor_sync(0xffffffffu, s2, m);
        }
        const float mean = s1 * (1.f / 256.f);
        const float var = s2 * (1.f / 256.f) - mean * mean;
        const float rstd = rsqrtf(var + 1e-6f);
        const float w = sw[v];
        const float4 g0 = *reinterpret_cast<const float4*>(gv + v * DDIM + c0);
        const float4 g1 = *reinterpret_cast<const float4*>(gv + v * DDIM + c0 + 4);
        const float4 b0 = *reinterpret_cast<const float4*>(bvn + v * DDIM + c0);
        const float4 b1 = *reinterpret_cast<const float4*>(bvn + v * DDIM + c0 + 4);
        const float gva[8] = {g0.x, g0.y, g0.z, g0.w, g1.x, g1.y, g1.z, g1.w};
        const float bva[8] = {b0.x, b0.y, b0.z, b0.w, b1.x, b1.y, b1.z, b1.w};
#pragma unroll
        for (int i = 0; i < 8; i++)
            acc[i] += ((e[i] - mean) * rstd * gva[i] + bva[i]) * w;
    }
#pragma unroll
    for (int i = 0; i < 8; i++) part[wid][c0 + i] = acc[i];
    __syncthreads();
    float s = 0.f;
#pragma unroll
    for (int wwi = 0; wwi < 8; wwi++) s += part[wwi][tid];
    outp[t * DDIM + tid] = s;
}

// ---------------------------------------------------------------------------
extern "C" void kernel_launch(void* const* d_in, const int* in_sizes, int n_in,
                              void* d_out, int out_size)
{
    const float* vars = (const float*)d_in[0];
    const float* Wg1  = (const float*)d_in[1];
    const float* bg1  = (const float*)d_in[2];
    const float* Wg2  = (const float*)d_in[3];
    const float* bg2  = (const float*)d_in[4];
    const float* Wg3  = (const float*)d_in[5];
    const float* bg3  = (const float*)d_in[6];
    const float* Wgs  = (const float*)d_in[7];
    const float* bgs  = (const float*)d_in[8];
    const float* gg   = (const float*)d_in[9];
    const float* bgn  = (const float*)d_in[10];
    const float* Wv1  = (const float*)d_in[11];
    const float* bv1  = (const float*)d_in[12];
    const float* Wv2  = (const float*)d_in[13];
    const float* bv2  = (const float*)d_in[14];
    const float* Wv3  = (const float*)d_in[15];
    const float* bv3  = (const float*)d_in[16];
    const float* gv   = (const float*)d_in[17];
    const float* bvn  = (const float*)d_in[18];

    float* out  = (float*)d_out;
    float* wout = out + BT_TOK * DDIM;

    unsigned char* gb = nullptr;
    cudaGetSymbolAddress((void**)&gb, g_buf);
    __half* VH  = (__half*)(gb + O_VH);
    __half* H1  = (__half*)(gb + O_H1);
    float*  H2F = (float*)(gb + O_H2F);
    __half* E   = (__half*)(gb + O_E);
    float*  SKP = (float*)(gb + O_SKIP);
    __half* G1T = (__half*)(gb + O_G1);
    __half* G2T = (__half*)(gb + O_G2);
    __half* W1T = (__half*)(gb + O_W1);
    __half* W2T = (__half*)(gb + O_W2);
    __half* W3T = (__half*)(gb + O_W3);

    cudaFuncSetAttribute(mma_gemm, cudaFuncAttributeMaxDynamicSharedMemorySize, SMEM_TOT);
    cudaFuncSetAttribute(fused_var, cudaFuncAttributeMaxDynamicSharedMemorySize, FSMEM);

    // conversions
    conv_split<<<32768, 256>>>(vars, VH);
    conv_wT<<<dim3(8, 128, 1), 256>>>(Wg1, G1T, 4096, 256);
    conv_wT<<<dim3(8, 8, 1),   256>>>(Wg2, G2T, 256, 256);
    conv_wT<<<dim3(8, 8, 16),  256>>>(Wv1, W1T, 256, 256);
    conv_wT<<<dim3(8, 8, 16),  256>>>(Wv2, W2T, 256, 256);
    conv_wT3<<<dim3(16, 8, 16), 256>>>(Wv3, W3T);

    // fused per-variable chain (M=64 tiles, 2 CTAs/SM)
    fused_var<<<dim3(256, 16), 256, FSMEM>>>(VH, W1T, W2T, W3T, bv1, bv2, bv3, E);

    // weight-GRN path
    skip_kernel<<<1024, 256>>>(VH, Wgs, bgs, SKP);
    mma_gemm<<<dim3(2, 128, 1), 256, SMEM_TOT>>>(
        VH, 0, DIN, G1T, 0, bg1, 0, nullptr, H1, 0, 256, 4096, 1);
    mma_gemm<<<dim3(2, 128, 1), 256, SMEM_TOT>>>(
        H1, 0, 256, G2T, 0, bg2, 0, H2F, nullptr, 0, 256, 256, 0);
    wlogits_kernel<<<2048, 256>>>(H2F, Wg3, bg3, gg, bgn, SKP, wout);

    // final combine
    enc_combine_kernel<<<16384, 256>>>(E, VH, wout, gv, bvn, out);
}

// round 11
// speedup vs baseline: 2.0457x; 1.0065x over previous
#include <cuda_runtime.h>
#include <cuda_fp16.h>
#include <cstdint>

// ---------------------------------------------------------------------------
// VSN on GB300 — Round 11: E = glu + x fused in fused_var copy-out (kills
// enc_combine's VH read); R10 config otherwise.
// B=8,T=2048,NV=16,D=256 -> BT=16384, DIN=4096
// ---------------------------------------------------------------------------

#define BT_TOK 16384L
#define DDIM   256
#define DIN    4096

// ---------------- scratch (bytes) ----------------
#define O_VH    0ULL            // vars fp16 [16384,4096]          128MB
#define O_H1    134217728ULL    // h1 fp16 [16384,256]
#define O_H2F   142606336ULL    // h2 fp32 [16384,256]
#define O_E     159383552ULL    // E=glu+x fp16 16x[16384,256]     128MB
#define O_SKIP  293601280ULL    // skip fp32 [16384,16]
#define O_G1    294649856ULL    // Wg1^T fp16 [256,4096]
#define O_G2    296747008ULL    // Wg2^T fp16 [256,256]
#define O_W1    296878080ULL    // Wv1^T fp16 16x[256,256]
#define O_W2    298975232ULL
#define O_W3    301072384ULL    // Wv3^T perm fp16 16x[512,256]
#define G_TOTAL 305266688ULL

__device__ __align__(1024) unsigned char g_buf[G_TOTAL];

// ---------------- helpers ----------------
__device__ __forceinline__ uint32_t smem_u32(const void* p) {
    uint32_t a;
    asm("{ .reg .u64 t; cvta.to.shared.u64 t, %1; cvt.u32.u64 %0, t; }" : "=r"(a) : "l"(p));
    return a;
}
__device__ __forceinline__ void cpasync16(uint32_t dst, const void* src) {
    asm volatile("cp.async.cg.shared.global [%0], [%1], 16;" :: "r"(dst), "l"(src));
}
#define CP_COMMIT() asm volatile("cp.async.commit_group;" ::: "memory")
#define CP_WAIT(n)  asm volatile("cp.async.wait_group %0;" :: "n"(n) : "memory")

__device__ __forceinline__ void ldsm_x4(uint32_t (&r)[4], uint32_t addr) {
    asm volatile("ldmatrix.sync.aligned.m8n8.x4.shared.b16 {%0,%1,%2,%3}, [%4];"
        : "=r"(r[0]), "=r"(r[1]), "=r"(r[2]), "=r"(r[3]) : "r"(addr));
}
__device__ __forceinline__ void mma16816(float (&c)[4], const uint32_t (&a)[4],
                                         uint32_t b0, uint32_t b1) {
    asm volatile("mma.sync.aligned.m16n8k16.row.col.f32.f16.f16.f32 "
        "{%0,%1,%2,%3}, {%4,%5,%6,%7}, {%8,%9}, {%0,%1,%2,%3};"
        : "+f"(c[0]), "+f"(c[1]), "+f"(c[2]), "+f"(c[3])
        : "r"(a[0]), "r"(a[1]), "r"(a[2]), "r"(a[3]), "r"(b0), "r"(b1));
}
__device__ __forceinline__ uint32_t hadd2_f32(uint32_t e, uint32_t x) {
    __half2 he = *reinterpret_cast<__half2*>(&e);
    __half2 hx = *reinterpret_cast<__half2*>(&x);
    float2 fe = __half22float2(he);
    float2 fx = __half22float2(hx);
    __half2 r = __floats2half2_rn(fe.x + fx.x, fe.y + fx.y);
    return *reinterpret_cast<uint32_t*>(&r);
}

// ---------------------------------------------------------------------------
// conversions
// ---------------------------------------------------------------------------
__global__ __launch_bounds__(256)
void conv_split(const float* __restrict__ x, __half* __restrict__ h)
{
    size_t i = ((size_t)blockIdx.x * 512 + threadIdx.x * 2) * 4;
#pragma unroll
    for (int u = 0; u < 2; u++) {
        float4 v = *reinterpret_cast<const float4*>(x + i + u * 4);
        *reinterpret_cast<__half2*>(h + i + u * 4)     = __floats2half2_rn(v.x, v.y);
        *reinterpret_cast<__half2*>(h + i + u * 4 + 2) = __floats2half2_rn(v.z, v.w);
    }
}

__global__ __launch_bounds__(256)
void conv_wT(const float* __restrict__ W, __half* __restrict__ TH, int K, int N)
{
    const size_t vb = (size_t)blockIdx.z * K * N;
    __shared__ float tile[32][33];
    const int k0 = blockIdx.y * 32, n0 = blockIdx.x * 32;
    const int tx = threadIdx.x & 31, ty = threadIdx.x >> 5;
#pragma unroll
    for (int i = 0; i < 4; i++)
        tile[ty + i * 8][tx] = W[vb + (size_t)(k0 + ty + i * 8) * N + n0 + tx];
    __syncthreads();
#pragma unroll
    for (int i = 0; i < 4; i++) {
        int n = ty + i * 8;
        TH[vb + (size_t)(n0 + n) * K + k0 + tx] = __float2half_rn(tile[tx][n]);
    }
}

// Wv3 transpose with GLU interleave
__global__ __launch_bounds__(256)
void conv_wT3(const float* __restrict__ W, __half* __restrict__ TH)
{
    const size_t vbs = (size_t)blockIdx.z * 256 * 512;
    const size_t vbd = (size_t)blockIdx.z * 512 * 256;
    __shared__ float tile[32][33];
    const int k0 = blockIdx.y * 32, c0 = blockIdx.x * 32;
    const int tx = threadIdx.x & 31, ty = threadIdx.x >> 5;
#pragma unroll
    for (int i = 0; i < 4; i++)
        tile[ty + i * 8][tx] = W[vbs + (size_t)(k0 + ty + i * 8) * 512 + c0 + tx];
    __syncthreads();
#pragma unroll
    for (int i = 0; i < 4; i++) {
        int c = c0 + ty + i * 8;
        int orow = (c < 256) ? (2 * c) : (2 * (c - 256) + 1);
        TH[vbd + (size_t)orow * 256 + k0 + tx] = __float2half_rn(tile[tx][ty + i * 8]);
    }
}

// ---------------------------------------------------------------------------
// mma_gemm: 3-stage cp.async ring, 2 CTAs/SM. G1 (mode1), G2 (mode0).
// ---------------------------------------------------------------------------
#define RS 72
#define OFF_B  18432
#define ST_SIZE 36864
#define SMEM_TOT 110592

__global__ __launch_bounds__(256, 2)
void mma_gemm(const __half* __restrict__ A, long long aV, int lda,
              const __half* __restrict__ BH, long long bV,
              const float* __restrict__ bias, int biasV,
              float* __restrict__ CF, __half* __restrict__ CH,
              long long cV, int ldc, int K, int mode)
{
    extern __shared__ __align__(1024) unsigned char sm[];
    const uint32_t sb = smem_u32(sm);
    const int tid = threadIdx.x;
    const int lane = tid & 31, wid = tid >> 5;
    const int wm = wid & 1, wn = wid >> 1;
    const int v = blockIdx.z;
    const int m0 = blockIdx.y * 128;
    const int nb = blockIdx.x * 128;

    const __half* Ap  = A  + (size_t)v * aV + (size_t)m0 * lda;
    const __half* Bhp = BH + (size_t)v * bV + (size_t)nb * K;

    const int lr = tid >> 3;
    const int lc = (tid & 7) * 8;

    float acc[4][4][4];
#pragma unroll
    for (int i = 0; i < 4; i++)
#pragma unroll
        for (int j = 0; j < 4; j++)
#pragma unroll
            for (int k = 0; k < 4; k++) acc[i][j][k] = 0.f;

    const int nc = K >> 6;

    auto load_stage = [&](int s, int k0) {
        const uint32_t base = sb + s * ST_SIZE;
#pragma unroll
        for (int t = 0; t < 4; t++) {
            const int row = lr + t * 32;
            const uint32_t doff = (uint32_t)(row * RS + lc) * 2;
            cpasync16(base + doff,         Ap  + (size_t)row * lda + k0 + lc);
            cpasync16(base + OFF_B + doff, Bhp + (size_t)row * K   + k0 + lc);
        }
    };

    const uint32_t aoff = (uint32_t)(((wm * 64 + (lane & 15)) * RS + (lane >> 4) * 8) * 2);
    const uint32_t boff = (uint32_t)(((wn * 32 + (lane & 15)) * RS + (lane >> 4) * 8) * 2);

    load_stage(0, 0);              CP_COMMIT();
    if (nc > 1) { load_stage(1, 64); } CP_COMMIT();

    int sidx = 0;
    for (int c = 0; c < nc; c++) {
        CP_WAIT(1);
        __syncthreads();
        const uint32_t base = sb + sidx * ST_SIZE;
#pragma unroll
        for (int kc = 0; kc < 64; kc += 16) {
            uint32_t a[4][4], bh[2][4];
#pragma unroll
            for (int mt = 0; mt < 4; mt++)
                ldsm_x4(a[mt], base + aoff + mt * (16 * RS * 2) + kc * 2);
#pragma unroll
            for (int p = 0; p < 2; p++)
                ldsm_x4(bh[p], base + OFF_B + boff + p * (16 * RS * 2) + kc * 2);
#pragma unroll
            for (int mt = 0; mt < 4; mt++)
#pragma unroll
                for (int q = 0; q < 4; q++)
                    mma16816(acc[mt][q], a[mt], bh[q >> 1][q & 1], bh[q >> 1][(q & 1) + 2]);
        }
        __syncthreads();
        if (c + 2 < nc) {
            int ns = sidx + 2; if (ns >= 3) ns -= 3;
            load_stage(ns, (c + 2) * 64);
        }
        CP_COMMIT();
        if (++sidx == 3) sidx = 0;
    }

    const int gid = lane >> 2, tig = lane & 3;
#pragma unroll
    for (int mt = 0; mt < 4; mt++) {
#pragma unroll
        for (int q = 0; q < 4; q++) {
            const int m = m0 + wm * 64 + mt * 16 + gid;
            const int n = nb + wn * 32 + q * 8 + tig * 2;
            const float* bp = bias + (size_t)v * biasV + n;
            const float b0 = bp[0], b1 = bp[1];
            float x0 = acc[mt][q][0] + b0, x1 = acc[mt][q][1] + b1;
            float y0 = acc[mt][q][2] + b0, y1 = acc[mt][q][3] + b1;
            if (mode == 1) {
                x0 = (x0 > 0.f) ? x0 : expm1f(x0);
                x1 = (x1 > 0.f) ? x1 : expm1f(x1);
                y0 = (y0 > 0.f) ? y0 : expm1f(y0);
                y1 = (y1 > 0.f) ? y1 : expm1f(y1);
            }
            if (mode == 0) {
                float* d0 = CF + (size_t)v * cV + (size_t)m * ldc + n;
                float2 o0; o0.x = x0; o0.y = x1;
                float2 o1; o1.x = y0; o1.y = y1;
                *reinterpret_cast<float2*>(d0) = o0;
                *reinterpret_cast<float2*>(d0 + 8 * ldc) = o1;
            } else {
                __half* d0 = CH + (size_t)v * cV + (size_t)m * ldc + n;
                *reinterpret_cast<__half2*>(d0) = __floats2half2_rn(x0, x1);
                *reinterpret_cast<__half2*>(d0 + 8 * ldc) = __floats2half2_rn(y0, y1);
            }
        }
    }
}

// ---------------------------------------------------------------------------
// fused per-variable chain, M=64 tiles (2 CTAs/SM):
//   E = glu(elu(x@W1+b1)@W2+b2 @ W3perm + b3) + x
// ---------------------------------------------------------------------------
#define ACH 9216u                   // 64 * 72 * 2
#define FA0 0u
#define FA1 36864u
#define FWB 73728u
#define FSMEM 110592

__global__ __launch_bounds__(256, 2)
void fused_var(const __half* __restrict__ VH,
               const __half* __restrict__ W1T, const __half* __restrict__ W2T,
               const __half* __restrict__ W3T,
               const float* __restrict__ bv1, const float* __restrict__ bv2,
               const float* __restrict__ bv3,
               __half* __restrict__ E)
{
    extern __shared__ __align__(1024) unsigned char sm[];
    const uint32_t sb = smem_u32(sm);
    const int tid = threadIdx.x;
    const int lane = tid & 31, wid = tid >> 5;
    const int wm = wid & 1, wn = wid >> 1;
    const int gid = lane >> 2, tig = lane & 3;
    const int v = blockIdx.y;
    const int m0 = blockIdx.x * 64;

    // ---- load x_v tile [64,256] into A0 (4 chunks) ----
    {
        const __half* xp = VH + (size_t)m0 * DIN + v * 256;
#pragma unroll
        for (int t = 0; t < 8; t++) {
            const int id = tid + t * 256;
            const int ch = id >> 9;
            const int rem = id & 511;
            const int row = rem >> 3;
            const int lc8 = (rem & 7) * 8;
            cpasync16(sb + FA0 + ch * ACH + (uint32_t)(row * RS + lc8) * 2,
                      xp + (size_t)row * DIN + ch * 64 + lc8);
        }
        CP_COMMIT();
    }

    const uint32_t aoff = (uint32_t)(((wm * 32 + (lane & 15)) * RS + (lane >> 4) * 8) * 2);
    const uint32_t boff = (uint32_t)(((wn * 32 + (lane & 15)) * RS + (lane >> 4) * 8) * 2);
    const int lr = tid >> 3;
    const int lc = (tid & 7) * 8;

    for (int stage = 0; stage < 3; stage++) {
        const __half* W = (stage == 0) ? (W1T + (size_t)v * 65536)
                        : (stage == 1) ? (W2T + (size_t)v * 65536)
                                       : (W3T + (size_t)v * 131072);
        const int nPass = (stage == 2) ? 4 : 2;
        const uint32_t aBuf = (stage == 1) ? FA1 : FA0;
        const uint32_t oBuf = (stage == 0) ? FA1 : FA0;

        for (int np = 0; np < nPass; np++) {
            float acc[2][4][4];
#pragma unroll
            for (int i = 0; i < 2; i++)
#pragma unroll
                for (int j = 0; j < 4; j++)
#pragma unroll
                    for (int k = 0; k < 4; k++) acc[i][j][k] = 0.f;

            const __half* Wp = W + (size_t)(np * 128) * 256;
#pragma unroll
            for (int pc = 0; pc < 2; pc++) {
#pragma unroll
                for (int t = 0; t < 4; t++) {
                    const int row = lr + t * 32;
                    cpasync16(sb + FWB + pc * 18432 + (uint32_t)(row * RS + lc) * 2,
                              Wp + (size_t)row * 256 + pc * 64 + lc);
                }
                CP_COMMIT();
            }

            for (int c = 0; c < 4; c++) {
                if (c < 3) { CP_WAIT(1); } else { CP_WAIT(0); }
                __syncthreads();
                const uint32_t abase = sb + aBuf + c * ACH;
                const uint32_t bbase = sb + FWB + (c & 1) * 18432;
#pragma unroll
                for (int kc = 0; kc < 64; kc += 16) {
                    uint32_t a[2][4], bh[2][4];
#pragma unroll
                    for (int mt = 0; mt < 2; mt++)
                        ldsm_x4(a[mt], abase + aoff + mt * (16 * RS * 2) + kc * 2);
#pragma unroll
                    for (int p = 0; p < 2; p++)
                        ldsm_x4(bh[p], bbase + boff + p * (16 * RS * 2) + kc * 2);
#pragma unroll
                    for (int mt = 0; mt < 2; mt++)
#pragma unroll
                        for (int q = 0; q < 4; q++)
                            mma16816(acc[mt][q], a[mt], bh[q >> 1][q & 1], bh[q >> 1][(q & 1) + 2]);
                }
                __syncthreads();
                if (c + 2 < 4) {
#pragma unroll
                    for (int t = 0; t < 4; t++) {
                        const int row = lr + t * 32;
                        cpasync16(sb + FWB + (c & 1) * 18432 + (uint32_t)(row * RS + lc) * 2,
                                  Wp + (size_t)row * 256 + (c + 2) * 64 + lc);
                    }
                    CP_COMMIT();
                }
            }

            // ---- epilogue ----
            if (stage < 2) {
                const float* bp = ((stage == 0) ? bv1 : bv2) + (size_t)v * 256;
                __half* ob = reinterpret_cast<__half*>(sm) + (oBuf >> 1);
#pragma unroll
                for (int mt = 0; mt < 2; mt++) {
#pragma unroll
                    for (int q = 0; q < 4; q++) {
                        const int m = wm * 32 + mt * 16 + gid;
                        const int gn = np * 128 + wn * 32 + q * 8 + tig * 2;
                        const float b0 = bp[gn], b1 = bp[gn + 1];
                        float x0 = acc[mt][q][0] + b0, x1 = acc[mt][q][1] + b1;
                        float y0 = acc[mt][q][2] + b0, y1 = acc[mt][q][3] + b1;
                        if (stage == 0) {
                            x0 = (x0 > 0.f) ? x0 : expm1f(x0);
                            x1 = (x1 > 0.f) ? x1 : expm1f(x1);
                            y0 = (y0 > 0.f) ? y0 : expm1f(y0);
                            y1 = (y1 > 0.f) ? y1 : expm1f(y1);
                        }
                        const int ch = gn >> 6;
                        const int ko = gn & 63;
                        __half* d0 = ob + ch * (ACH / 2) + m * RS + ko;
                        *reinterpret_cast<__half2*>(d0) = __floats2half2_rn(x0, x1);
                        *reinterpret_cast<__half2*>(d0 + 8 * RS) = __floats2half2_rn(y0, y1);
                    }
                }
                __syncthreads();
            } else {
                // GLU -> stage in A1 [64][64]; copy-out adds x (coalesced) -> E
                const float* bp = bv3 + (size_t)v * 512;
                const int jbase = np * 64;
                __half* Eg = reinterpret_cast<__half*>(sm) + (FA1 >> 1);
#pragma unroll
                for (int mt = 0; mt < 2; mt++) {
#pragma unroll
                    for (int q = 0; q < 4; q++) {
                        const int nl = wn * 32 + q * 8 + tig * 2;
                        const int jl = nl >> 1;
                        const int jg = jbase + jl;
                        const float ba = bp[jg], bb = bp[jg + 256];
                        const int r0 = wm * 32 + mt * 16 + gid;
                        float a0 = acc[mt][q][0] + ba, b0 = acc[mt][q][1] + bb;
                        float a1 = acc[mt][q][2] + ba, b1 = acc[mt][q][3] + bb;
                        Eg[r0 * 64 + jl]       = __float2half_rn(a0 * (1.f / (1.f + expf(-b0))));
                        Eg[(r0 + 8) * 64 + jl] = __float2half_rn(a1 * (1.f / (1.f + expf(-b1))));
                    }
                }
                __syncthreads();
                const int row = tid >> 2;
                const int chh = (tid & 3) * 16;
                const __half* src = Eg + row * 64 + chh;
                const __half* xsrc = VH + (size_t)(m0 + row) * DIN + v * 256 + jbase + chh;
                __half* dst = E + ((size_t)v * BT_TOK + m0 + row) * 256 + jbase + chh;
#pragma unroll
                for (int u = 0; u < 2; u++) {
                    uint4 ev = *reinterpret_cast<const uint4*>(src + u * 8);
                    uint4 xv = *reinterpret_cast<const uint4*>(xsrc + u * 8);
                    uint4 ov;
                    ov.x = hadd2_f32(ev.x, xv.x);
                    ov.y = hadd2_f32(ev.y, xv.y);
                    ov.z = hadd2_f32(ev.z, xv.z);
                    ov.w = hadd2_f32(ev.w, xv.w);
                    *reinterpret_cast<uint4*>(dst + u * 8) = ov;
                }
                __syncthreads();
            }
        }
    }
}

// ---------------------------------------------------------------------------
// skip = flat @ Wgs + bgs (fp16 VH), K-chunk 256
// ---------------------------------------------------------------------------
__global__ __launch_bounds__(256)
void skip_kernel(const __half* __restrict__ vh, const float* __restrict__ Wgs,
                 const float* __restrict__ bgs, float* __restrict__ skipOut)
{
    __shared__ __half As[16][256];
    __shared__ float Ws[256][16];
    const int tid = threadIdx.x;
    const long t0 = (long)blockIdx.x * 16;
    const int o = tid & 15;
    const int tr = tid >> 4;
    float s = 0.f;
    for (int k0 = 0; k0 < DIN; k0 += 256) {
        {
            const int r = tid >> 4;
            const int cc = (tid & 15) * 16;
            *reinterpret_cast<uint4*>(&As[r][cc]) =
                *reinterpret_cast<const uint4*>(vh + (t0 + r) * DIN + k0 + cc);
            *reinterpret_cast<uint4*>(&As[r][cc + 8]) =
                *reinterpret_cast<const uint4*>(vh + (t0 + r) * DIN + k0 + cc + 8);
        }
        {
            const int r = tid;
            *reinterpret_cast<float4*>(&Ws[r][0])  = *reinterpret_cast<const float4*>(Wgs + (long)(k0 + r) * 16 + 0);
            *reinterpret_cast<float4*>(&Ws[r][4])  = *reinterpret_cast<const float4*>(Wgs + (long)(k0 + r) * 16 + 4);
            *reinterpret_cast<float4*>(&Ws[r][8])  = *reinterpret_cast<const float4*>(Wgs + (long)(k0 + r) * 16 + 8);
            *reinterpret_cast<float4*>(&Ws[r][12]) = *reinterpret_cast<const float4*>(Wgs + (long)(k0 + r) * 16 + 12);
        }
        __syncthreads();
#pragma unroll 16
        for (int kk = 0; kk < 256; kk++) s += __half2float(As[tr][kk]) * Ws[kk][o];
        __syncthreads();
    }
    skipOut[(t0 + tr) * 16 + o] = s + bgs[o];
}

// ---------------------------------------------------------------------------
// weight logits -> softmax weights
// ---------------------------------------------------------------------------
__global__ __launch_bounds__(256)
void wlogits_kernel(const float* __restrict__ h2, const float* __restrict__ Wg3,
                    const float* __restrict__ bg3, const float* __restrict__ gg,
                    const float* __restrict__ bgn, const float* __restrict__ skipIn,
                    float* __restrict__ wout)
{
    __shared__ float Ws[256 * 32];
    const int tid = threadIdx.x;
    const int lane = tid & 31;
#pragma unroll
    for (int i = 0; i < 32; i++) Ws[tid + i * 256] = Wg3[tid + i * 256];
    __syncthreads();

    const long t = (long)blockIdx.x * 8 + (tid >> 5);
    const float* h2t = h2 + t * 256;
    float s = bg3[lane];
#pragma unroll 8
    for (int k = 0; k < 256; k += 4) {
        float4 h = *reinterpret_cast<const float4*>(h2t + k);
        s += h.x * Ws[(k + 0) * 32 + lane];
        s += h.y * Ws[(k + 1) * 32 + lane];
        s += h.z * Ws[(k + 2) * 32 + lane];
        s += h.w * Ws[(k + 3) * 32 + lane];
    }
    float bhalf = __shfl_down_sync(0xffffffffu, s, 16);
    float r = 0.f;
    if (lane < 16)
        r = s * (1.f / (1.f + expf(-bhalf))) + skipIn[t * 16 + lane];
    float sum = r;
    for (int m = 8; m; m >>= 1) sum += __shfl_xor_sync(0xffffffffu, sum, m, 16);
    float mean = sum * (1.f / 16.f);
    float d = r - mean;
    float vs = d * d;
    for (int m = 8; m; m >>= 1) vs += __shfl_xor_sync(0xffffffffu, vs, m, 16);
    float rstd = rsqrtf(vs * (1.f / 16.f) + 1e-6f);
    float ln = 0.f;
    if (lane < 16) ln = d * rstd * gg[lane] + bgn[lane];
    float mx = ln;
    for (int m = 8; m; m >>= 1) mx = fmaxf(mx, __shfl_xor_sync(0xffffffffu, mx, m, 16));
    float e = (lane < 16) ? expf(ln - mx) : 0.f;
    float se = e;
    for (int m = 8; m; m >>= 1) se += __shfl_xor_sync(0xffffffffu, se, m, 16);
    if (lane < 16) wout[t * 16 + lane] = e / se;
}

// ---------------------------------------------------------------------------
// out = sum_v LN(E[v]) * weight[v]    (E already = glu + x)
// ---------------------------------------------------------------------------
__global__ __launch_bounds__(256)
void enc_combine_kernel(const __half* __restrict__ E, const float* __restrict__ wout,
                        const float* __restrict__ gv, const float* __restrict__ bvn,
                        float* __restrict__ outp)
{
    const long t = blockIdx.x;
    const int tid = threadIdx.x;
    const int lane = tid & 31, wid = tid >> 5;
    __shared__ float sw[16];
    __shared__ float part[8][256];
    if (tid < 16) sw[tid] = wout[t * 16 + tid];
    __syncthreads();

    const int c0 = lane * 8;
    float acc[8];
#pragma unroll
    for (int i = 0; i < 8; i++) acc[i] = 0.f;

#pragma unroll
    for (int vi = 0; vi < 2; vi++) {
        const int v = wid * 2 + vi;
        uint4 rawE = *reinterpret_cast<const uint4*>(
            E + ((size_t)v * BT_TOK + t) * 256 + c0);
        const __half2* he = reinterpret_cast<const __half2*>(&rawE);
        float e[8];
#pragma unroll
        for (int i = 0; i < 4; i++) {
            float2 fe = __half22float2(he[i]);
            e[2 * i]     = fe.x;
            e[2 * i + 1] = fe.y;
        }
        float s1 = 0.f, s2 = 0.f;
#pragma unroll
        for (int i = 0; i < 8; i++) { s1 += e[i]; s2 += e[i] * e[i]; }
#pragma unroll
        for (int m = 16; m; m >>= 1) {
            s1 += __shfl_xor_sync(0xffffffffu, s1, m);
            s2 += __shfl_xor_sync(0xffffffffu, s2, m);
        }
        const float mean = s1 * (1.f / 256.f);
        const float var = s2 * (1.f / 256.f) - mean * mean;
        const float rstd = rsqrtf(var + 1e-6f);
        const float w = sw[v];
        const float4 g0 = *reinterpret_cast<const float4*>(gv + v * DDIM + c0);
        const float4 g1 = *reinterpret_cast<const float4*>(gv + v * DDIM + c0 + 4);
        const float4 b0 = *reinterpret_cast<const float4*>(bvn + v * DDIM + c0);
        const float4 b1 = *reinterpret_cast<const float4*>(bvn + v * DDIM + c0 + 4);
        const float gva[8] = {g0.x, g0.y, g0.z, g0.w, g1.x, g1.y, g1.z, g1.w};
        const float bva[8] = {b0.x, b0.y, b0.z, b0.w, b1.x, b1.y, b1.z, b1.w};
#pragma unroll
        for (int i = 0; i < 8; i++)
            acc[i] += ((e[i] - mean) * rstd * gva[i] + bva[i]) * w;
    }
#pragma unroll
    for (int i = 0; i < 8; i++) part[wid][c0 + i] = acc[i];
    __syncthreads();
    float s = 0.f;
#pragma unroll
    for (int wwi = 0; wwi < 8; wwi++) s += part[wwi][tid];
    outp[t * DDIM + tid] = s;
}

// ---------------------------------------------------------------------------
extern "C" void kernel_launch(void* const* d_in, const int* in_sizes, int n_in,
                              void* d_out, int out_size)
{
    const float* vars = (const float*)d_in[0];
    const float* Wg1  = (const float*)d_in[1];
    const float* bg1  = (const float*)d_in[2];
    const float* Wg2  = (const float*)d_in[3];
    const float* bg2  = (const float*)d_in[4];
    const float* Wg3  = (const float*)d_in[5];
    const float* bg3  = (const float*)d_in[6];
    const float* Wgs  = (const float*)d_in[7];
    const float* bgs  = (const float*)d_in[8];
    const float* gg   = (const float*)d_in[9];
    const float* bgn  = (const float*)d_in[10];
    const float* Wv1  = (const float*)d_in[11];
    const float* bv1  = (const float*)d_in[12];
    const float* Wv2  = (const float*)d_in[13];
    const float* bv2  = (const float*)d_in[14];
    const float* Wv3  = (const float*)d_in[15];
    const float* bv3  = (const float*)d_in[16];
    const float* gv   = (const float*)d_in[17];
    const float* bvn  = (const float*)d_in[18];

    float* out  = (float*)d_out;
    float* wout = out + BT_TOK * DDIM;

    unsigned char* gb = nullptr;
    cudaGetSymbolAddress((void**)&gb, g_buf);
    __half* VH  = (__half*)(gb + O_VH);
    __half* H1  = (__half*)(gb + O_H1);
    float*  H2F = (float*)(gb + O_H2F);
    __half* E   = (__half*)(gb + O_E);
    float*  SKP = (float*)(gb + O_SKIP);
    __half* G1T = (__half*)(gb + O_G1);
    __half* G2T = (__half*)(gb + O_G2);
    __half* W1T = (__half*)(gb + O_W1);
    __half* W2T = (__half*)(gb + O_W2);
    __half* W3T = (__half*)(gb + O_W3);

    cudaFuncSetAttribute(mma_gemm, cudaFuncAttributeMaxDynamicSharedMemorySize, SMEM_TOT);
    cudaFuncSetAttribute(fused_var, cudaFuncAttributeMaxDynamicSharedMemorySize, FSMEM);

    // conversions
    conv_split<<<32768, 256>>>(vars, VH);
    conv_wT<<<dim3(8, 128, 1), 256>>>(Wg1, G1T, 4096, 256);
    conv_wT<<<dim3(8, 8, 1),   256>>>(Wg2, G2T, 256, 256);
    conv_wT<<<dim3(8, 8, 16),  256>>>(Wv1, W1T, 256, 256);
    conv_wT<<<dim3(8, 8, 16),  256>>>(Wv2, W2T, 256, 256);
    conv_wT3<<<dim3(16, 8, 16), 256>>>(Wv3, W3T);

    // fused per-variable chain (M=64 tiles, 2 CTAs/SM)
    fused_var<<<dim3(256, 16), 256, FSMEM>>>(VH, W1T, W2T, W3T, bv1, bv2, bv3, E);

    // weight-GRN path
    skip_kernel<<<1024, 256>>>(VH, Wgs, bgs, SKP);
    mma_gemm<<<dim3(2, 128, 1), 256, SMEM_TOT>>>(
        VH, 0, DIN, G1T, 0, bg1, 0, nullptr, H1, 0, 256, 4096, 1);
    mma_gemm<<<dim3(2, 128, 1), 256, SMEM_TOT>>>(
        H1, 0, 256, G2T, 0, bg2, 0, H2F, nullptr, 0, 256, 256, 0);
    wlogits_kernel<<<2048, 256>>>(H2F, Wg3, bg3, gg, bgn, SKP, wout);

    // final combine
    enc_combine_kernel<<<16384, 256>>>(E, wout, gv, bvn, out);
}

// round 12
// speedup vs baseline: 2.1452x; 1.0486x over previous
#include <cuda_runtime.h>
#include <cuda_fp16.h>
#include <cstdint>

// ---------------------------------------------------------------------------
// VSN on GB300 — Round 12: mega-kernel co-schedules G1 GEMM + skip + fused
// per-variable chain in one launch (independent work overlaps on the SMs).
// B=8,T=2048,NV=16,D=256 -> BT=16384, DIN=4096
// ---------------------------------------------------------------------------

#define BT_TOK 16384L
#define DDIM   256
#define DIN    4096

// ---------------- scratch (bytes) ----------------
#define O_VH    0ULL            // vars fp16 [16384,4096]          128MB
#define O_H1    134217728ULL    // h1 fp16 [16384,256]
#define O_H2F   142606336ULL    // h2 fp32 [16384,256]
#define O_E     159383552ULL    // E=glu+x fp16 16x[16384,256]     128MB
#define O_SKIP  293601280ULL    // skip fp32 [16384,16]
#define O_G1    294649856ULL    // Wg1^T fp16 [256,4096]
#define O_G2    296747008ULL    // Wg2^T fp16 [256,256]
#define O_W1    296878080ULL    // Wv1^T fp16 16x[256,256]
#define O_W2    298975232ULL
#define O_W3    301072384ULL    // Wv3^T perm fp16 16x[512,256]
#define G_TOTAL 305266688ULL

__device__ __align__(1024) unsigned char g_buf[G_TOTAL];

// ---------------- helpers ----------------
__device__ __forceinline__ uint32_t smem_u32(const void* p) {
    uint32_t a;
    asm("{ .reg .u64 t; cvta.to.shared.u64 t, %1; cvt.u32.u64 %0, t; }" : "=r"(a) : "l"(p));
    return a;
}
__device__ __forceinline__ void cpasync16(uint32_t dst, const void* src) {
    asm volatile("cp.async.cg.shared.global [%0], [%1], 16;" :: "r"(dst), "l"(src));
}
#define CP_COMMIT() asm volatile("cp.async.commit_group;" ::: "memory")
#define CP_WAIT(n)  asm volatile("cp.async.wait_group %0;" :: "n"(n) : "memory")

__device__ __forceinline__ void ldsm_x4(uint32_t (&r)[4], uint32_t addr) {
    asm volatile("ldmatrix.sync.aligned.m8n8.x4.shared.b16 {%0,%1,%2,%3}, [%4];"
        : "=r"(r[0]), "=r"(r[1]), "=r"(r[2]), "=r"(r[3]) : "r"(addr));
}
__device__ __forceinline__ void mma16816(float (&c)[4], const uint32_t (&a)[4],
                                         uint32_t b0, uint32_t b1) {
    asm volatile("mma.sync.aligned.m16n8k16.row.col.f32.f16.f16.f32 "
        "{%0,%1,%2,%3}, {%4,%5,%6,%7}, {%8,%9}, {%0,%1,%2,%3};"
        : "+f"(c[0]), "+f"(c[1]), "+f"(c[2]), "+f"(c[3])
        : "r"(a[0]), "r"(a[1]), "r"(a[2]), "r"(a[3]), "r"(b0), "r"(b1));
}
__device__ __forceinline__ uint32_t hadd2_f32(uint32_t e, uint32_t x) {
    __half2 he = *reinterpret_cast<__half2*>(&e);
    __half2 hx = *reinterpret_cast<__half2*>(&x);
    float2 fe = __half22float2(he);
    float2 fx = __half22float2(hx);
    __half2 r = __floats2half2_rn(fe.x + fx.x, fe.y + fx.y);
    return *reinterpret_cast<uint32_t*>(&r);
}

// ---------------------------------------------------------------------------
// conversions
// ---------------------------------------------------------------------------
__global__ __launch_bounds__(256)
void conv_split(const float* __restrict__ x, __half* __restrict__ h)
{
    size_t i = ((size_t)blockIdx.x * 512 + threadIdx.x * 2) * 4;
#pragma unroll
    for (int u = 0; u < 2; u++) {
        float4 v = *reinterpret_cast<const float4*>(x + i + u * 4);
        *reinterpret_cast<__half2*>(h + i + u * 4)     = __floats2half2_rn(v.x, v.y);
        *reinterpret_cast<__half2*>(h + i + u * 4 + 2) = __floats2half2_rn(v.z, v.w);
    }
}

__global__ __launch_bounds__(256)
void conv_wT(const float* __restrict__ W, __half* __restrict__ TH, int K, int N)
{
    const size_t vb = (size_t)blockIdx.z * K * N;
    __shared__ float tile[32][33];
    const int k0 = blockIdx.y * 32, n0 = blockIdx.x * 32;
    const int tx = threadIdx.x & 31, ty = threadIdx.x >> 5;
#pragma unroll
    for (int i = 0; i < 4; i++)
        tile[ty + i * 8][tx] = W[vb + (size_t)(k0 + ty + i * 8) * N + n0 + tx];
    __syncthreads();
#pragma unroll
    for (int i = 0; i < 4; i++) {
        int n = ty + i * 8;
        TH[vb + (size_t)(n0 + n) * K + k0 + tx] = __float2half_rn(tile[tx][n]);
    }
}

__global__ __launch_bounds__(256)
void conv_wT3(const float* __restrict__ W, __half* __restrict__ TH)
{
    const size_t vbs = (size_t)blockIdx.z * 256 * 512;
    const size_t vbd = (size_t)blockIdx.z * 512 * 256;
    __shared__ float tile[32][33];
    const int k0 = blockIdx.y * 32, c0 = blockIdx.x * 32;
    const int tx = threadIdx.x & 31, ty = threadIdx.x >> 5;
#pragma unroll
    for (int i = 0; i < 4; i++)
        tile[ty + i * 8][tx] = W[vbs + (size_t)(k0 + ty + i * 8) * 512 + c0 + tx];
    __syncthreads();
#pragma unroll
    for (int i = 0; i < 4; i++) {
        int c = c0 + ty + i * 8;
        int orow = (c < 256) ? (2 * c) : (2 * (c - 256) + 1);
        TH[vbd + (size_t)orow * 256 + k0 + tx] = __float2half_rn(tile[tx][ty + i * 8]);
    }
}

// ---------------------------------------------------------------------------
#define RS 72
#define OFF_B  18432
#define ST_SIZE 36864
#define SMEM_TOT 110592

#define ACH 9216u
#define FA0 0u
#define FA1 36864u
#define FWB 73728u

// ---- G1 GEMM body (mode 1: ELU + fp16 out). K=4096, block bidx in [0,256) ----
__device__ __noinline__ void dev_g1(unsigned char* sm, uint32_t sb,
                                    const __half* VH, const __half* G1T,
                                    const float* bg1, __half* H1, int bidx)
{
    const int tid = threadIdx.x;
    const int lane = tid & 31, wid = tid >> 5;
    const int wm = wid & 1, wn = wid >> 1;
    const int nb = (bidx & 1) * 128;
    const int m0 = (bidx >> 1) * 128;

    const __half* Ap  = VH + (size_t)m0 * DIN;
    const __half* Bhp = G1T + (size_t)nb * DIN;
    const int lr = tid >> 3;
    const int lc = (tid & 7) * 8;

    float acc[4][4][4];
#pragma unroll
    for (int i = 0; i < 4; i++)
#pragma unroll
        for (int j = 0; j < 4; j++)
#pragma unroll
            for (int k = 0; k < 4; k++) acc[i][j][k] = 0.f;

    auto load_stage = [&](int s, int k0) {
        const uint32_t base = sb + s * ST_SIZE;
#pragma unroll
        for (int t = 0; t < 4; t++) {
            const int row = lr + t * 32;
            const uint32_t doff = (uint32_t)(row * RS + lc) * 2;
            cpasync16(base + doff,         Ap  + (size_t)row * DIN + k0 + lc);
            cpasync16(base + OFF_B + doff, Bhp + (size_t)row * DIN + k0 + lc);
        }
    };

    const uint32_t aoff = (uint32_t)(((wm * 64 + (lane & 15)) * RS + (lane >> 4) * 8) * 2);
    const uint32_t boff = (uint32_t)(((wn * 32 + (lane & 15)) * RS + (lane >> 4) * 8) * 2);

    load_stage(0, 0);  CP_COMMIT();
    load_stage(1, 64); CP_COMMIT();

    int sidx = 0;
    for (int c = 0; c < 64; c++) {
        CP_WAIT(1);
        __syncthreads();
        const uint32_t base = sb + sidx * ST_SIZE;
#pragma unroll
        for (int kc = 0; kc < 64; kc += 16) {
            uint32_t a[4][4], bh[2][4];
#pragma unroll
            for (int mt = 0; mt < 4; mt++)
                ldsm_x4(a[mt], base + aoff + mt * (16 * RS * 2) + kc * 2);
#pragma unroll
            for (int p = 0; p < 2; p++)
                ldsm_x4(bh[p], base + OFF_B + boff + p * (16 * RS * 2) + kc * 2);
#pragma unroll
            for (int mt = 0; mt < 4; mt++)
#pragma unroll
                for (int q = 0; q < 4; q++)
                    mma16816(acc[mt][q], a[mt], bh[q >> 1][q & 1], bh[q >> 1][(q & 1) + 2]);
        }
        __syncthreads();
        if (c + 2 < 64) {
            int ns = sidx + 2; if (ns >= 3) ns -= 3;
            load_stage(ns, (c + 2) * 64);
        }
        CP_COMMIT();
        if (++sidx == 3) sidx = 0;
    }

    const int gid = lane >> 2, tig = lane & 3;
#pragma unroll
    for (int mt = 0; mt < 4; mt++) {
#pragma unroll
        for (int q = 0; q < 4; q++) {
            const int m = m0 + wm * 64 + mt * 16 + gid;
            const int n = nb + wn * 32 + q * 8 + tig * 2;
            const float b0 = bg1[n], b1 = bg1[n + 1];
            float x0 = acc[mt][q][0] + b0, x1 = acc[mt][q][1] + b1;
            float y0 = acc[mt][q][2] + b0, y1 = acc[mt][q][3] + b1;
            x0 = (x0 > 0.f) ? x0 : expm1f(x0);
            x1 = (x1 > 0.f) ? x1 : expm1f(x1);
            y0 = (y0 > 0.f) ? y0 : expm1f(y0);
            y1 = (y1 > 0.f) ? y1 : expm1f(y1);
            __half* d0 = H1 + (size_t)m * 256 + n;
            *reinterpret_cast<__half2*>(d0) = __floats2half2_rn(x0, x1);
            *reinterpret_cast<__half2*>(d0 + 8 * 256) = __floats2half2_rn(y0, y1);
        }
    }
}

// ---- skip body: bidx in [0,1024) ----
__device__ __noinline__ void dev_skip(unsigned char* sm,
                                      const __half* vh, const float* Wgs,
                                      const float* bgs, float* skipOut, int bidx)
{
    __half (*As)[256] = reinterpret_cast<__half (*)[256]>(sm);            // 8KB
    float (*Ws)[16]  = reinterpret_cast<float (*)[16]>(sm + 8192);        // 16KB
    const int tid = threadIdx.x;
    const long t0 = (long)bidx * 16;
    const int o = tid & 15;
    const int tr = tid >> 4;
    float s = 0.f;
    for (int k0 = 0; k0 < DIN; k0 += 256) {
        {
            const int r = tid >> 4;
            const int cc = (tid & 15) * 16;
            *reinterpret_cast<uint4*>(&As[r][cc]) =
                *reinterpret_cast<const uint4*>(vh + (t0 + r) * DIN + k0 + cc);
            *reinterpret_cast<uint4*>(&As[r][cc + 8]) =
                *reinterpret_cast<const uint4*>(vh + (t0 + r) * DIN + k0 + cc + 8);
        }
        {
            const int r = tid;
            *reinterpret_cast<float4*>(&Ws[r][0])  = *reinterpret_cast<const float4*>(Wgs + (long)(k0 + r) * 16 + 0);
            *reinterpret_cast<float4*>(&Ws[r][4])  = *reinterpret_cast<const float4*>(Wgs + (long)(k0 + r) * 16 + 4);
            *reinterpret_cast<float4*>(&Ws[r][8])  = *reinterpret_cast<const float4*>(Wgs + (long)(k0 + r) * 16 + 8);
            *reinterpret_cast<float4*>(&Ws[r][12]) = *reinterpret_cast<const float4*>(Wgs + (long)(k0 + r) * 16 + 12);
        }
        __syncthreads();
#pragma unroll 16
        for (int kk = 0; kk < 256; kk++) s += __half2float(As[tr][kk]) * Ws[kk][o];
        __syncthreads();
    }
    skipOut[(t0 + tr) * 16 + o] = s + bgs[o];
}

// ---- fused per-variable chain body: bidx in [0,4096) ----
__device__ __noinline__ void dev_fused(unsigned char* sm, uint32_t sb,
                                       const __half* VH,
                                       const __half* W1T, const __half* W2T,
                                       const __half* W3T,
                                       const float* bv1, const float* bv2,
                                       const float* bv3, __half* E, int bidx)
{
    const int tid = threadIdx.x;
    const int lane = tid & 31, wid = tid >> 5;
    const int wm = wid & 1, wn = wid >> 1;
    const int gid = lane >> 2, tig = lane & 3;
    const int v = bidx >> 8;
    const int m0 = (bidx & 255) * 64;

    {
        const __half* xp = VH + (size_t)m0 * DIN + v * 256;
#pragma unroll
        for (int t = 0; t < 8; t++) {
            const int id = tid + t * 256;
            const int ch = id >> 9;
            const int rem = id & 511;
            const int row = rem >> 3;
            const int lc8 = (rem & 7) * 8;
            cpasync16(sb + FA0 + ch * ACH + (uint32_t)(row * RS + lc8) * 2,
                      xp + (size_t)row * DIN + ch * 64 + lc8);
        }
        CP_COMMIT();
    }

    const uint32_t aoff = (uint32_t)(((wm * 32 + (lane & 15)) * RS + (lane >> 4) * 8) * 2);
    const uint32_t boff = (uint32_t)(((wn * 32 + (lane & 15)) * RS + (lane >> 4) * 8) * 2);
    const int lr = tid >> 3;
    const int lc = (tid & 7) * 8;

    for (int stage = 0; stage < 3; stage++) {
        const __half* W = (stage == 0) ? (W1T + (size_t)v * 65536)
                        : (stage == 1) ? (W2T + (size_t)v * 65536)
                                       : (W3T + (size_t)v * 131072);
        const int nPass = (stage == 2) ? 4 : 2;
        const uint32_t aBuf = (stage == 1) ? FA1 : FA0;
        const uint32_t oBuf = (stage == 0) ? FA1 : FA0;

        for (int np = 0; np < nPass; np++) {
            float acc[2][4][4];
#pragma unroll
            for (int i = 0; i < 2; i++)
#pragma unroll
                for (int j = 0; j < 4; j++)
#pragma unroll
                    for (int k = 0; k < 4; k++) acc[i][j][k] = 0.f;

            const __half* Wp = W + (size_t)(np * 128) * 256;
#pragma unroll
            for (int pc = 0; pc < 2; pc++) {
#pragma unroll
                for (int t = 0; t < 4; t++) {
                    const int row = lr + t * 32;
                    cpasync16(sb + FWB + pc * 18432 + (uint32_t)(row * RS + lc) * 2,
                              Wp + (size_t)row * 256 + pc * 64 + lc);
                }
                CP_COMMIT();
            }

            for (int c = 0; c < 4; c++) {
                if (c < 3) { CP_WAIT(1); } else { CP_WAIT(0); }
                __syncthreads();
                const uint32_t abase = sb + aBuf + c * ACH;
                const uint32_t bbase = sb + FWB + (c & 1) * 18432;
#pragma unroll
                for (int kc = 0; kc < 64; kc += 16) {
                    uint32_t a[2][4], bh[2][4];
#pragma unroll
                    for (int mt = 0; mt < 2; mt++)
                        ldsm_x4(a[mt], abase + aoff + mt * (16 * RS * 2) + kc * 2);
#pragma unroll
                    for (int p = 0; p < 2; p++)
                        ldsm_x4(bh[p], bbase + boff + p * (16 * RS * 2) + kc * 2);
#pragma unroll
                    for (int mt = 0; mt < 2; mt++)
#pragma unroll
                        for (int q = 0; q < 4; q++)
                            mma16816(acc[mt][q], a[mt], bh[q >> 1][q & 1], bh[q >> 1][(q & 1) + 2]);
                }
                __syncthreads();
                if (c + 2 < 4) {
#pragma unroll
                    for (int t = 0; t < 4; t++) {
                        const int row = lr + t * 32;
                        cpasync16(sb + FWB + (c & 1) * 18432 + (uint32_t)(row * RS + lc) * 2,
                                  Wp + (size_t)row * 256 + (c + 2) * 64 + lc);
                    }
                    CP_COMMIT();
                }
            }

            if (stage < 2) {
                const float* bp = ((stage == 0) ? bv1 : bv2) + (size_t)v * 256;
                __half* ob = reinterpret_cast<__half*>(sm) + (oBuf >> 1);
#pragma unroll
                for (int mt = 0; mt < 2; mt++) {
#pragma unroll
                    for (int q = 0; q < 4; q++) {
                        const int m = wm * 32 + mt * 16 + gid;
                        const int gn = np * 128 + wn * 32 + q * 8 + tig * 2;
                        const float b0 = bp[gn], b1 = bp[gn + 1];
                        float x0 = acc[mt][q][0] + b0, x1 = acc[mt][q][1] + b1;
                        float y0 = acc[mt][q][2] + b0, y1 = acc[mt][q][3] + b1;
                        if (stage == 0) {
                            x0 = (x0 > 0.f) ? x0 : expm1f(x0);
                            x1 = (x1 > 0.f) ? x1 : expm1f(x1);
                            y0 = (y0 > 0.f) ? y0 : expm1f(y0);
                            y1 = (y1 > 0.f) ? y1 : expm1f(y1);
                        }
                        const int ch = gn >> 6;
                        const int ko = gn & 63;
                        __half* d0 = ob + ch * (ACH / 2) + m * RS + ko;
                        *reinterpret_cast<__half2*>(d0) = __floats2half2_rn(x0, x1);
                        *reinterpret_cast<__half2*>(d0 + 8 * RS) = __floats2half2_rn(y0, y1);
                    }
                }
                __syncthreads();
            } else {
                const float* bp = bv3 + (size_t)v * 512;
                const int jbase = np * 64;
                __half* Eg = reinterpret_cast<__half*>(sm) + (FA1 >> 1);
#pragma unroll
                for (int mt = 0; mt < 2; mt++) {
#pragma unroll
                    for (int q = 0; q < 4; q++) {
                        const int nl = wn * 32 + q * 8 + tig * 2;
                        const int jl = nl >> 1;
                        const int jg = jbase + jl;
                        const float ba = bp[jg], bb = bp[jg + 256];
                        const int r0 = wm * 32 + mt * 16 + gid;
                        float a0 = acc[mt][q][0] + ba, b0 = acc[mt][q][1] + bb;
                        float a1 = acc[mt][q][2] + ba, b1 = acc[mt][q][3] + bb;
                        Eg[r0 * 64 + jl]       = __float2half_rn(a0 * (1.f / (1.f + expf(-b0))));
                        Eg[(r0 + 8) * 64 + jl] = __float2half_rn(a1 * (1.f / (1.f + expf(-b1))));
                    }
                }
                __syncthreads();
                const int row = tid >> 2;
                const int chh = (tid & 3) * 16;
                const __half* src = Eg + row * 64 + chh;
                const __half* xsrc = VH + (size_t)(m0 + row) * DIN + v * 256 + jbase + chh;
                __half* dst = E + ((size_t)v * BT_TOK + m0 + row) * 256 + jbase + chh;
#pragma unroll
                for (int u = 0; u < 2; u++) {
                    uint4 ev = *reinterpret_cast<const uint4*>(src + u * 8);
                    uint4 xv = *reinterpret_cast<const uint4*>(xsrc + u * 8);
                    uint4 ov;
                    ov.x = hadd2_f32(ev.x, xv.x);
                    ov.y = hadd2_f32(ev.y, xv.y);
                    ov.z = hadd2_f32(ev.z, xv.z);
                    ov.w = hadd2_f32(ev.w, xv.w);
                    *reinterpret_cast<uint4*>(dst + u * 8) = ov;
                }
                __syncthreads();
            }
        }
    }
}

// ---- mega kernel: [0,256) G1, [256,1280) skip, [1280,5376) fused ----
__global__ __launch_bounds__(256, 2)
void mega_kernel(const __half* __restrict__ VH,
                 const __half* __restrict__ G1T, const float* __restrict__ bg1,
                 __half* __restrict__ H1,
                 const float* __restrict__ Wgs, const float* __restrict__ bgs,
                 float* __restrict__ SKP,
                 const __half* __restrict__ W1T, const __half* __restrict__ W2T,
                 const __half* __restrict__ W3T,
                 const float* __restrict__ bv1, const float* __restrict__ bv2,
                 const float* __restrict__ bv3, __half* __restrict__ E)
{
    extern __shared__ __align__(1024) unsigned char sm[];
    const uint32_t sb = smem_u32(sm);
    const int b = blockIdx.x;
    if (b < 256) {
        dev_g1(sm, sb, VH, G1T, bg1, H1, b);
    } else if (b < 1280) {
        dev_skip(sm, VH, Wgs, bgs, SKP, b - 256);
    } else {
        dev_fused(sm, sb, VH, W1T, W2T, W3T, bv1, bv2, bv3, E, b - 1280);
    }
}

// ---------------------------------------------------------------------------
// mma_gemm for G2 (mode 0, fp32 out, K=256)
// ---------------------------------------------------------------------------
__global__ __launch_bounds__(256, 2)
void mma_gemm(const __half* __restrict__ A, int lda,
              const __half* __restrict__ BH,
              const float* __restrict__ bias,
              float* __restrict__ CF, int ldc, int K)
{
    extern __shared__ __align__(1024) unsigned char sm[];
    const uint32_t sb = smem_u32(sm);
    const int tid = threadIdx.x;
    const int lane = tid & 31, wid = tid >> 5;
    const int wm = wid & 1, wn = wid >> 1;
    const int m0 = blockIdx.y * 128;
    const int nb = blockIdx.x * 128;

    const __half* Ap  = A + (size_t)m0 * lda;
    const __half* Bhp = BH + (size_t)nb * K;
    const int lr = tid >> 3;
    const int lc = (tid & 7) * 8;

    float acc[4][4][4];
#pragma unroll
    for (int i = 0; i < 4; i++)
#pragma unroll
        for (int j = 0; j < 4; j++)
#pragma unroll
            for (int k = 0; k < 4; k++) acc[i][j][k] = 0.f;

    const int nc = K >> 6;

    auto load_stage = [&](int s, int k0) {
        const uint32_t base = sb + s * ST_SIZE;
#pragma unroll
        for (int t = 0; t < 4; t++) {
            const int row = lr + t * 32;
            const uint32_t doff = (uint32_t)(row * RS + lc) * 2;
            cpasync16(base + doff,         Ap  + (size_t)row * lda + k0 + lc);
            cpasync16(base + OFF_B + doff, Bhp + (size_t)row * K   + k0 + lc);
        }
    };

    const uint32_t aoff = (uint32_t)(((wm * 64 + (lane & 15)) * RS + (lane >> 4) * 8) * 2);
    const uint32_t boff = (uint32_t)(((wn * 32 + (lane & 15)) * RS + (lane >> 4) * 8) * 2);

    load_stage(0, 0);              CP_COMMIT();
    if (nc > 1) { load_stage(1, 64); } CP_COMMIT();

    int sidx = 0;
    for (int c = 0; c < nc; c++) {
        CP_WAIT(1);
        __syncthreads();
        const uint32_t base = sb + sidx * ST_SIZE;
#pragma unroll
        for (int kc = 0; kc < 64; kc += 16) {
            uint32_t a[4][4], bh[2][4];
#pragma unroll
            for (int mt = 0; mt < 4; mt++)
                ldsm_x4(a[mt], base + aoff + mt * (16 * RS * 2) + kc * 2);
#pragma unroll
            for (int p = 0; p < 2; p++)
                ldsm_x4(bh[p], base + OFF_B + boff + p * (16 * RS * 2) + kc * 2);
#pragma unroll
            for (int mt = 0; mt < 4; mt++)
#pragma unroll
                for (int q = 0; q < 4; q++)
                    mma16816(acc[mt][q], a[mt], bh[q >> 1][q & 1], bh[q >> 1][(q & 1) + 2]);
        }
        __syncthreads();
        if (c + 2 < nc) {
            int ns = sidx + 2; if (ns >= 3) ns -= 3;
            load_stage(ns, (c + 2) * 64);
        }
        CP_COMMIT();
        if (++sidx == 3) sidx = 0;
    }

    const int gid = lane >> 2, tig = lane & 3;
#pragma unroll
    for (int mt = 0; mt < 4; mt++) {
#pragma unroll
        for (int q = 0; q < 4; q++) {
            const int m = m0 + wm * 64 + mt * 16 + gid;
            const int n = nb + wn * 32 + q * 8 + tig * 2;
            const float b0 = bias[n], b1 = bias[n + 1];
            float* d0 = CF + (size_t)m * ldc + n;
            float2 o0; o0.x = acc[mt][q][0] + b0; o0.y = acc[mt][q][1] + b1;
            float2 o1; o1.x = acc[mt][q][2] + b0; o1.y = acc[mt][q][3] + b1;
            *reinterpret_cast<float2*>(d0) = o0;
            *reinterpret_cast<float2*>(d0 + 8 * ldc) = o1;
        }
    }
}

// ---------------------------------------------------------------------------
// weight logits -> softmax weights
// ---------------------------------------------------------------------------
__global__ __launch_bounds__(256)
void wlogits_kernel(const float* __restrict__ h2, const float* __restrict__ Wg3,
                    const float* __restrict__ bg3, const float* __restrict__ gg,
                    const float* __restrict__ bgn, const float* __restrict__ skipIn,
                    float* __restrict__ wout)
{
    __shared__ float Ws[256 * 32];
    const int tid = threadIdx.x;
    const int lane = tid & 31;
#pragma unroll
    for (int i = 0; i < 32; i++) Ws[tid + i * 256] = Wg3[tid + i * 256];
    __syncthreads();

    const long t = (long)blockIdx.x * 8 + (tid >> 5);
    const float* h2t = h2 + t * 256;
    float s = bg3[lane];
#pragma unroll 8
    for (int k = 0; k < 256; k += 4) {
        float4 h = *reinterpret_cast<const float4*>(h2t + k);
        s += h.x * Ws[(k + 0) * 32 + lane];
        s += h.y * Ws[(k + 1) * 32 + lane];
        s += h.z * Ws[(k + 2) * 32 + lane];
        s += h.w * Ws[(k + 3) * 32 + lane];
    }
    float bhalf = __shfl_down_sync(0xffffffffu, s, 16);
    float r = 0.f;
    if (lane < 16)
        r = s * (1.f / (1.f + expf(-bhalf))) + skipIn[t * 16 + lane];
    float sum = r;
    for (int m = 8; m; m >>= 1) sum += __shfl_xor_sync(0xffffffffu, sum, m, 16);
    float mean = sum * (1.f / 16.f);
    float d = r - mean;
    float vs = d * d;
    for (int m = 8; m; m >>= 1) vs += __shfl_xor_sync(0xffffffffu, vs, m, 16);
    float rstd = rsqrtf(vs * (1.f / 16.f) + 1e-6f);
    float ln = 0.f;
    if (lane < 16) ln = d * rstd * gg[lane] + bgn[lane];
    float mx = ln;
    for (int m = 8; m; m >>= 1) mx = fmaxf(mx, __shfl_xor_sync(0xffffffffu, mx, m, 16));
    float e = (lane < 16) ? expf(ln - mx) : 0.f;
    float se = e;
    for (int m = 8; m; m >>= 1) se += __shfl_xor_sync(0xffffffffu, se, m, 16);
    if (lane < 16) wout[t * 16 + lane] = e / se;
}

// ---------------------------------------------------------------------------
// out = sum_v LN(E[v]) * weight[v]    (E already = glu + x)
// ---------------------------------------------------------------------------
__global__ __launch_bounds__(256)
void enc_combine_kernel(const __half* __restrict__ E, const float* __restrict__ wout,
                        const float* __restrict__ gv, const float* __restrict__ bvn,
                        float* __restrict__ outp)
{
    const long t = blockIdx.x;
    const int tid = threadIdx.x;
    const int lane = tid & 31, wid = tid >> 5;
    __shared__ float sw[16];
    __shared__ float part[8][256];
    if (tid < 16) sw[tid] = wout[t * 16 + tid];
    __syncthreads();

    const int c0 = lane * 8;
    float acc[8];
#pragma unroll
    for (int i = 0; i < 8; i++) acc[i] = 0.f;

#pragma unroll
    for (int vi = 0; vi < 2; vi++) {
        const int v = wid * 2 + vi;
        uint4 rawE = *reinterpret_cast<const uint4*>(
            E + ((size_t)v * BT_TOK + t) * 256 + c0);
        const __half2* he = reinterpret_cast<const __half2*>(&rawE);
        float e[8];
#pragma unroll
        for (int i = 0; i < 4; i++) {
            float2 fe = __half22float2(he[i]);
            e[2 * i]     = fe.x;
            e[2 * i + 1] = fe.y;
        }
        float s1 = 0.f, s2 = 0.f;
#pragma unroll
        for (int i = 0; i < 8; i++) { s1 += e[i]; s2 += e[i] * e[i]; }
#pragma unroll
        for (int m = 16; m; m >>= 1) {
            s1 += __shfl_xor_sync(0xffffffffu, s1, m);
            s2 += __shfl_xor_sync(0xffffffffu, s2, m);
        }
        const float mean = s1 * (1.f / 256.f);
        const float var = s2 * (1.f / 256.f) - mean * mean;
        const float rstd = rsqrtf(var + 1e-6f);
        const float w = sw[v];
        const float4 g0 = *reinterpret_cast<const float4*>(gv + v * DDIM + c0);
        const float4 g1 = *reinterpret_cast<const float4*>(gv + v * DDIM + c0 + 4);
        const float4 b0 = *reinterpret_cast<const float4*>(bvn + v * DDIM + c0);
        const float4 b1 = *reinterpret_cast<const float4*>(bvn + v * DDIM + c0 + 4);
        const float gva[8] = {g0.x, g0.y, g0.z, g0.w, g1.x, g1.y, g1.z, g1.w};
        const float bva[8] = {b0.x, b0.y, b0.z, b0.w, b1.x, b1.y, b1.z, b1.w};
#pragma unroll
        for (int i = 0; i < 8; i++)
            acc[i] += ((e[i] - mean) * rstd * gva[i] + bva[i]) * w;
    }
#pragma unroll
    for (int i = 0; i < 8; i++) part[wid][c0 + i] = acc[i];
    __syncthreads();
    float s = 0.f;
#pragma unroll
    for (int wwi = 0; wwi < 8; wwi++) s += part[wwi][tid];
    outp[t * DDIM + tid] = s;
}

// ---------------------------------------------------------------------------
extern "C" void kernel_launch(void* const* d_in, const int* in_sizes, int n_in,
                              void* d_out, int out_size)
{
    const float* vars = (const float*)d_in[0];
    const float* Wg1  = (const float*)d_in[1];
    const float* bg1  = (const float*)d_in[2];
    const float* Wg2  = (const float*)d_in[3];
    const float* bg2  = (const float*)d_in[4];
    const float* Wg3  = (const float*)d_in[5];
    const float* bg3  = (const float*)d_in[6];
    const float* Wgs  = (const float*)d_in[7];
    const float* bgs  = (const float*)d_in[8];
    const float* gg   = (const float*)d_in[9];
    const float* bgn  = (const float*)d_in[10];
    const float* Wv1  = (const float*)d_in[11];
    const float* bv1  = (const float*)d_in[12];
    const float* Wv2  = (const float*)d_in[13];
    const float* bv2  = (const float*)d_in[14];
    const float* Wv3  = (const float*)d_in[15];
    const float* bv3  = (const float*)d_in[16];
    const float* gv   = (const float*)d_in[17];
    const float* bvn  = (const float*)d_in[18];

    float* out  = (float*)d_out;
    float* wout = out + BT_TOK * DDIM;

    unsigned char* gb = nullptr;
    cudaGetSymbolAddress((void**)&gb, g_buf);
    __half* VH  = (__half*)(gb + O_VH);
    __half* H1  = (__half*)(gb + O_H1);
    float*  H2F = (float*)(gb + O_H2F);
    __half* E   = (__half*)(gb + O_E);
    float*  SKP = (float*)(gb + O_SKIP);
    __half* G1T = (__half*)(gb + O_G1);
    __half* G2T = (__half*)(gb + O_G2);
    __half* W1T = (__half*)(gb + O_W1);
    __half* W2T = (__half*)(gb + O_W2);
    __half* W3T = (__half*)(gb + O_W3);

    cudaFuncSetAttribute(mega_kernel, cudaFuncAttributeMaxDynamicSharedMemorySize, SMEM_TOT);
    cudaFuncSetAttribute(mma_gemm, cudaFuncAttributeMaxDynamicSharedMemorySize, SMEM_TOT);

    // conversions
    conv_split<<<32768, 256>>>(vars, VH);
    conv_wT<<<dim3(8, 128, 1), 256>>>(Wg1, G1T, 4096, 256);
    conv_wT<<<dim3(8, 8, 1),   256>>>(Wg2, G2T, 256, 256);
    conv_wT<<<dim3(8, 8, 16),  256>>>(Wv1, W1T, 256, 256);
    conv_wT<<<dim3(8, 8, 16),  256>>>(Wv2, W2T, 256, 256);
    conv_wT3<<<dim3(16, 8, 16), 256>>>(Wv3, W3T);

    // mega: G1 + skip + fused per-variable chain, co-scheduled
    mega_kernel<<<5376, 256, SMEM_TOT>>>(VH, G1T, bg1, H1, Wgs, bgs, SKP,
                                         W1T, W2T, W3T, bv1, bv2, bv3, E);

    // G2: h2 = h1 @ Wg2 + bg2 (fp32 out)
    mma_gemm<<<dim3(2, 128), 256, SMEM_TOT>>>(H1, 256, G2T, bg2, H2F, 256, 256);
    wlogits_kernel<<<2048, 256>>>(H2F, Wg3, bg3, gg, bgn, SKP, wout);

    // final combine
    enc_combine_kernel<<<16384, 256>>>(E, wout, gv, bvn, out);
}